// round 1
// baseline (speedup 1.0000x reference)
#include <cuda_runtime.h>
#include <cuda_bf16.h>
#include <cstdint>
#include <cstddef>

// ---------------------------------------------------------------------------
// Problem constants
// ---------------------------------------------------------------------------
#define BATCH   4
#define CC      512          // channels C
#define NTOK    4096         // 64*64 spatial tokens
#define NROWS   (BATCH*NTOK) // 16384 total token rows
#define HHEADS  8
#define HD      64           // head dim
#define CTX_S   77
#define CTX_D   768
#define GEO_S   256
#define GEO_D   512
#define FFN_D   2048
#define LN_EPS  1e-5f

// ---------------------------------------------------------------------------
// Scratch (static device globals; no runtime allocation allowed)
// ---------------------------------------------------------------------------
__device__ float g_t   [(size_t)NROWS * CC];      // running residual stream (B,N,C)
__device__ float g_xn  [(size_t)NROWS * CC];      // layernormed input (also t0 temp)
__device__ float g_q   [(size_t)NROWS * CC];      // Q projection
__device__ float g_attn[(size_t)NROWS * CC];      // attention context (pre-Wo)
__device__ float g_k   [(size_t)BATCH * GEO_S * CC]; // K projection (max S=256)
__device__ float g_v   [(size_t)BATCH * GEO_S * CC]; // V projection
__device__ float g_big [(size_t)NROWS * FFN_D];   // FFN hidden / attention scores (reused)

// ---------------------------------------------------------------------------
// Transpose: in is (batch, R, Cc) row-major -> out is (batch, Cc, R)
// out[b][j][i] = in[b][i][j]
// ---------------------------------------------------------------------------
__global__ void transpose_kernel(const float* __restrict__ in, float* __restrict__ out,
                                 int R, int Ccol) {
    __shared__ float tile[32][33];
    int b = blockIdx.z;
    const float* ip = in  + (size_t)b * R * Ccol;
    float*       op = out + (size_t)b * R * Ccol;
    int j0 = blockIdx.x * 32;   // col index in input
    int i0 = blockIdx.y * 32;   // row index in input
    int tx = threadIdx.x, ty = threadIdx.y;
    #pragma unroll
    for (int k = 0; k < 32; k += 8) {
        int i = i0 + ty + k, j = j0 + tx;
        if (i < R && j < Ccol) tile[ty + k][tx] = ip[(size_t)i * Ccol + j];
    }
    __syncthreads();
    #pragma unroll
    for (int k = 0; k < 32; k += 8) {
        int j = j0 + ty + k, i = i0 + tx;
        if (j < Ccol && i < R) op[(size_t)j * R + i] = tile[tx][ty + k];
    }
}

// ---------------------------------------------------------------------------
// LayerNorm over C=512 per row. One block (128 threads) per row, float4 path.
// ADD: out = in + LN(in)   else out = LN(in)
// ---------------------------------------------------------------------------
template <bool ADD>
__global__ void ln_kernel(const float* __restrict__ in,
                          const float* __restrict__ gamma,
                          const float* __restrict__ beta,
                          float* __restrict__ out) {
    int row = blockIdx.x;
    const float4* rin = reinterpret_cast<const float4*>(in + (size_t)row * CC);
    float4* rout = reinterpret_cast<float4*>(out + (size_t)row * CC);
    int t = threadIdx.x;      // 128 threads * 4 = 512
    float4 v = rin[t];
    float s  = v.x + v.y + v.z + v.w;
    float ss = v.x*v.x + v.y*v.y + v.z*v.z + v.w*v.w;
    // warp reduce
    #pragma unroll
    for (int o = 16; o > 0; o >>= 1) {
        s  += __shfl_xor_sync(0xffffffffu, s,  o);
        ss += __shfl_xor_sync(0xffffffffu, ss, o);
    }
    __shared__ float shs[4], shss[4];
    int warp = t >> 5, lane = t & 31;
    if (lane == 0) { shs[warp] = s; shss[warp] = ss; }
    __syncthreads();
    s  = shs[0] + shs[1] + shs[2] + shs[3];
    ss = shss[0] + shss[1] + shss[2] + shss[3];
    float mu  = s * (1.0f / CC);
    float var = ss * (1.0f / CC) - mu * mu;
    float rs  = rsqrtf(var + LN_EPS);
    float4 g4 = reinterpret_cast<const float4*>(gamma)[t];
    float4 b4 = reinterpret_cast<const float4*>(beta)[t];
    float4 o4;
    o4.x = (v.x - mu) * rs * g4.x + b4.x;
    o4.y = (v.y - mu) * rs * g4.y + b4.y;
    o4.z = (v.z - mu) * rs * g4.z + b4.z;
    o4.w = (v.w - mu) * rs * g4.w + b4.w;
    if (ADD) { o4.x += v.x; o4.y += v.y; o4.z += v.z; o4.w += v.w; }
    rout[t] = o4;
}

// ---------------------------------------------------------------------------
// Row softmax (in-place). One warp per row, row length S.
// ---------------------------------------------------------------------------
__global__ void softmax_kernel(float* __restrict__ data, long long rows, int S) {
    long long row = (long long)blockIdx.x * 4 + (threadIdx.x >> 5);
    if (row >= rows) return;
    float* p = data + row * (long long)S;
    int lane = threadIdx.x & 31;
    float mx = -1e30f;
    for (int j = lane; j < S; j += 32) mx = fmaxf(mx, p[j]);
    #pragma unroll
    for (int o = 16; o > 0; o >>= 1) mx = fmaxf(mx, __shfl_xor_sync(0xffffffffu, mx, o));
    float sum = 0.0f;
    for (int j = lane; j < S; j += 32) { float e = __expf(p[j] - mx); p[j] = e; sum += e; }
    #pragma unroll
    for (int o = 16; o > 0; o >>= 1) sum += __shfl_xor_sync(0xffffffffu, sum, o);
    float inv = 1.0f / sum;
    for (int j = lane; j < S; j += 32) p[j] *= inv;
}

// ---------------------------------------------------------------------------
// Generic tiled SGEMM, optionally batched over grid.z with (b,h) split strides.
//   C = alpha * A @ op(B)   [+ bias]  [GELU]  [+= residual in C]
// A: M x K, lda        op(B): K x N (TRANSB: B stored N x K row-major)
// EPI: 0=store, 1=+bias store, 2=+bias, GELU, store, 3=C += result + bias
// ---------------------------------------------------------------------------
__device__ __forceinline__ float gelu_exact(float x) {
    return 0.5f * x * (1.0f + erff(x * 0.70710678118654752440f));
}

template <bool TRANSB, int EPI>
__global__ void sgemm_kernel(const float* __restrict__ A, int lda, long long sAb, long long sAh,
                             const float* __restrict__ B, int ldb, long long sBb, long long sBh,
                             float* __restrict__ C, int ldc, long long sCb, long long sCh,
                             const float* __restrict__ bias,
                             int M, int N, int K, float alpha, int H) {
    const int BM = 64, BN = 64, BK = 16;
    __shared__ __align__(16) float sA[BK][BM + 4];
    __shared__ __align__(16) float sB[BK][BN + 4];

    int z = blockIdx.z;
    int bb = z / H, hh = z % H;
    A += bb * sAb + hh * sAh;
    B += bb * sBb + hh * sBh;
    C += bb * sCb + hh * sCh;

    int tid = threadIdx.x;            // 256
    int tx = tid & 15, ty = tid >> 4; // 16x16
    int row0 = blockIdx.y * BM;
    int col0 = blockIdx.x * BN;

    float acc[4][4] = {};

    for (int k0 = 0; k0 < K; k0 += BK) {
        // Load A tile: sA[kk][m]
        #pragma unroll
        for (int r = 0; r < 4; r++) {
            int idx = tid + r * 256;
            int m = idx / BK, kk = idx % BK;
            int gm = row0 + m, gk = k0 + kk;
            sA[kk][m] = (gm < M && gk < K) ? A[(size_t)gm * lda + gk] : 0.0f;
        }
        // Load B tile: sB[kk][n]
        #pragma unroll
        for (int r = 0; r < 4; r++) {
            int idx = tid + r * 256;
            if (!TRANSB) {
                int kk = idx / BN, n = idx % BN;
                int gk = k0 + kk, gn = col0 + n;
                sB[kk][n] = (gk < K && gn < N) ? B[(size_t)gk * ldb + gn] : 0.0f;
            } else {
                int n = idx / BK, kk = idx % BK;
                int gn = col0 + n, gk = k0 + kk;
                sB[kk][n] = (gn < N && gk < K) ? B[(size_t)gn * ldb + gk] : 0.0f;
            }
        }
        __syncthreads();
        #pragma unroll
        for (int kk = 0; kk < BK; kk++) {
            float4 a4 = *reinterpret_cast<const float4*>(&sA[kk][ty * 4]);
            float4 b4 = *reinterpret_cast<const float4*>(&sB[kk][tx * 4]);
            float a[4] = {a4.x, a4.y, a4.z, a4.w};
            float b[4] = {b4.x, b4.y, b4.z, b4.w};
            #pragma unroll
            for (int i = 0; i < 4; i++)
                #pragma unroll
                for (int j = 0; j < 4; j++)
                    acc[i][j] += a[i] * b[j];
        }
        __syncthreads();
    }

    // Epilogue
    #pragma unroll
    for (int i = 0; i < 4; i++) {
        int gm = row0 + ty * 4 + i;
        if (gm >= M) continue;
        #pragma unroll
        for (int j = 0; j < 4; j++) {
            int gn = col0 + tx * 4 + j;
            if (gn >= N) continue;
            size_t off = (size_t)gm * ldc + gn;
            float v = acc[i][j] * alpha;
            if (EPI == 1) {
                v += bias[gn];
            } else if (EPI == 2) {
                v = gelu_exact(v + bias[gn]);
            } else if (EPI == 3) {
                v += bias[gn] + C[off];
            }
            C[off] = v;
        }
    }
}

// ---------------------------------------------------------------------------
// Host-side launch helpers
// ---------------------------------------------------------------------------
static inline int ceil_div(int a, int b) { return (a + b - 1) / b; }

template <bool TRANSB, int EPI>
static void launch_gemm(const float* A, int lda, long long sAb, long long sAh,
                        const float* B, int ldb, long long sBb, long long sBh,
                        float* C, int ldc, long long sCb, long long sCh,
                        const float* bias, int M, int N, int K, float alpha,
                        int batches, int H) {
    dim3 grid(ceil_div(N, 64), ceil_div(M, 64), batches);
    sgemm_kernel<TRANSB, EPI><<<grid, 256>>>(A, lda, sAb, sAh, B, ldb, sBb, sBh,
                                             C, ldc, sCb, sCh, bias, M, N, K, alpha, H);
}

// One full cross-attention sublayer: t += Attn(LN(t), kv_src) @ Wo + bo
static void cross_attention(float* t_dev, float* xn_dev, float* q_dev, float* attn_dev,
                            float* k_dev, float* v_dev, float* scores_dev,
                            const float* gamma, const float* beta,
                            const float* kv_src, int S, int D,
                            const float* Wq, const float* Wk, const float* Wv,
                            const float* Wo, const float* bo) {
    // LN
    ln_kernel<false><<<NROWS, 128>>>(t_dev, gamma, beta, xn_dev);
    // Q = xn @ Wq   (16384 x 512 x 512)
    launch_gemm<false, 0>(xn_dev, CC, 0, 0, Wq, CC, 0, 0, q_dev, CC, 0, 0,
                          nullptr, NROWS, CC, CC, 1.0f, 1, 1);
    // K = kv @ Wk,  V = kv @ Wv   ((B*S) x D x 512)
    int MK = BATCH * S;
    launch_gemm<false, 0>(kv_src, D, 0, 0, Wk, CC, 0, 0, k_dev, CC, 0, 0,
                          nullptr, MK, CC, D, 1.0f, 1, 1);
    launch_gemm<false, 0>(kv_src, D, 0, 0, Wv, CC, 0, 0, v_dev, CC, 0, 0,
                          nullptr, MK, CC, D, 1.0f, 1, 1);
    // scores[b,h] = Q[b,:,h] @ K[b,:,h]^T * d^-0.5    (4096 x S x 64), 32 batches
    launch_gemm<true, 0>(q_dev, CC, (long long)NTOK * CC, HD,
                         k_dev, CC, (long long)S * CC, HD,
                         scores_dev, S, (long long)HHEADS * NTOK * S, (long long)NTOK * S,
                         nullptr, NTOK, S, HD, 0.125f, BATCH * HHEADS, HHEADS);
    // softmax over S
    long long rows = (long long)BATCH * HHEADS * NTOK;
    softmax_kernel<<<(unsigned)((rows + 3) / 4), 128>>>(scores_dev, rows, S);
    // attn[b,:,h] = P @ V[b,:,h]   (4096 x 64 x S)
    launch_gemm<false, 0>(scores_dev, S, (long long)HHEADS * NTOK * S, (long long)NTOK * S,
                          v_dev, CC, (long long)S * CC, HD,
                          attn_dev, CC, (long long)NTOK * CC, HD,
                          nullptr, NTOK, HD, S, 1.0f, BATCH * HHEADS, HHEADS);
    // t += attn @ Wo + bo
    launch_gemm<false, 3>(attn_dev, CC, 0, 0, Wo, CC, 0, 0, t_dev, CC, 0, 0,
                          bo, NROWS, CC, CC, 1.0f, 1, 1);
}

// ---------------------------------------------------------------------------
// Entry point
// ---------------------------------------------------------------------------
extern "C" void kernel_launch(void* const* d_in, const int* in_sizes, int n_in,
                              void* d_out, int out_size) {
    const float* x    = (const float*)d_in[0];
    const float* ctx  = (const float*)d_in[1];
    const float* geo  = (const float*)d_in[2];
    const float* g1 = (const float*)d_in[3],  *b1 = (const float*)d_in[4];
    const float* g2 = (const float*)d_in[5],  *b2 = (const float*)d_in[6];
    const float* g3 = (const float*)d_in[7],  *b3 = (const float*)d_in[8];
    const float* g4 = (const float*)d_in[9],  *b4 = (const float*)d_in[10];
    const float* cWq = (const float*)d_in[11], *cWk = (const float*)d_in[12];
    const float* cWv = (const float*)d_in[13], *cWo = (const float*)d_in[14];
    const float* cbo = (const float*)d_in[15];
    const float* gWq = (const float*)d_in[16], *gWk = (const float*)d_in[17];
    const float* gWv = (const float*)d_in[18], *gWo = (const float*)d_in[19];
    const float* gbo = (const float*)d_in[20];
    const float* W1  = (const float*)d_in[21], *bf1 = (const float*)d_in[22];
    const float* W2  = (const float*)d_in[23], *bf2 = (const float*)d_in[24];
    float* out = (float*)d_out;

    float *t_dev, *xn_dev, *q_dev, *attn_dev, *k_dev, *v_dev, *big_dev;
    cudaGetSymbolAddress((void**)&t_dev,    g_t);
    cudaGetSymbolAddress((void**)&xn_dev,   g_xn);
    cudaGetSymbolAddress((void**)&q_dev,    g_q);
    cudaGetSymbolAddress((void**)&attn_dev, g_attn);
    cudaGetSymbolAddress((void**)&k_dev,    g_k);
    cudaGetSymbolAddress((void**)&v_dev,    g_v);
    cudaGetSymbolAddress((void**)&big_dev,  g_big);

    // 1) transpose x (B,C,N) -> t0 (B,N,C) into xn
    {
        dim3 grid(NTOK / 32, CC / 32, BATCH);
        transpose_kernel<<<grid, dim3(32, 8)>>>(x, xn_dev, CC, NTOK);
    }
    // 2) t = t0 + LN1(t0)
    ln_kernel<true><<<NROWS, 128>>>(xn_dev, g1, b1, t_dev);

    // 3) context cross-attention (S=77, D=768)
    cross_attention(t_dev, xn_dev, q_dev, attn_dev, k_dev, v_dev, big_dev,
                    g2, b2, ctx, CTX_S, CTX_D, cWq, cWk, cWv, cWo, cbo);

    // 4) geometry cross-attention (S=256, D=512)
    cross_attention(t_dev, xn_dev, q_dev, attn_dev, k_dev, v_dev, big_dev,
                    g3, b3, geo, GEO_S, GEO_D, gWq, gWk, gWv, gWo, gbo);

    // 5) FFN: t += GELU(LN4(t) @ W1 + bf1) @ W2 + bf2
    ln_kernel<false><<<NROWS, 128>>>(t_dev, g4, b4, xn_dev);
    launch_gemm<false, 2>(xn_dev, CC, 0, 0, W1, FFN_D, 0, 0, big_dev, FFN_D, 0, 0,
                          bf1, NROWS, FFN_D, CC, 1.0f, 1, 1);
    launch_gemm<false, 3>(big_dev, FFN_D, 0, 0, W2, CC, 0, 0, t_dev, CC, 0, 0,
                          bf2, NROWS, CC, FFN_D, 1.0f, 1, 1);

    // 6) transpose back t (B,N,C) -> out (B,C,N)
    {
        dim3 grid(CC / 32, NTOK / 32, BATCH);
        transpose_kernel<<<grid, dim3(32, 8)>>>(t_dev, out, NTOK, CC);
    }
}

// round 4
// speedup vs baseline: 1.3331x; 1.3331x over previous
#include <cuda_runtime.h>
#include <cuda_bf16.h>
#include <cstdint>
#include <cstddef>

// ---------------------------------------------------------------------------
// Problem constants
// ---------------------------------------------------------------------------
#define BATCH   4
#define CC      512
#define NTOK    4096
#define NROWS   (BATCH*NTOK)
#define HHEADS  8
#define HD      64
#define CTX_S   77
#define CTX_D   768
#define GEO_S   256
#define GEO_D   512
#define FFN_D   2048
#define LN_EPS  1e-5f

// ---------------------------------------------------------------------------
// Scratch (static device globals)
// ---------------------------------------------------------------------------
__device__ float g_t   [(size_t)NROWS * CC];
__device__ float g_xn  [(size_t)NROWS * CC];
__device__ float g_q   [(size_t)NROWS * CC];
__device__ float g_attn[(size_t)NROWS * CC];
__device__ float g_k   [(size_t)BATCH * GEO_S * CC];
__device__ float g_v   [(size_t)BATCH * GEO_S * CC];
__device__ float g_big [(size_t)NROWS * FFN_D];
// transposed weights: cWq_t, cWo_t, gWq_t, gWo_t (each 512x512), W1_t (2048x512), W2_t (512x2048)
__device__ float g_wt  [(size_t)4 * CC * CC + 2 * (size_t)CC * FFN_D];

#define WT_CWQ 0
#define WT_CWO ((size_t)CC*CC)
#define WT_GWQ ((size_t)2*CC*CC)
#define WT_GWO ((size_t)3*CC*CC)
#define WT_W1  ((size_t)4*CC*CC)
#define WT_W2  ((size_t)4*CC*CC + (size_t)CC*FFN_D)

__device__ __forceinline__ float gelu_exact(float x) {
    return 0.5f * x * (1.0f + erff(x * 0.70710678118654752440f));
}

// ---------------------------------------------------------------------------
// bf16 hi/lo split helper
// ---------------------------------------------------------------------------
__device__ __forceinline__ void cvt_pair(float x, float y, uint32_t& hi, uint32_t& lo) {
    __nv_bfloat16 hx = __float2bfloat16(x);
    __nv_bfloat16 hy = __float2bfloat16(y);
    __nv_bfloat16 lx = __float2bfloat16(x - __bfloat162float(hx));
    __nv_bfloat16 ly = __float2bfloat16(y - __bfloat162float(hy));
    hi = (uint32_t)__bfloat16_as_ushort(hx) | ((uint32_t)__bfloat16_as_ushort(hy) << 16);
    lo = (uint32_t)__bfloat16_as_ushort(lx) | ((uint32_t)__bfloat16_as_ushort(ly) << 16);
}

__device__ __forceinline__ void mma16816(float c[4], uint32_t a0, uint32_t a1, uint32_t a2,
                                         uint32_t a3, uint32_t b0, uint32_t b1) {
    asm volatile(
        "mma.sync.aligned.m16n8k16.row.col.f32.bf16.bf16.f32 "
        "{%0,%1,%2,%3}, {%4,%5,%6,%7}, {%8,%9}, {%0,%1,%2,%3};"
        : "+f"(c[0]), "+f"(c[1]), "+f"(c[2]), "+f"(c[3])
        : "r"(a0), "r"(a1), "r"(a2), "r"(a3), "r"(b0), "r"(b1));
}

// XOR swizzle: word column within a 16-word (64B) row
__device__ __forceinline__ int swz(int row, int kw) {
    int xv = ((row & 7) << 1) | ((row >> 3) & 1);
    return row * 16 + (kw ^ xv);
}

// ---------------------------------------------------------------------------
// HMMA bf16x3-split GEMM:  C[M,N] = A[M,K](f32) @ Bt[N,K](f32, pre-transposed)
// CTA tile 128x128, 8 warps (2x4), warp tile 64x32, K-chunk 32.
// EPI: 0 = store, 2 = gelu(v+bias), 3 = C += v + bias
// Requires M%128==0, N%128==0, K%32==0.
// ---------------------------------------------------------------------------
template <int EPI>
__global__ void __launch_bounds__(256) hmma_gemm_kernel(
    const float* __restrict__ A, int lda,
    const float* __restrict__ Bt,        // N x K row-major
    float* __restrict__ C, int ldc,
    const float* __restrict__ bias,
    int M, int N, int K)
{
    __shared__ uint32_t sAhi[128 * 16];
    __shared__ uint32_t sAlo[128 * 16];
    __shared__ uint32_t sBhi[128 * 16];
    __shared__ uint32_t sBlo[128 * 16];

    const int tid  = threadIdx.x;
    const int wid  = tid >> 5;
    const int lane = tid & 31;
    const int g    = lane >> 2;      // row group 0..7
    const int t4   = lane & 3;       // k-pair selector 0..3
    const int wm   = wid >> 2;       // 0..1  (M dir)
    const int wn   = wid & 3;        // 0..3  (N dir)

    const int m0 = blockIdx.y * 128;
    const int n0 = blockIdx.x * 128;

    float acc[4][4][4];
    #pragma unroll
    for (int i = 0; i < 4; ++i)
        #pragma unroll
        for (int j = 0; j < 4; ++j)
            #pragma unroll
            for (int r = 0; r < 4; ++r) acc[i][j][r] = 0.0f;

    const int r    = tid >> 1;       // fill row 0..127
    const int half = tid & 1;        // which 16-float half of the 32-k chunk

    for (int k0 = 0; k0 < K; k0 += 32) {
        // ---- fill A (128 rows x 32 k) and Bt (128 n-rows x 32 k)
        {
            const float* srcA = A  + (size_t)(m0 + r) * lda + k0 + half * 16;
            const float* srcB = Bt + (size_t)(n0 + r) * K   + k0 + half * 16;
            #pragma unroll
            for (int q = 0; q < 4; ++q) {
                float4 fa = reinterpret_cast<const float4*>(srcA)[q];
                float4 fb = reinterpret_cast<const float4*>(srcB)[q];
                uint32_t h0, l0, h1, l1;
                int kw = half * 8 + q * 2;
                cvt_pair(fa.x, fa.y, h0, l0);
                cvt_pair(fa.z, fa.w, h1, l1);
                sAhi[swz(r, kw)] = h0; sAhi[swz(r, kw + 1)] = h1;
                sAlo[swz(r, kw)] = l0; sAlo[swz(r, kw + 1)] = l1;
                cvt_pair(fb.x, fb.y, h0, l0);
                cvt_pair(fb.z, fb.w, h1, l1);
                sBhi[swz(r, kw)] = h0; sBhi[swz(r, kw + 1)] = h1;
                sBlo[swz(r, kw)] = l0; sBlo[swz(r, kw + 1)] = l1;
            }
        }
        __syncthreads();

        // ---- 3 passes: Ah*Bh, Ah*Bl, Al*Bh
        #pragma unroll
        for (int pass = 0; pass < 3; ++pass) {
            const uint32_t* pa = (pass == 2) ? sAlo : sAhi;
            const uint32_t* pb = (pass == 1) ? sBlo : sBhi;
            #pragma unroll
            for (int ks = 0; ks < 2; ++ks) {
                uint32_t afr[4][4];
                #pragma unroll
                for (int mi = 0; mi < 4; ++mi) {
                    int r0 = wm * 64 + mi * 16 + g;
                    int r1 = r0 + 8;
                    int kw = ks * 8 + t4;
                    afr[mi][0] = pa[swz(r0, kw)];
                    afr[mi][1] = pa[swz(r1, kw)];
                    afr[mi][2] = pa[swz(r0, kw + 4)];
                    afr[mi][3] = pa[swz(r1, kw + 4)];
                }
                uint32_t bfr[4][2];
                #pragma unroll
                for (int ni = 0; ni < 4; ++ni) {
                    int nr = wn * 32 + ni * 8 + g;
                    int kw = ks * 8 + t4;
                    bfr[ni][0] = pb[swz(nr, kw)];
                    bfr[ni][1] = pb[swz(nr, kw + 4)];
                }
                #pragma unroll
                for (int mi = 0; mi < 4; ++mi)
                    #pragma unroll
                    for (int ni = 0; ni < 4; ++ni)
                        mma16816(acc[mi][ni], afr[mi][0], afr[mi][1], afr[mi][2],
                                 afr[mi][3], bfr[ni][0], bfr[ni][1]);
            }
        }
        __syncthreads();
    }

    // ---- epilogue
    #pragma unroll
    for (int mi = 0; mi < 4; ++mi) {
        #pragma unroll
        for (int ni = 0; ni < 4; ++ni) {
            int row0 = m0 + wm * 64 + mi * 16 + g;
            int col  = n0 + wn * 32 + ni * 8 + 2 * t4;
            float* c = acc[mi][ni];
            #pragma unroll
            for (int h = 0; h < 2; ++h) {
                int row = row0 + h * 8;
                float v0 = c[2 * h], v1 = c[2 * h + 1];
                size_t off = (size_t)row * ldc + col;
                if (EPI == 2) {
                    v0 = gelu_exact(v0 + bias[col]);
                    v1 = gelu_exact(v1 + bias[col + 1]);
                } else if (EPI == 3) {
                    v0 += bias[col]     + C[off];
                    v1 += bias[col + 1] + C[off + 1];
                }
                float2 o; o.x = v0; o.y = v1;
                *reinterpret_cast<float2*>(&C[off]) = o;
            }
        }
    }
}

template <int EPI>
static void launch_hmma_gemm(const float* A, int lda, const float* Bt,
                             float* C, int ldc, const float* bias,
                             int M, int N, int K) {
    dim3 grid(N / 128, M / 128);
    hmma_gemm_kernel<EPI><<<grid, 256>>>(A, lda, Bt, C, ldc, bias, M, N, K);
}

// ---------------------------------------------------------------------------
// Transpose: in (batch, R, Cc) -> out (batch, Cc, R)
// ---------------------------------------------------------------------------
__global__ void transpose_kernel(const float* __restrict__ in, float* __restrict__ out,
                                 int R, int Ccol) {
    __shared__ float tile[32][33];
    int b = blockIdx.z;
    const float* ip = in  + (size_t)b * R * Ccol;
    float*       op = out + (size_t)b * R * Ccol;
    int j0 = blockIdx.x * 32;
    int i0 = blockIdx.y * 32;
    int tx = threadIdx.x, ty = threadIdx.y;
    #pragma unroll
    for (int k = 0; k < 32; k += 8) {
        int i = i0 + ty + k, j = j0 + tx;
        if (i < R && j < Ccol) tile[ty + k][tx] = ip[(size_t)i * Ccol + j];
    }
    __syncthreads();
    #pragma unroll
    for (int k = 0; k < 32; k += 8) {
        int j = j0 + ty + k, i = i0 + tx;
        if (j < Ccol && i < R) op[(size_t)j * R + i] = tile[tx][ty + k];
    }
}

// ---------------------------------------------------------------------------
// LayerNorm over C=512. One block (128 threads) per row.
// ---------------------------------------------------------------------------
template <bool ADD>
__global__ void ln_kernel(const float* __restrict__ in,
                          const float* __restrict__ gamma,
                          const float* __restrict__ beta,
                          float* __restrict__ out) {
    int row = blockIdx.x;
    const float4* rin = reinterpret_cast<const float4*>(in + (size_t)row * CC);
    float4* rout = reinterpret_cast<float4*>(out + (size_t)row * CC);
    int t = threadIdx.x;
    float4 v = rin[t];
    float s  = v.x + v.y + v.z + v.w;
    float ss = v.x*v.x + v.y*v.y + v.z*v.z + v.w*v.w;
    #pragma unroll
    for (int o = 16; o > 0; o >>= 1) {
        s  += __shfl_xor_sync(0xffffffffu, s,  o);
        ss += __shfl_xor_sync(0xffffffffu, ss, o);
    }
    __shared__ float shs[4], shss[4];
    int warp = t >> 5, lane = t & 31;
    if (lane == 0) { shs[warp] = s; shss[warp] = ss; }
    __syncthreads();
    s  = shs[0] + shs[1] + shs[2] + shs[3];
    ss = shss[0] + shss[1] + shss[2] + shss[3];
    float mu  = s * (1.0f / CC);
    float var = ss * (1.0f / CC) - mu * mu;
    float rs  = rsqrtf(var + LN_EPS);
    float4 g4 = reinterpret_cast<const float4*>(gamma)[t];
    float4 b4 = reinterpret_cast<const float4*>(beta)[t];
    float4 o4;
    o4.x = (v.x - mu) * rs * g4.x + b4.x;
    o4.y = (v.y - mu) * rs * g4.y + b4.y;
    o4.z = (v.z - mu) * rs * g4.z + b4.z;
    o4.w = (v.w - mu) * rs * g4.w + b4.w;
    if (ADD) { o4.x += v.x; o4.y += v.y; o4.z += v.z; o4.w += v.w; }
    rout[t] = o4;
}

// ---------------------------------------------------------------------------
// Softmax (in-place), one warp per row
// ---------------------------------------------------------------------------
__global__ void softmax_kernel(float* __restrict__ data, long long rows, int S) {
    long long row = (long long)blockIdx.x * 4 + (threadIdx.x >> 5);
    if (row >= rows) return;
    float* p = data + row * (long long)S;
    int lane = threadIdx.x & 31;
    float mx = -1e30f;
    for (int j = lane; j < S; j += 32) mx = fmaxf(mx, p[j]);
    #pragma unroll
    for (int o = 16; o > 0; o >>= 1) mx = fmaxf(mx, __shfl_xor_sync(0xffffffffu, mx, o));
    float sum = 0.0f;
    for (int j = lane; j < S; j += 32) { float e = __expf(p[j] - mx); p[j] = e; sum += e; }
    #pragma unroll
    for (int o = 16; o > 0; o >>= 1) sum += __shfl_xor_sync(0xffffffffu, sum, o);
    float inv = 1.0f / sum;
    for (int j = lane; j < S; j += 32) p[j] *= inv;
}

// ---------------------------------------------------------------------------
// fp32 SGEMM (attention einsums + K/V projections)
// ---------------------------------------------------------------------------
template <bool TRANSB, int EPI>
__global__ void sgemm_kernel(const float* __restrict__ A, int lda, long long sAb, long long sAh,
                             const float* __restrict__ B, int ldb, long long sBb, long long sBh,
                             float* __restrict__ C, int ldc, long long sCb, long long sCh,
                             const float* __restrict__ bias,
                             int M, int N, int K, float alpha, int H) {
    const int BM = 64, BN = 64, BK = 16;
    __shared__ __align__(16) float sA[BK][BM + 4];
    __shared__ __align__(16) float sB[BK][BN + 4];

    int z = blockIdx.z;
    int bb = z / H, hh = z % H;
    A += bb * sAb + hh * sAh;
    B += bb * sBb + hh * sBh;
    C += bb * sCb + hh * sCh;

    int tid = threadIdx.x;
    int tx = tid & 15, ty = tid >> 4;
    int row0 = blockIdx.y * BM;
    int col0 = blockIdx.x * BN;

    float acc[4][4] = {};

    for (int k0 = 0; k0 < K; k0 += BK) {
        #pragma unroll
        for (int rr = 0; rr < 4; rr++) {
            int idx = tid + rr * 256;
            int m = idx / BK, kk = idx % BK;
            int gm = row0 + m, gk = k0 + kk;
            sA[kk][m] = (gm < M && gk < K) ? A[(size_t)gm * lda + gk] : 0.0f;
        }
        #pragma unroll
        for (int rr = 0; rr < 4; rr++) {
            int idx = tid + rr * 256;
            if (!TRANSB) {
                int kk = idx / BN, n = idx % BN;
                int gk = k0 + kk, gn = col0 + n;
                sB[kk][n] = (gk < K && gn < N) ? B[(size_t)gk * ldb + gn] : 0.0f;
            } else {
                int n = idx / BK, kk = idx % BK;
                int gn = col0 + n, gk = k0 + kk;
                sB[kk][n] = (gn < N && gk < K) ? B[(size_t)gn * ldb + gk] : 0.0f;
            }
        }
        __syncthreads();
        #pragma unroll
        for (int kk = 0; kk < BK; kk++) {
            float4 a4 = *reinterpret_cast<const float4*>(&sA[kk][ty * 4]);
            float4 b4 = *reinterpret_cast<const float4*>(&sB[kk][tx * 4]);
            float a[4] = {a4.x, a4.y, a4.z, a4.w};
            float b[4] = {b4.x, b4.y, b4.z, b4.w};
            #pragma unroll
            for (int i = 0; i < 4; i++)
                #pragma unroll
                for (int j = 0; j < 4; j++)
                    acc[i][j] += a[i] * b[j];
        }
        __syncthreads();
    }

    #pragma unroll
    for (int i = 0; i < 4; i++) {
        int gm = row0 + ty * 4 + i;
        if (gm >= M) continue;
        #pragma unroll
        for (int j = 0; j < 4; j++) {
            int gn = col0 + tx * 4 + j;
            if (gn >= N) continue;
            size_t off = (size_t)gm * ldc + gn;
            float v = acc[i][j] * alpha;
            if (EPI == 1) {
                v += bias[gn];
            } else if (EPI == 2) {
                v = gelu_exact(v + bias[gn]);
            } else if (EPI == 3) {
                v += bias[gn] + C[off];
            }
            C[off] = v;
        }
    }
}

static inline int ceil_div(int a, int b) { return (a + b - 1) / b; }

template <bool TRANSB, int EPI>
static void launch_gemm(const float* A, int lda, long long sAb, long long sAh,
                        const float* B, int ldb, long long sBb, long long sBh,
                        float* C, int ldc, long long sCb, long long sCh,
                        const float* bias, int M, int N, int K, float alpha,
                        int batches, int H) {
    dim3 grid(ceil_div(N, 64), ceil_div(M, 64), batches);
    sgemm_kernel<TRANSB, EPI><<<grid, 256>>>(A, lda, sAb, sAh, B, ldb, sBb, sBh,
                                             C, ldc, sCb, sCh, bias, M, N, K, alpha, H);
}

// ---------------------------------------------------------------------------
// Cross-attention sublayer (Q and O projections on the HMMA path)
// ---------------------------------------------------------------------------
static void cross_attention(float* t_dev, float* xn_dev, float* q_dev, float* attn_dev,
                            float* k_dev, float* v_dev, float* scores_dev,
                            const float* gamma, const float* beta,
                            const float* kv_src, int S, int D,
                            const float* Wqt,               // transposed Wq (N x K)
                            const float* Wk, const float* Wv,
                            const float* Wot,               // transposed Wo
                            const float* bo) {
    ln_kernel<false><<<NROWS, 128>>>(t_dev, gamma, beta, xn_dev);
    // Q = xn @ Wq
    launch_hmma_gemm<0>(xn_dev, CC, Wqt, q_dev, CC, nullptr, NROWS, CC, CC);
    // K,V projections (small, fp32)
    int MK = BATCH * S;
    launch_gemm<false, 0>(kv_src, D, 0, 0, Wk, CC, 0, 0, k_dev, CC, 0, 0,
                          nullptr, MK, CC, D, 1.0f, 1, 1);
    launch_gemm<false, 0>(kv_src, D, 0, 0, Wv, CC, 0, 0, v_dev, CC, 0, 0,
                          nullptr, MK, CC, D, 1.0f, 1, 1);
    // scores
    launch_gemm<true, 0>(q_dev, CC, (long long)NTOK * CC, HD,
                         k_dev, CC, (long long)S * CC, HD,
                         scores_dev, S, (long long)HHEADS * NTOK * S, (long long)NTOK * S,
                         nullptr, NTOK, S, HD, 0.125f, BATCH * HHEADS, HHEADS);
    long long rows = (long long)BATCH * HHEADS * NTOK;
    softmax_kernel<<<(unsigned)((rows + 3) / 4), 128>>>(scores_dev, rows, S);
    // P @ V
    launch_gemm<false, 0>(scores_dev, S, (long long)HHEADS * NTOK * S, (long long)NTOK * S,
                          v_dev, CC, (long long)S * CC, HD,
                          attn_dev, CC, (long long)NTOK * CC, HD,
                          nullptr, NTOK, HD, S, 1.0f, BATCH * HHEADS, HHEADS);
    // t += attn @ Wo + bo
    launch_hmma_gemm<3>(attn_dev, CC, Wot, t_dev, CC, bo, NROWS, CC, CC);
}

// ---------------------------------------------------------------------------
// Entry
// ---------------------------------------------------------------------------
extern "C" void kernel_launch(void* const* d_in, const int* in_sizes, int n_in,
                              void* d_out, int out_size) {
    const float* x    = (const float*)d_in[0];
    const float* ctx  = (const float*)d_in[1];
    const float* geo  = (const float*)d_in[2];
    const float* g1 = (const float*)d_in[3],  *b1 = (const float*)d_in[4];
    const float* g2 = (const float*)d_in[5],  *b2 = (const float*)d_in[6];
    const float* g3 = (const float*)d_in[7],  *b3 = (const float*)d_in[8];
    const float* g4 = (const float*)d_in[9],  *b4 = (const float*)d_in[10];
    const float* cWq = (const float*)d_in[11], *cWk = (const float*)d_in[12];
    const float* cWv = (const float*)d_in[13], *cWo = (const float*)d_in[14];
    const float* cbo = (const float*)d_in[15];
    const float* gWq = (const float*)d_in[16], *gWk = (const float*)d_in[17];
    const float* gWv = (const float*)d_in[18], *gWo = (const float*)d_in[19];
    const float* gbo = (const float*)d_in[20];
    const float* W1  = (const float*)d_in[21], *bf1 = (const float*)d_in[22];
    const float* W2  = (const float*)d_in[23], *bf2 = (const float*)d_in[24];
    float* out = (float*)d_out;

    float *t_dev, *xn_dev, *q_dev, *attn_dev, *k_dev, *v_dev, *big_dev, *wt_dev;
    cudaGetSymbolAddress((void**)&t_dev,    g_t);
    cudaGetSymbolAddress((void**)&xn_dev,   g_xn);
    cudaGetSymbolAddress((void**)&q_dev,    g_q);
    cudaGetSymbolAddress((void**)&attn_dev, g_attn);
    cudaGetSymbolAddress((void**)&k_dev,    g_k);
    cudaGetSymbolAddress((void**)&v_dev,    g_v);
    cudaGetSymbolAddress((void**)&big_dev,  g_big);
    cudaGetSymbolAddress((void**)&wt_dev,   g_wt);

    // ---- pre-transpose weights for the HMMA GEMM (Bt = N x K)
    {
        dim3 blk(32, 8);
        dim3 gr1(CC / 32, CC / 32, 1);
        transpose_kernel<<<gr1, blk>>>(cWq, wt_dev + WT_CWQ, CC, CC);
        transpose_kernel<<<gr1, blk>>>(cWo, wt_dev + WT_CWO, CC, CC);
        transpose_kernel<<<gr1, blk>>>(gWq, wt_dev + WT_GWQ, CC, CC);
        transpose_kernel<<<gr1, blk>>>(gWo, wt_dev + WT_GWO, CC, CC);
        dim3 gr2(FFN_D / 32, CC / 32, 1);     // W1: 512 x 2048 -> 2048 x 512
        transpose_kernel<<<gr2, blk>>>(W1, wt_dev + WT_W1, CC, FFN_D);
        dim3 gr3(CC / 32, FFN_D / 32, 1);     // W2: 2048 x 512 -> 512 x 2048
        transpose_kernel<<<gr3, blk>>>(W2, wt_dev + WT_W2, FFN_D, CC);
    }

    // 1) transpose x (B,C,N) -> t0 (B,N,C)
    {
        dim3 grid(NTOK / 32, CC / 32, BATCH);
        transpose_kernel<<<grid, dim3(32, 8)>>>(x, xn_dev, CC, NTOK);
    }
    // 2) t = t0 + LN1(t0)
    ln_kernel<true><<<NROWS, 128>>>(xn_dev, g1, b1, t_dev);

    // 3) context cross-attention
    cross_attention(t_dev, xn_dev, q_dev, attn_dev, k_dev, v_dev, big_dev,
                    g2, b2, ctx, CTX_S, CTX_D,
                    wt_dev + WT_CWQ, cWk, cWv, wt_dev + WT_CWO, cbo);

    // 4) geometry cross-attention
    cross_attention(t_dev, xn_dev, q_dev, attn_dev, k_dev, v_dev, big_dev,
                    g3, b3, geo, GEO_S, GEO_D,
                    wt_dev + WT_GWQ, gWk, gWv, wt_dev + WT_GWO, gbo);

    // 5) FFN
    ln_kernel<false><<<NROWS, 128>>>(t_dev, g4, b4, xn_dev);
    launch_hmma_gemm<2>(xn_dev, CC, wt_dev + WT_W1, big_dev, FFN_D, bf1, NROWS, FFN_D, CC);
    launch_hmma_gemm<3>(big_dev, FFN_D, wt_dev + WT_W2, t_dev, CC, bf2, NROWS, CC, FFN_D);

    // 6) transpose back
    {
        dim3 grid(CC / 32, NTOK / 32, BATCH);
        transpose_kernel<<<grid, dim3(32, 8)>>>(t_dev, out, NTOK, CC);
    }
}

// round 5
// speedup vs baseline: 1.4048x; 1.0538x over previous
#include <cuda_runtime.h>
#include <cuda_bf16.h>
#include <cstdint>
#include <cstddef>

// ---------------------------------------------------------------------------
// Problem constants
// ---------------------------------------------------------------------------
#define BATCH   4
#define CC      512
#define NTOK    4096
#define NROWS   (BATCH*NTOK)
#define HHEADS  8
#define HD      64
#define CTX_S   77
#define CTX_D   768
#define GEO_S   256
#define GEO_D   512
#define FFN_D   2048
#define LN_EPS  1e-5f

// ---------------------------------------------------------------------------
// Scratch (static device globals)
// ---------------------------------------------------------------------------
__device__ float g_t   [(size_t)NROWS * CC];
__device__ float g_xn  [(size_t)NROWS * CC];
__device__ float g_q   [(size_t)NROWS * CC];
__device__ float g_attn[(size_t)NROWS * CC];
__device__ float g_k   [(size_t)BATCH * GEO_S * CC];
__device__ float g_v   [(size_t)BATCH * GEO_S * CC];
__device__ float g_big [(size_t)NROWS * FFN_D];

// transposed weights
#define WT_CWQ 0
#define WT_CWO ((size_t)CC*CC)
#define WT_GWQ ((size_t)2*CC*CC)
#define WT_GWO ((size_t)3*CC*CC)
#define WT_W1  ((size_t)4*CC*CC)
#define WT_W2  (WT_W1 + (size_t)CC*FFN_D)
#define WT_CWK (WT_W2 + (size_t)CC*FFN_D)
#define WT_CWV (WT_CWK + (size_t)CC*CTX_D)
#define WT_GWK (WT_CWV + (size_t)CC*CTX_D)
#define WT_GWV (WT_GWK + (size_t)CC*GEO_D)
#define WT_END (WT_GWV + (size_t)CC*GEO_D)
__device__ float g_wt[WT_END];

__device__ __forceinline__ float gelu_exact(float x) {
    return 0.5f * x * (1.0f + erff(x * 0.70710678118654752440f));
}

// ---------------------------------------------------------------------------
// bf16 hi/lo split + MMA helpers
// ---------------------------------------------------------------------------
__device__ __forceinline__ void cvt_pair(float x, float y, uint32_t& hi, uint32_t& lo) {
    __nv_bfloat16 hx = __float2bfloat16(x);
    __nv_bfloat16 hy = __float2bfloat16(y);
    __nv_bfloat16 lx = __float2bfloat16(x - __bfloat162float(hx));
    __nv_bfloat16 ly = __float2bfloat16(y - __bfloat162float(hy));
    hi = (uint32_t)__bfloat16_as_ushort(hx) | ((uint32_t)__bfloat16_as_ushort(hy) << 16);
    lo = (uint32_t)__bfloat16_as_ushort(lx) | ((uint32_t)__bfloat16_as_ushort(ly) << 16);
}

__device__ __forceinline__ void mma16816(float c[4], uint32_t a0, uint32_t a1, uint32_t a2,
                                         uint32_t a3, uint32_t b0, uint32_t b1) {
    asm volatile(
        "mma.sync.aligned.m16n8k16.row.col.f32.bf16.bf16.f32 "
        "{%0,%1,%2,%3}, {%4,%5,%6,%7}, {%8,%9}, {%0,%1,%2,%3};"
        : "+f"(c[0]), "+f"(c[1]), "+f"(c[2]), "+f"(c[3])
        : "r"(a0), "r"(a1), "r"(a2), "r"(a3), "r"(b0), "r"(b1));
}

__device__ __forceinline__ int swz(int row, int kw) {
    int xv = ((row & 7) << 1) | ((row >> 3) & 1);
    return row * 16 + (kw ^ xv);
}

// ---------------------------------------------------------------------------
// Unified HMMA bf16x3-split GEMM.
//   C[M,N] = alpha * A[M,K] @ Bt[N,K]^T  (+ epilogue)
// NT: 128 (warps 2x4, warptile 64x32) or 64 (warps 4x2, warptile 32x32).
// GN: guard N (cols may exceed N; scalar-guarded B fill rows + epilogue stores)
// GM: guard M (rows may exceed M)
// GK: K not multiple of 32 and/or A rows unaligned -> scalar guarded A fill
// TRB: B supplied as K-major matrix (Bt[n][k] = B[k*ldb + n]); only with NT=64
// EPI: 0 = store, 2 = gelu(v+bias), 3 = C += v + bias
// Batched via grid.z: z -> (bb = z/H, hh = z%H), strides per operand.
// ---------------------------------------------------------------------------
template <int NT, int EPI, bool GN, bool GM, bool GK, bool TRB>
__global__ void __launch_bounds__(256) hmma_kernel(
    const float* __restrict__ A, int lda, long long sAb, long long sAh,
    const float* __restrict__ B, int ldb, long long sBb, long long sBh,
    float* __restrict__ C, int ldc, long long sCb, long long sCh,
    const float* __restrict__ bias,
    int M, int N, int K, float alpha, int H)
{
    constexpr int MI = (NT == 128) ? 4 : 2;   // m16 tiles per warp
    __shared__ uint32_t sAhi[128 * 16];
    __shared__ uint32_t sAlo[128 * 16];
    __shared__ uint32_t sBhi[NT * 16];
    __shared__ uint32_t sBlo[NT * 16];

    {
        int z = blockIdx.z;
        int bb = z / H, hh = z % H;
        A += bb * sAb + hh * sAh;
        B += bb * sBb + hh * sBh;
        C += bb * sCb + hh * sCh;
    }

    const int tid  = threadIdx.x;
    const int wid  = tid >> 5;
    const int lane = tid & 31;
    const int g    = lane >> 2;
    const int t4   = lane & 3;
    const int wm   = (NT == 128) ? (wid >> 2) : (wid >> 1);
    const int wn   = (NT == 128) ? (wid & 3)  : (wid & 1);

    const int m0 = blockIdx.y * 128;
    const int n0 = blockIdx.x * NT;

    float acc[MI][4][4];
    #pragma unroll
    for (int i = 0; i < MI; ++i)
        #pragma unroll
        for (int j = 0; j < 4; ++j)
            #pragma unroll
            for (int r = 0; r < 4; ++r) acc[i][j][r] = 0.0f;

    const int nch = (K + 31) >> 5;
    for (int ch = 0; ch < nch; ++ch) {
        const int k0 = ch << 5;

        // ---------------- A fill: 128 rows x 32 k ----------------
        {
            const int r = tid >> 1, half = tid & 1;
            const int gm = m0 + r;
            const bool mok = !GM || (gm < M);
            if (!GK) {
                const float* src = A + (size_t)gm * lda + k0 + half * 16;
                #pragma unroll
                for (int q = 0; q < 4; ++q) {
                    float4 fa = mok ? reinterpret_cast<const float4*>(src)[q]
                                    : make_float4(0.f, 0.f, 0.f, 0.f);
                    uint32_t h0, l0, h1, l1;
                    int kw = half * 8 + q * 2;
                    cvt_pair(fa.x, fa.y, h0, l0);
                    cvt_pair(fa.z, fa.w, h1, l1);
                    sAhi[swz(r, kw)] = h0; sAhi[swz(r, kw + 1)] = h1;
                    sAlo[swz(r, kw)] = l0; sAlo[swz(r, kw + 1)] = l1;
                }
            } else {
                const float* src = A + (size_t)gm * lda;
                #pragma unroll
                for (int q = 0; q < 8; ++q) {
                    int k = k0 + half * 16 + q * 2;
                    float x = (mok && k     < K) ? src[k]     : 0.f;
                    float y = (mok && k + 1 < K) ? src[k + 1] : 0.f;
                    uint32_t h, l;
                    cvt_pair(x, y, h, l);
                    int kw = half * 8 + q;
                    sAhi[swz(r, kw)] = h;
                    sAlo[swz(r, kw)] = l;
                }
            }
        }

        // ---------------- B fill ----------------
        if (!TRB) {
            // NT==128 path: Bt rows are rows of B (N x K row-major)
            const int r = tid >> 1, half = tid & 1;
            const bool nok = !GN || (n0 + r < N);
            const float* src = B + (size_t)(n0 + r) * ldb + k0 + half * 16;
            #pragma unroll
            for (int q = 0; q < 4; ++q) {
                float4 fb = nok ? reinterpret_cast<const float4*>(src)[q]
                                : make_float4(0.f, 0.f, 0.f, 0.f);
                uint32_t h0, l0, h1, l1;
                int kw = half * 8 + q * 2;
                cvt_pair(fb.x, fb.y, h0, l0);
                cvt_pair(fb.z, fb.w, h1, l1);
                sBhi[swz(r, kw)] = h0; sBhi[swz(r, kw + 1)] = h1;
                sBlo[swz(r, kw)] = l0; sBlo[swz(r, kw + 1)] = l1;
            }
        } else {
            // NT==64 path: Bt[n][k] = B[k*ldb + n], coalesced over n
            const int n  = tid & 63;
            const int kp = tid >> 6;       // 0..3
            const float* src = B + n0 + n;
            #pragma unroll
            for (int j = 0; j < 4; ++j) {
                int kw = kp + j * 4;
                int k  = k0 + kw * 2;
                float x = (!GK || k     < K) ? src[(size_t)k       * ldb] : 0.f;
                float y = (!GK || k + 1 < K) ? src[(size_t)(k + 1) * ldb] : 0.f;
                uint32_t h, l;
                cvt_pair(x, y, h, l);
                sBhi[swz(n, kw)] = h;
                sBlo[swz(n, kw)] = l;
            }
        }
        __syncthreads();

        // ---------------- 3 passes: Ah*Bh, Ah*Bl, Al*Bh ----------------
        #pragma unroll
        for (int pass = 0; pass < 3; ++pass) {
            const uint32_t* pa = (pass == 2) ? sAlo : sAhi;
            const uint32_t* pb = (pass == 1) ? sBlo : sBhi;
            #pragma unroll
            for (int ks = 0; ks < 2; ++ks) {
                uint32_t afr[MI][4];
                #pragma unroll
                for (int mi = 0; mi < MI; ++mi) {
                    int r0 = wm * (MI * 16) + mi * 16 + g;
                    int r1 = r0 + 8;
                    int kw = ks * 8 + t4;
                    afr[mi][0] = pa[swz(r0, kw)];
                    afr[mi][1] = pa[swz(r1, kw)];
                    afr[mi][2] = pa[swz(r0, kw + 4)];
                    afr[mi][3] = pa[swz(r1, kw + 4)];
                }
                uint32_t bfr[4][2];
                #pragma unroll
                for (int ni = 0; ni < 4; ++ni) {
                    int nr = wn * 32 + ni * 8 + g;
                    int kw = ks * 8 + t4;
                    bfr[ni][0] = pb[swz(nr, kw)];
                    bfr[ni][1] = pb[swz(nr, kw + 4)];
                }
                #pragma unroll
                for (int mi = 0; mi < MI; ++mi)
                    #pragma unroll
                    for (int ni = 0; ni < 4; ++ni)
                        mma16816(acc[mi][ni], afr[mi][0], afr[mi][1], afr[mi][2],
                                 afr[mi][3], bfr[ni][0], bfr[ni][1]);
            }
        }
        __syncthreads();
    }

    // ---------------- epilogue ----------------
    #pragma unroll
    for (int mi = 0; mi < MI; ++mi) {
        #pragma unroll
        for (int ni = 0; ni < 4; ++ni) {
            int row0 = m0 + wm * (MI * 16) + mi * 16 + g;
            int col  = n0 + wn * 32 + ni * 8 + 2 * t4;
            float* c = acc[mi][ni];
            #pragma unroll
            for (int h = 0; h < 2; ++h) {
                int row = row0 + h * 8;
                if (GM && row >= M) continue;
                float v0 = c[2 * h] * alpha, v1 = c[2 * h + 1] * alpha;
                size_t off = (size_t)row * ldc + col;
                if (GN) {
                    // scalar guarded stores
                    if (col < N) {
                        float v = v0;
                        if (EPI == 2)      v = gelu_exact(v + bias[col]);
                        else if (EPI == 3) v = v + bias[col] + C[off];
                        C[off] = v;
                    }
                    if (col + 1 < N) {
                        float v = v1;
                        if (EPI == 2)      v = gelu_exact(v + bias[col + 1]);
                        else if (EPI == 3) v = v + bias[col + 1] + C[off + 1];
                        C[off + 1] = v;
                    }
                } else {
                    if (EPI == 2) {
                        v0 = gelu_exact(v0 + bias[col]);
                        v1 = gelu_exact(v1 + bias[col + 1]);
                    } else if (EPI == 3) {
                        v0 += bias[col]     + C[off];
                        v1 += bias[col + 1] + C[off + 1];
                    }
                    float2 o; o.x = v0; o.y = v1;
                    *reinterpret_cast<float2*>(&C[off]) = o;
                }
            }
        }
    }
}

static inline int ceil_div(int a, int b) { return (a + b - 1) / b; }

template <int NT, int EPI, bool GN, bool GM, bool GK, bool TRB>
static void launch_hmma(const float* A, int lda, long long sAb, long long sAh,
                        const float* B, int ldb, long long sBb, long long sBh,
                        float* C, int ldc, long long sCb, long long sCh,
                        const float* bias, int M, int N, int K, float alpha,
                        int batches, int H) {
    dim3 grid(ceil_div(N, NT), ceil_div(M, 128), batches);
    hmma_kernel<NT, EPI, GN, GM, GK, TRB><<<grid, 256>>>(
        A, lda, sAb, sAh, B, ldb, sBb, sBh, C, ldc, sCb, sCh,
        bias, M, N, K, alpha, H);
}

// simple (non-batched) weight-style GEMM: C = A @ Bt^T
template <int EPI>
static void launch_hmma_gemm(const float* A, int lda, const float* Bt,
                             float* C, int ldc, const float* bias,
                             int M, int N, int K) {
    launch_hmma<128, EPI, false, false, false, false>(
        A, lda, 0, 0, Bt, K, 0, 0, C, ldc, 0, 0, bias, M, N, K, 1.0f, 1, 1);
}

// ---------------------------------------------------------------------------
// Transpose: in (batch, R, Cc) -> out (batch, Cc, R)
// ---------------------------------------------------------------------------
__global__ void transpose_kernel(const float* __restrict__ in, float* __restrict__ out,
                                 int R, int Ccol) {
    __shared__ float tile[32][33];
    int b = blockIdx.z;
    const float* ip = in  + (size_t)b * R * Ccol;
    float*       op = out + (size_t)b * R * Ccol;
    int j0 = blockIdx.x * 32;
    int i0 = blockIdx.y * 32;
    int tx = threadIdx.x, ty = threadIdx.y;
    #pragma unroll
    for (int k = 0; k < 32; k += 8) {
        int i = i0 + ty + k, j = j0 + tx;
        if (i < R && j < Ccol) tile[ty + k][tx] = ip[(size_t)i * Ccol + j];
    }
    __syncthreads();
    #pragma unroll
    for (int k = 0; k < 32; k += 8) {
        int j = j0 + ty + k, i = i0 + tx;
        if (j < Ccol && i < R) op[(size_t)j * R + i] = tile[tx][ty + k];
    }
}

// ---------------------------------------------------------------------------
// LayerNorm
// ---------------------------------------------------------------------------
template <bool ADD>
__global__ void ln_kernel(const float* __restrict__ in,
                          const float* __restrict__ gamma,
                          const float* __restrict__ beta,
                          float* __restrict__ out) {
    int row = blockIdx.x;
    const float4* rin = reinterpret_cast<const float4*>(in + (size_t)row * CC);
    float4* rout = reinterpret_cast<float4*>(out + (size_t)row * CC);
    int t = threadIdx.x;
    float4 v = rin[t];
    float s  = v.x + v.y + v.z + v.w;
    float ss = v.x*v.x + v.y*v.y + v.z*v.z + v.w*v.w;
    #pragma unroll
    for (int o = 16; o > 0; o >>= 1) {
        s  += __shfl_xor_sync(0xffffffffu, s,  o);
        ss += __shfl_xor_sync(0xffffffffu, ss, o);
    }
    __shared__ float shs[4], shss[4];
    int warp = t >> 5, lane = t & 31;
    if (lane == 0) { shs[warp] = s; shss[warp] = ss; }
    __syncthreads();
    s  = shs[0] + shs[1] + shs[2] + shs[3];
    ss = shss[0] + shss[1] + shss[2] + shss[3];
    float mu  = s * (1.0f / CC);
    float var = ss * (1.0f / CC) - mu * mu;
    float rs  = rsqrtf(var + LN_EPS);
    float4 g4 = reinterpret_cast<const float4*>(gamma)[t];
    float4 b4 = reinterpret_cast<const float4*>(beta)[t];
    float4 o4;
    o4.x = (v.x - mu) * rs * g4.x + b4.x;
    o4.y = (v.y - mu) * rs * g4.y + b4.y;
    o4.z = (v.z - mu) * rs * g4.z + b4.z;
    o4.w = (v.w - mu) * rs * g4.w + b4.w;
    if (ADD) { o4.x += v.x; o4.y += v.y; o4.z += v.z; o4.w += v.w; }
    rout[t] = o4;
}

// ---------------------------------------------------------------------------
// Softmax (in-place), one warp per row
// ---------------------------------------------------------------------------
__global__ void softmax_kernel(float* __restrict__ data, long long rows, int S) {
    long long row = (long long)blockIdx.x * 4 + (threadIdx.x >> 5);
    if (row >= rows) return;
    float* p = data + row * (long long)S;
    int lane = threadIdx.x & 31;
    float mx = -1e30f;
    for (int j = lane; j < S; j += 32) mx = fmaxf(mx, p[j]);
    #pragma unroll
    for (int o = 16; o > 0; o >>= 1) mx = fmaxf(mx, __shfl_xor_sync(0xffffffffu, mx, o));
    float sum = 0.0f;
    for (int j = lane; j < S; j += 32) { float e = __expf(p[j] - mx); p[j] = e; sum += e; }
    #pragma unroll
    for (int o = 16; o > 0; o >>= 1) sum += __shfl_xor_sync(0xffffffffu, sum, o);
    float inv = 1.0f / sum;
    for (int j = lane; j < S; j += 32) p[j] *= inv;
}

// ---------------------------------------------------------------------------
// Cross-attention sublayer (all GEMMs on HMMA)
// ---------------------------------------------------------------------------
template <int S, int D, bool GN_SC, bool GM_KV, bool GK_PV>
static void cross_attention(float* t_dev, float* xn_dev, float* q_dev, float* attn_dev,
                            float* k_dev, float* v_dev, float* scores_dev,
                            const float* gamma, const float* beta,
                            const float* kv_src,
                            const float* Wqt, const float* Wkt, const float* Wvt,
                            const float* Wot, const float* bo) {
    ln_kernel<false><<<NROWS, 128>>>(t_dev, gamma, beta, xn_dev);
    // Q = xn @ Wq
    launch_hmma_gemm<0>(xn_dev, CC, Wqt, q_dev, CC, nullptr, NROWS, CC, CC);
    // K,V projections
    constexpr int MK = BATCH * S;
    launch_hmma<128, 0, false, GM_KV, false, false>(
        kv_src, D, 0, 0, Wkt, D, 0, 0, k_dev, CC, 0, 0,
        nullptr, MK, CC, D, 1.0f, 1, 1);
    launch_hmma<128, 0, false, GM_KV, false, false>(
        kv_src, D, 0, 0, Wvt, D, 0, 0, v_dev, CC, 0, 0,
        nullptr, MK, CC, D, 1.0f, 1, 1);
    // scores[b,h] = 0.125 * Q[b,:,h] @ K[b,:,h]^T   (M=4096, N=S, K=64)
    launch_hmma<128, 0, GN_SC, false, false, false>(
        q_dev, CC, (long long)NTOK * CC, HD,
        k_dev, CC, (long long)S * CC, HD,
        scores_dev, S, (long long)HHEADS * NTOK * S, (long long)NTOK * S,
        nullptr, NTOK, S, HD, 0.125f, BATCH * HHEADS, HHEADS);
    // softmax over S
    long long rows = (long long)BATCH * HHEADS * NTOK;
    softmax_kernel<<<(unsigned)((rows + 3) / 4), 128>>>(scores_dev, rows, S);
    // attn[b,:,h] = P @ V[b,:,h]   (M=4096, N=64, K=S) ; B read transposed
    launch_hmma<64, 0, false, false, GK_PV, true>(
        scores_dev, S, (long long)HHEADS * NTOK * S, (long long)NTOK * S,
        v_dev, CC, (long long)S * CC, HD,
        attn_dev, CC, (long long)NTOK * CC, HD,
        nullptr, NTOK, HD, S, 1.0f, BATCH * HHEADS, HHEADS);
    // t += attn @ Wo + bo
    launch_hmma_gemm<3>(attn_dev, CC, Wot, t_dev, CC, bo, NROWS, CC, CC);
}

// ---------------------------------------------------------------------------
// Entry
// ---------------------------------------------------------------------------
extern "C" void kernel_launch(void* const* d_in, const int* in_sizes, int n_in,
                              void* d_out, int out_size) {
    const float* x    = (const float*)d_in[0];
    const float* ctx  = (const float*)d_in[1];
    const float* geo  = (const float*)d_in[2];
    const float* g1 = (const float*)d_in[3],  *b1 = (const float*)d_in[4];
    const float* g2 = (const float*)d_in[5],  *b2 = (const float*)d_in[6];
    const float* g3 = (const float*)d_in[7],  *b3 = (const float*)d_in[8];
    const float* g4 = (const float*)d_in[9],  *b4 = (const float*)d_in[10];
    const float* cWq = (const float*)d_in[11], *cWk = (const float*)d_in[12];
    const float* cWv = (const float*)d_in[13], *cWo = (const float*)d_in[14];
    const float* cbo = (const float*)d_in[15];
    const float* gWq = (const float*)d_in[16], *gWk = (const float*)d_in[17];
    const float* gWv = (const float*)d_in[18], *gWo = (const float*)d_in[19];
    const float* gbo = (const float*)d_in[20];
    const float* W1  = (const float*)d_in[21], *bf1 = (const float*)d_in[22];
    const float* W2  = (const float*)d_in[23], *bf2 = (const float*)d_in[24];
    float* out = (float*)d_out;

    float *t_dev, *xn_dev, *q_dev, *attn_dev, *k_dev, *v_dev, *big_dev, *wt_dev;
    cudaGetSymbolAddress((void**)&t_dev,    g_t);
    cudaGetSymbolAddress((void**)&xn_dev,   g_xn);
    cudaGetSymbolAddress((void**)&q_dev,    g_q);
    cudaGetSymbolAddress((void**)&attn_dev, g_attn);
    cudaGetSymbolAddress((void**)&k_dev,    g_k);
    cudaGetSymbolAddress((void**)&v_dev,    g_v);
    cudaGetSymbolAddress((void**)&big_dev,  g_big);
    cudaGetSymbolAddress((void**)&wt_dev,   g_wt);

    // ---- pre-transpose weights (Bt = N x K layout for hmma)
    {
        dim3 blk(32, 8);
        dim3 gr1(CC / 32, CC / 32, 1);
        transpose_kernel<<<gr1, blk>>>(cWq, wt_dev + WT_CWQ, CC, CC);
        transpose_kernel<<<gr1, blk>>>(cWo, wt_dev + WT_CWO, CC, CC);
        transpose_kernel<<<gr1, blk>>>(gWq, wt_dev + WT_GWQ, CC, CC);
        transpose_kernel<<<gr1, blk>>>(gWo, wt_dev + WT_GWO, CC, CC);
        transpose_kernel<<<gr1, blk>>>(gWk, wt_dev + WT_GWK, GEO_D, CC);
        transpose_kernel<<<gr1, blk>>>(gWv, wt_dev + WT_GWV, GEO_D, CC);
        dim3 grc(CC / 32, CTX_D / 32, 1);    // 768x512 -> 512x768
        transpose_kernel<<<grc, blk>>>(cWk, wt_dev + WT_CWK, CTX_D, CC);
        transpose_kernel<<<grc, blk>>>(cWv, wt_dev + WT_CWV, CTX_D, CC);
        dim3 gr2(FFN_D / 32, CC / 32, 1);    // W1: 512x2048 -> 2048x512
        transpose_kernel<<<gr2, blk>>>(W1, wt_dev + WT_W1, CC, FFN_D);
        dim3 gr3(CC / 32, FFN_D / 32, 1);    // W2: 2048x512 -> 512x2048
        transpose_kernel<<<gr3, blk>>>(W2, wt_dev + WT_W2, FFN_D, CC);
    }

    // 1) transpose x (B,C,N) -> t0 (B,N,C)
    {
        dim3 grid(NTOK / 32, CC / 32, BATCH);
        transpose_kernel<<<grid, dim3(32, 8)>>>(x, xn_dev, CC, NTOK);
    }
    // 2) t = t0 + LN1(t0)
    ln_kernel<true><<<NROWS, 128>>>(xn_dev, g1, b1, t_dev);

    // 3) context cross-attention (S=77: GN scores, GM kv-proj, GK pv)
    cross_attention<CTX_S, CTX_D, true, true, true>(
        t_dev, xn_dev, q_dev, attn_dev, k_dev, v_dev, big_dev,
        g2, b2, ctx,
        wt_dev + WT_CWQ, wt_dev + WT_CWK, wt_dev + WT_CWV, wt_dev + WT_CWO, cbo);

    // 4) geometry cross-attention (S=256: all exact)
    cross_attention<GEO_S, GEO_D, false, false, false>(
        t_dev, xn_dev, q_dev, attn_dev, k_dev, v_dev, big_dev,
        g3, b3, geo,
        wt_dev + WT_GWQ, wt_dev + WT_GWK, wt_dev + WT_GWV, wt_dev + WT_GWO, gbo);

    // 5) FFN
    ln_kernel<false><<<NROWS, 128>>>(t_dev, g4, b4, xn_dev);
    launch_hmma_gemm<2>(xn_dev, CC, wt_dev + WT_W1, big_dev, FFN_D, bf1, NROWS, FFN_D, CC);
    launch_hmma_gemm<3>(big_dev, FFN_D, wt_dev + WT_W2, t_dev, CC, bf2, NROWS, CC, FFN_D);

    // 6) transpose back
    {
        dim3 grid(CC / 32, NTOK / 32, BATCH);
        transpose_kernel<<<grid, dim3(32, 8)>>>(t_dev, out, NTOK, CC);
    }
}

// round 6
// speedup vs baseline: 1.8829x; 1.3403x over previous
#include <cuda_runtime.h>
#include <cuda_bf16.h>
#include <cstdint>
#include <cstddef>

// ---------------------------------------------------------------------------
// Problem constants
// ---------------------------------------------------------------------------
#define BATCH   4
#define CC      512
#define NTOK    4096
#define NROWS   (BATCH*NTOK)
#define HHEADS  8
#define HD      64
#define CTX_S   77
#define CTX_SP  96        // padded S for ctx scores / P
#define CTX_D   768
#define GEO_S   256
#define GEO_D   512
#define FFN_D   2048
#define LN_EPS  1e-5f

static inline int ceil_div(int a, int b) { return (a + b - 1) / b; }

// ---------------------------------------------------------------------------
// Scratch (static device globals) — hi/lo packed bf16 pairs as uint32
// ---------------------------------------------------------------------------
__device__ __align__(16) uint32_t g_xnh[4194304], g_xnl[4194304];   // LN output
__device__ __align__(16) uint32_t g_qh [4194304], g_ql [4194304];   // Q
__device__ __align__(16) uint32_t g_kh [262144],  g_kl [262144];    // K proj
__device__ __align__(16) uint32_t g_vth[262144],  g_vtl[262144];    // V^T per head
__device__ __align__(16) uint32_t g_ah [4194304], g_al [4194304];   // attn ctxout
__device__ __align__(16) uint32_t g_ph [16777216],g_pl [16777216];  // P / FFN hidden
__device__ __align__(16) uint32_t g_cth[118272],  g_ctl[118272];    // ctx input
__device__ __align__(16) uint32_t g_geoh[262144], g_geol[262144];   // geo input
__device__ __align__(16) uint32_t g_wth[2228224], g_wtl[2228224];   // weights^T
__device__ float g_t  [(size_t)NROWS * CC];       // residual stream (fp32)
__device__ float g_v  [(size_t)BATCH * GEO_S * CC];
__device__ float g_big[(size_t)33554432];         // scores fp32 / t0 temp

// word offsets into g_wth/g_wtl
#define WT2_CWQ 0
#define WT2_CWO 131072
#define WT2_GWQ 262144
#define WT2_GWO 393216
#define WT2_W1  524288
#define WT2_W2  1048576
#define WT2_CWK 1572864
#define WT2_CWV 1769472
#define WT2_GWK 1966080
#define WT2_GWV 2097152

__device__ __forceinline__ float gelu_exact(float x) {
    return 0.5f * x * (1.0f + erff(x * 0.70710678118654752440f));
}

// ---------------------------------------------------------------------------
// helpers
// ---------------------------------------------------------------------------
__device__ __forceinline__ uint32_t smem_u32(const void* p) {
    uint32_t a;
    asm("{ .reg .u64 t; cvta.to.shared.u64 t, %1; cvt.u32.u64 %0, t; }" : "=r"(a) : "l"(p));
    return a;
}
__device__ __forceinline__ void cvt_pair(float x, float y, uint32_t& hi, uint32_t& lo) {
    __nv_bfloat16 hx = __float2bfloat16(x);
    __nv_bfloat16 hy = __float2bfloat16(y);
    __nv_bfloat16 lx = __float2bfloat16(x - __bfloat162float(hx));
    __nv_bfloat16 ly = __float2bfloat16(y - __bfloat162float(hy));
    hi = (uint32_t)__bfloat16_as_ushort(hx) | ((uint32_t)__bfloat16_as_ushort(hy) << 16);
    lo = (uint32_t)__bfloat16_as_ushort(lx) | ((uint32_t)__bfloat16_as_ushort(ly) << 16);
}
__device__ __forceinline__ void mma16816(float c[4], uint32_t a0, uint32_t a1, uint32_t a2,
                                         uint32_t a3, uint32_t b0, uint32_t b1) {
    asm volatile(
        "mma.sync.aligned.m16n8k16.row.col.f32.bf16.bf16.f32 "
        "{%0,%1,%2,%3}, {%4,%5,%6,%7}, {%8,%9}, {%0,%1,%2,%3};"
        : "+f"(c[0]), "+f"(c[1]), "+f"(c[2]), "+f"(c[3])
        : "r"(a0), "r"(a1), "r"(a2), "r"(a3), "r"(b0), "r"(b1));
}
// 16B-group XOR swizzle: word index within a 128x16-word tile
__device__ __forceinline__ int swz(int row, int kw) {
    return row * 16 + ((((kw >> 2) ^ ((row >> 1) & 3))) << 2) + (kw & 3);
}
__device__ __forceinline__ void cpa16(uint32_t dst, const uint32_t* src, bool ok) {
    int sz = ok ? 16 : 0;
    asm volatile("cp.async.cg.shared.global [%0], [%1], 16, %2;"
                 :: "r"(dst), "l"(src), "r"(sz) : "memory");
}

// ---------------------------------------------------------------------------
// Unified HMMA bf16x3 GEMM on pre-split hi/lo operands, cp.async 2-stage pipe.
//   C[M,N] = alpha * A[M,K] @ B[N,K]^T
// NT: 128 (warps 2x4) or 64 (warps 4x2). K multiple of 32.
// GN: B rows limited to N (+f32 epilogue col guard). GM: A rows limited to M.
// EPI: 0 none, 2 gelu(v+bias), 3 C += v + bias.  OUT: 0 fp32 C, 1 hi/lo C.
// Batched via grid.z (bb = z/H, hh = z%H); strides in words (A/B) / elems (C).
// ---------------------------------------------------------------------------
template <int NT, int EPI, int OUT, bool GN, bool GM>
__global__ void __launch_bounds__(256) hgemm_kernel(
    const uint32_t* __restrict__ Ah, const uint32_t* __restrict__ Al, int lda2,
    long long sAb2, long long sAh2,
    const uint32_t* __restrict__ Bh, const uint32_t* __restrict__ Bl, int ldb2,
    long long sBb2, long long sBh2,
    float* __restrict__ Cf, uint32_t* __restrict__ Ch, uint32_t* __restrict__ Cl,
    int ldc, long long sCb, long long sChh,
    const float* __restrict__ bias,
    int M, int N, int K, float alpha, int H)
{
    constexpr int MI = (NT == 128) ? 4 : 2;
    constexpr int AW = 2048;            // words per A array (128 rows x 16)
    constexpr int BW = NT * 16;
    constexpr int STG = 2 * AW + 2 * BW;
    constexpr int O_AH = 0, O_AL = AW, O_BH = 2 * AW, O_BL = 2 * AW + BW;
    extern __shared__ uint32_t sm[];

    {
        int z = blockIdx.z;
        int bb = z / H, hh = z - bb * H;
        long long ao = bb * sAb2 + hh * sAh2;
        long long bo = bb * sBb2 + hh * sBh2;
        Ah += ao; Al += ao; Bh += bo; Bl += bo;
        long long co = bb * sCb + hh * sChh;
        if (OUT == 0) Cf += co;
        else { Ch += (co >> 1); Cl += (co >> 1); }
    }

    const int tid  = threadIdx.x;
    const int wid  = tid >> 5, lane = tid & 31;
    const int g    = lane >> 2, t4 = lane & 3;
    const int wm   = (NT == 128) ? (wid >> 2) : (wid >> 1);
    const int wn   = (NT == 128) ? (wid & 3)  : (wid & 1);
    const int m0   = blockIdx.y * 128;
    const int n0   = blockIdx.x * NT;
    const uint32_t smb = smem_u32(sm);

    auto issue = [&](int ch, int stg) {
        const int k0w = ch * 16;
        const uint32_t base = smb + (uint32_t)stg * STG * 4;
        // ---- A: 128 rows, 4 groups of 16B per row per array
        {
            int r  = tid >> 1;
            int gr = m0 + r;
            bool ok = !GM || (gr < M);
            if (GM) gr = min(gr, M - 1);
            const uint32_t* sa = Ah + (size_t)gr * lda2 + k0w;
            const uint32_t* sl = Al + (size_t)gr * lda2 + k0w;
            #pragma unroll
            for (int e = 0; e < 2; ++e) {
                int grp = (tid & 1) * 2 + e;
                int d = r * 16 + (((grp ^ ((r >> 1) & 3))) << 2);
                cpa16(base + (O_AH + d) * 4, sa + grp * 4, ok);
                cpa16(base + (O_AL + d) * 4, sl + grp * 4, ok);
            }
        }
        // ---- B
        if (NT == 128) {
            int r  = tid >> 1;
            int gr = n0 + r;
            bool ok = !GN || (gr < N);
            if (GN) gr = min(gr, N - 1);
            const uint32_t* sb = Bh + (size_t)gr * ldb2 + k0w;
            const uint32_t* sl = Bl + (size_t)gr * ldb2 + k0w;
            #pragma unroll
            for (int e = 0; e < 2; ++e) {
                int grp = (tid & 1) * 2 + e;
                int d = r * 16 + (((grp ^ ((r >> 1) & 3))) << 2);
                cpa16(base + (O_BH + d) * 4, sb + grp * 4, ok);
                cpa16(base + (O_BL + d) * 4, sl + grp * 4, ok);
            }
        } else {
            int r = tid >> 2, grp = tid & 3;
            const uint32_t* sb = Bh + (size_t)(n0 + r) * ldb2 + k0w;
            const uint32_t* sl = Bl + (size_t)(n0 + r) * ldb2 + k0w;
            int d = r * 16 + (((grp ^ ((r >> 1) & 3))) << 2);
            cpa16(base + (O_BH + d) * 4, sb + grp * 4, true);
            cpa16(base + (O_BL + d) * 4, sl + grp * 4, true);
        }
        asm volatile("cp.async.commit_group;" ::: "memory");
    };

    float acc[MI][4][4] = {};
    const int nch = K >> 5;

    issue(0, 0);
    for (int ch = 0; ch < nch; ++ch) {
        if (ch + 1 < nch) {
            issue(ch + 1, (ch + 1) & 1);
            asm volatile("cp.async.wait_group 1;" ::: "memory");
        } else {
            asm volatile("cp.async.wait_group 0;" ::: "memory");
        }
        __syncthreads();

        const uint32_t* st = sm + (ch & 1) * STG;
        #pragma unroll
        for (int pass = 0; pass < 3; ++pass) {
            const uint32_t* pa = st + (pass == 2 ? O_AL : O_AH);
            const uint32_t* pb = st + (pass == 1 ? O_BL : O_BH);
            #pragma unroll
            for (int ks = 0; ks < 2; ++ks) {
                uint32_t afr[MI][4];
                #pragma unroll
                for (int mi = 0; mi < MI; ++mi) {
                    int r0 = wm * (MI * 16) + mi * 16 + g;
                    int r1 = r0 + 8;
                    int kw = ks * 8 + t4;
                    afr[mi][0] = pa[swz(r0, kw)];
                    afr[mi][1] = pa[swz(r1, kw)];
                    afr[mi][2] = pa[swz(r0, kw + 4)];
                    afr[mi][3] = pa[swz(r1, kw + 4)];
                }
                uint32_t bfr[4][2];
                #pragma unroll
                for (int ni = 0; ni < 4; ++ni) {
                    int nr = wn * 32 + ni * 8 + g;
                    int kw = ks * 8 + t4;
                    bfr[ni][0] = pb[swz(nr, kw)];
                    bfr[ni][1] = pb[swz(nr, kw + 4)];
                }
                #pragma unroll
                for (int mi = 0; mi < MI; ++mi)
                    #pragma unroll
                    for (int ni = 0; ni < 4; ++ni)
                        mma16816(acc[mi][ni], afr[mi][0], afr[mi][1], afr[mi][2],
                                 afr[mi][3], bfr[ni][0], bfr[ni][1]);
            }
        }
        __syncthreads();
    }

    // ---------------- epilogue ----------------
    const int ldc2 = ldc >> 1;
    #pragma unroll
    for (int mi = 0; mi < MI; ++mi) {
        #pragma unroll
        for (int ni = 0; ni < 4; ++ni) {
            int row0 = m0 + wm * (MI * 16) + mi * 16 + g;
            int col  = n0 + wn * 32 + ni * 8 + 2 * t4;
            float* c = acc[mi][ni];
            #pragma unroll
            for (int h = 0; h < 2; ++h) {
                int row = row0 + h * 8;
                if (GM && row >= M) continue;
                float v0 = c[2 * h] * alpha, v1 = c[2 * h + 1] * alpha;
                if (EPI == 2) {
                    v0 = gelu_exact(v0 + bias[col]);
                    v1 = gelu_exact(v1 + bias[col + 1]);
                }
                if (OUT == 0) {
                    size_t off = (size_t)row * ldc + col;
                    if (EPI == 3) {
                        v0 += bias[col]     + Cf[off];
                        v1 += bias[col + 1] + Cf[off + 1];
                    }
                    if (GN) {
                        if (col < N)     Cf[off]     = v0;
                        if (col + 1 < N) Cf[off + 1] = v1;
                    } else {
                        float2 o; o.x = v0; o.y = v1;
                        *reinterpret_cast<float2*>(&Cf[off]) = o;
                    }
                } else {
                    uint32_t wh, wl;
                    cvt_pair(v0, v1, wh, wl);
                    size_t o = (size_t)row * ldc2 + (col >> 1);
                    Ch[o] = wh; Cl[o] = wl;
                }
            }
        }
    }
}

template <int NT, int EPI, int OUT, bool GN, bool GM>
static void L(const uint32_t* Ah, const uint32_t* Al, int lda2,
              long long sAb2, long long sAh2,
              const uint32_t* Bh, const uint32_t* Bl, int ldb2,
              long long sBb2, long long sBh2,
              float* Cf, uint32_t* Ch, uint32_t* Cl, int ldc,
              long long sCb, long long sChh, const float* bias,
              int M, int N, int K, float alpha, int batches, int H) {
    constexpr int STG = 2 * 2048 + 2 * NT * 16;
    const int smem = 2 * STG * 4;
    cudaFuncSetAttribute(hgemm_kernel<NT, EPI, OUT, GN, GM>,
                         cudaFuncAttributeMaxDynamicSharedMemorySize, smem);
    dim3 grid(ceil_div(N, NT), ceil_div(M, 128), batches);
    hgemm_kernel<NT, EPI, OUT, GN, GM><<<grid, 256, smem>>>(
        Ah, Al, lda2, sAb2, sAh2, Bh, Bl, ldb2, sBb2, sBh2,
        Cf, Ch, Cl, ldc, sCb, sChh, bias, M, N, K, alpha, H);
}

// ---------------------------------------------------------------------------
// fp32 transpose (x in/out)
// ---------------------------------------------------------------------------
__global__ void transpose_kernel(const float* __restrict__ in, float* __restrict__ out,
                                 int R, int Ccol) {
    __shared__ float tile[32][33];
    int b = blockIdx.z;
    const float* ip = in  + (size_t)b * R * Ccol;
    float*       op = out + (size_t)b * R * Ccol;
    int j0 = blockIdx.x * 32, i0 = blockIdx.y * 32;
    int tx = threadIdx.x, ty = threadIdx.y;
    #pragma unroll
    for (int k = 0; k < 32; k += 8) tile[ty + k][tx] = ip[(size_t)(i0 + ty + k) * Ccol + j0 + tx];
    __syncthreads();
    #pragma unroll
    for (int k = 0; k < 32; k += 8) op[(size_t)(j0 + ty + k) * R + i0 + tx] = tile[tx][ty + k];
}

// transpose weights fp32 (R x Ccol) -> hi/lo (Ccol x R) packed pairs
__global__ void transpose_hl(const float* __restrict__ in,
                             uint32_t* __restrict__ oh, uint32_t* __restrict__ ol,
                             int R, int Ccol) {
    __shared__ float tile[32][33];
    int j0 = blockIdx.x * 32, i0 = blockIdx.y * 32;
    int tx = threadIdx.x, ty = threadIdx.y;
    #pragma unroll
    for (int k = 0; k < 32; k += 8) tile[ty + k][tx] = in[(size_t)(i0 + ty + k) * Ccol + j0 + tx];
    __syncthreads();
    int flat = ty * 32 + tx;
    int R2 = R >> 1;
    #pragma unroll
    for (int rep = 0; rep < 2; ++rep) {
        int idx = flat + rep * 256;
        int i2 = idx & 15, j = idx >> 4;
        uint32_t h, l;
        cvt_pair(tile[2 * i2][j], tile[2 * i2 + 1][j], h, l);
        size_t o = (size_t)(j0 + j) * R2 + (i0 >> 1) + i2;
        oh[o] = h; ol[o] = l;
    }
}

// elementwise fp32 -> hi/lo pairs
__global__ void cvt_split(const float* __restrict__ in, uint32_t* __restrict__ oh,
                          uint32_t* __restrict__ ol, int nw) {
    int w = blockIdx.x * 256 + threadIdx.x;
    if (w >= nw) return;
    float2 f = reinterpret_cast<const float2*>(in)[w];
    uint32_t h, l; cvt_pair(f.x, f.y, h, l);
    oh[w] = h; ol[w] = l;
}

// ---------------------------------------------------------------------------
// LayerNorm: ADD variant (fp32 out = in + LN(in)); HL variant (hi/lo out)
// ---------------------------------------------------------------------------
__device__ __forceinline__ void ln_core(const float4& v, float& s, float& ss) {
    s  = v.x + v.y + v.z + v.w;
    ss = v.x*v.x + v.y*v.y + v.z*v.z + v.w*v.w;
}
template <bool HL>
__global__ void ln_kernel(const float* __restrict__ in,
                          const float* __restrict__ gamma,
                          const float* __restrict__ beta,
                          float* __restrict__ outf,
                          uint32_t* __restrict__ oh, uint32_t* __restrict__ ol) {
    int row = blockIdx.x;
    const float4* rin = reinterpret_cast<const float4*>(in + (size_t)row * CC);
    int t = threadIdx.x;
    float4 v = rin[t];
    float s, ss; ln_core(v, s, ss);
    #pragma unroll
    for (int o = 16; o > 0; o >>= 1) {
        s  += __shfl_xor_sync(0xffffffffu, s,  o);
        ss += __shfl_xor_sync(0xffffffffu, ss, o);
    }
    __shared__ float shs[4], shss[4];
    int warp = t >> 5, lane = t & 31;
    if (lane == 0) { shs[warp] = s; shss[warp] = ss; }
    __syncthreads();
    s  = shs[0] + shs[1] + shs[2] + shs[3];
    ss = shss[0] + shss[1] + shss[2] + shss[3];
    float mu  = s * (1.0f / CC);
    float var = ss * (1.0f / CC) - mu * mu;
    float rs  = rsqrtf(var + LN_EPS);
    float4 g4 = reinterpret_cast<const float4*>(gamma)[t];
    float4 b4 = reinterpret_cast<const float4*>(beta)[t];
    float4 o4;
    o4.x = (v.x - mu) * rs * g4.x + b4.x;
    o4.y = (v.y - mu) * rs * g4.y + b4.y;
    o4.z = (v.z - mu) * rs * g4.z + b4.z;
    o4.w = (v.w - mu) * rs * g4.w + b4.w;
    if (!HL) {
        o4.x += v.x; o4.y += v.y; o4.z += v.z; o4.w += v.w;
        reinterpret_cast<float4*>(outf + (size_t)row * CC)[t] = o4;
    } else {
        uint32_t h0, l0, h1, l1;
        cvt_pair(o4.x, o4.y, h0, l0);
        cvt_pair(o4.z, o4.w, h1, l1);
        size_t w = (size_t)row * (CC / 2) + t * 2;
        oh[w] = h0; oh[w + 1] = h1;
        ol[w] = l0; ol[w + 1] = l1;
    }
}

// ---------------------------------------------------------------------------
// Softmax: fp32 scores (ld=SP) -> P hi/lo (padded zeros to SP)
// ---------------------------------------------------------------------------
template <int S, int SP>
__global__ void softmax_hl(const float* __restrict__ sc,
                           uint32_t* __restrict__ ph, uint32_t* __restrict__ pl,
                           long long rows) {
    long long row = (long long)blockIdx.x * 4 + (threadIdx.x >> 5);
    if (row >= rows) return;
    const float* p = sc + row * SP;
    int lane = threadIdx.x & 31;
    float mx = -1e30f;
    for (int j = lane; j < S; j += 32) mx = fmaxf(mx, p[j]);
    #pragma unroll
    for (int o = 16; o > 0; o >>= 1) mx = fmaxf(mx, __shfl_xor_sync(0xffffffffu, mx, o));
    float sum = 0.0f;
    for (int j = lane; j < S; j += 32) sum += __expf(p[j] - mx);
    #pragma unroll
    for (int o = 16; o > 0; o >>= 1) sum += __shfl_xor_sync(0xffffffffu, sum, o);
    float inv = 1.0f / sum;
    uint32_t* oh = ph + row * (SP / 2);
    uint32_t* ol = pl + row * (SP / 2);
    for (int j2 = lane; j2 < SP / 2; j2 += 32) {
        int j = 2 * j2;
        float a = (j     < S) ? __expf(p[j]     - mx) * inv : 0.0f;
        float b = (j + 1 < S) ? __expf(p[j + 1] - mx) * inv : 0.0f;
        uint32_t h, l; cvt_pair(a, b, h, l);
        oh[j2] = h; ol[j2] = l;
    }
}

// ---------------------------------------------------------------------------
// V (B*S x CC fp32) -> per-head V^T hi/lo (32 x HD x SP/2 words), zero-padded
// ---------------------------------------------------------------------------
template <int S, int SP>
__global__ void vt_build(const float* __restrict__ v,
                         uint32_t* __restrict__ vth, uint32_t* __restrict__ vtl) {
    int bh = blockIdx.x;
    int b = bh >> 3, h = bh & 7;
    const float* vb = v + (size_t)b * S * CC + h * 64;
    uint32_t* oh = vth + (size_t)bh * HD * (SP / 2);
    uint32_t* ol = vtl + (size_t)bh * HD * (SP / 2);
    for (int idx = threadIdx.x; idx < HD * (SP / 2); idx += blockDim.x) {
        int d = idx / (SP / 2), sw = idx % (SP / 2);
        int s = 2 * sw;
        float x = (s     < S) ? vb[(size_t)s       * CC + d] : 0.0f;
        float y = (s + 1 < S) ? vb[(size_t)(s + 1) * CC + d] : 0.0f;
        uint32_t hh, ll; cvt_pair(x, y, hh, ll);
        oh[idx] = hh; ol[idx] = ll;
    }
}

// ---------------------------------------------------------------------------
// Entry
// ---------------------------------------------------------------------------
extern "C" void kernel_launch(void* const* d_in, const int* in_sizes, int n_in,
                              void* d_out, int out_size) {
    const float* x    = (const float*)d_in[0];
    const float* ctx  = (const float*)d_in[1];
    const float* geo  = (const float*)d_in[2];
    const float* g1 = (const float*)d_in[3],  *b1 = (const float*)d_in[4];
    const float* g2 = (const float*)d_in[5],  *b2 = (const float*)d_in[6];
    const float* g3 = (const float*)d_in[7],  *b3 = (const float*)d_in[8];
    const float* g4 = (const float*)d_in[9],  *b4 = (const float*)d_in[10];
    const float* cWq = (const float*)d_in[11], *cWk = (const float*)d_in[12];
    const float* cWv = (const float*)d_in[13], *cWo = (const float*)d_in[14];
    const float* cbo = (const float*)d_in[15];
    const float* gWq = (const float*)d_in[16], *gWk = (const float*)d_in[17];
    const float* gWv = (const float*)d_in[18], *gWo = (const float*)d_in[19];
    const float* gbo = (const float*)d_in[20];
    const float* W1  = (const float*)d_in[21], *bf1 = (const float*)d_in[22];
    const float* W2  = (const float*)d_in[23], *bf2 = (const float*)d_in[24];
    float* out = (float*)d_out;

    float *t_d, *v_d, *big_d;
    uint32_t *xnh, *xnl, *qh, *ql, *kh, *kl, *vth, *vtl, *ah, *al, *ph, *pl;
    uint32_t *cth, *ctl, *geoh, *geol, *wth, *wtl;
    cudaGetSymbolAddress((void**)&t_d,  g_t);
    cudaGetSymbolAddress((void**)&v_d,  g_v);
    cudaGetSymbolAddress((void**)&big_d, g_big);
    cudaGetSymbolAddress((void**)&xnh, g_xnh);  cudaGetSymbolAddress((void**)&xnl, g_xnl);
    cudaGetSymbolAddress((void**)&qh,  g_qh);   cudaGetSymbolAddress((void**)&ql,  g_ql);
    cudaGetSymbolAddress((void**)&kh,  g_kh);   cudaGetSymbolAddress((void**)&kl,  g_kl);
    cudaGetSymbolAddress((void**)&vth, g_vth);  cudaGetSymbolAddress((void**)&vtl, g_vtl);
    cudaGetSymbolAddress((void**)&ah,  g_ah);   cudaGetSymbolAddress((void**)&al,  g_al);
    cudaGetSymbolAddress((void**)&ph,  g_ph);   cudaGetSymbolAddress((void**)&pl,  g_pl);
    cudaGetSymbolAddress((void**)&cth, g_cth);  cudaGetSymbolAddress((void**)&ctl, g_ctl);
    cudaGetSymbolAddress((void**)&geoh, g_geoh); cudaGetSymbolAddress((void**)&geol, g_geol);
    cudaGetSymbolAddress((void**)&wth, g_wth);  cudaGetSymbolAddress((void**)&wtl, g_wtl);

    // ---- weight transpose+split, input split
    {
        dim3 blk(32, 8);
        dim3 gr1(CC / 32, CC / 32);
        transpose_hl<<<gr1, blk>>>(cWq, wth + WT2_CWQ, wtl + WT2_CWQ, CC, CC);
        transpose_hl<<<gr1, blk>>>(cWo, wth + WT2_CWO, wtl + WT2_CWO, CC, CC);
        transpose_hl<<<gr1, blk>>>(gWq, wth + WT2_GWQ, wtl + WT2_GWQ, CC, CC);
        transpose_hl<<<gr1, blk>>>(gWo, wth + WT2_GWO, wtl + WT2_GWO, CC, CC);
        transpose_hl<<<gr1, blk>>>(gWk, wth + WT2_GWK, wtl + WT2_GWK, GEO_D, CC);
        transpose_hl<<<gr1, blk>>>(gWv, wth + WT2_GWV, wtl + WT2_GWV, GEO_D, CC);
        dim3 grc(CC / 32, CTX_D / 32);
        transpose_hl<<<grc, blk>>>(cWk, wth + WT2_CWK, wtl + WT2_CWK, CTX_D, CC);
        transpose_hl<<<grc, blk>>>(cWv, wth + WT2_CWV, wtl + WT2_CWV, CTX_D, CC);
        dim3 gr2(FFN_D / 32, CC / 32);
        transpose_hl<<<gr2, blk>>>(W1, wth + WT2_W1, wtl + WT2_W1, CC, FFN_D);
        dim3 gr3(CC / 32, FFN_D / 32);
        transpose_hl<<<gr3, blk>>>(W2, wth + WT2_W2, wtl + WT2_W2, FFN_D, CC);
        int nwc = BATCH * CTX_S * CTX_D / 2;
        cvt_split<<<ceil_div(nwc, 256), 256>>>(ctx, cth, ctl, nwc);
        int nwg = BATCH * GEO_S * GEO_D / 2;
        cvt_split<<<ceil_div(nwg, 256), 256>>>(geo, geoh, geol, nwg);
    }

    // 1) transpose x (B,C,N) -> t0 (B,N,C) in big; t = t0 + LN1(t0)
    {
        dim3 grid(NTOK / 32, CC / 32, BATCH);
        transpose_kernel<<<grid, dim3(32, 8)>>>(x, big_d, CC, NTOK);
    }
    ln_kernel<false><<<NROWS, 128>>>(big_d, g1, b1, t_d, nullptr, nullptr);

    long long rows32 = (long long)BATCH * HHEADS * NTOK;

    // ================= context cross-attention (S=77) =================
    ln_kernel<true><<<NROWS, 128>>>(t_d, g2, b2, nullptr, xnh, xnl);
    L<128, 0, 1, false, false>(xnh, xnl, 256, 0, 0,
        wth + WT2_CWQ, wtl + WT2_CWQ, 256, 0, 0,
        nullptr, qh, ql, CC, 0, 0, nullptr, NROWS, CC, CC, 1.0f, 1, 1);
    L<128, 0, 1, false, true>(cth, ctl, 384, 0, 0,
        wth + WT2_CWK, wtl + WT2_CWK, 384, 0, 0,
        nullptr, kh, kl, CC, 0, 0, nullptr, BATCH * CTX_S, CC, CTX_D, 1.0f, 1, 1);
    L<128, 0, 0, false, true>(cth, ctl, 384, 0, 0,
        wth + WT2_CWV, wtl + WT2_CWV, 384, 0, 0,
        v_d, nullptr, nullptr, CC, 0, 0, nullptr, BATCH * CTX_S, CC, CTX_D, 1.0f, 1, 1);
    vt_build<CTX_S, CTX_SP><<<32, 256>>>(v_d, vth, vtl);
    L<128, 0, 0, true, false>(qh, ql, 256, (long long)NTOK * 256, 32,
        kh, kl, 256, (long long)CTX_S * 256, 32,
        big_d, nullptr, nullptr, CTX_SP,
        (long long)HHEADS * NTOK * CTX_SP, (long long)NTOK * CTX_SP,
        nullptr, NTOK, CTX_S, HD, 0.125f, BATCH * HHEADS, HHEADS);
    softmax_hl<CTX_S, CTX_SP><<<(unsigned)(rows32 / 4), 128>>>(big_d, ph, pl, rows32);
    L<64, 0, 1, false, false>(ph, pl, CTX_SP / 2,
        (long long)HHEADS * NTOK * (CTX_SP / 2), (long long)NTOK * (CTX_SP / 2),
        vth, vtl, CTX_SP / 2,
        (long long)HHEADS * HD * (CTX_SP / 2), (long long)HD * (CTX_SP / 2),
        nullptr, ah, al, CC, (long long)NTOK * CC, HD,
        nullptr, NTOK, HD, CTX_SP, 1.0f, BATCH * HHEADS, HHEADS);
    L<128, 3, 0, false, false>(ah, al, 256, 0, 0,
        wth + WT2_CWO, wtl + WT2_CWO, 256, 0, 0,
        t_d, nullptr, nullptr, CC, 0, 0, cbo, NROWS, CC, CC, 1.0f, 1, 1);

    // ================= geometry cross-attention (S=256) =================
    ln_kernel<true><<<NROWS, 128>>>(t_d, g3, b3, nullptr, xnh, xnl);
    L<128, 0, 1, false, false>(xnh, xnl, 256, 0, 0,
        wth + WT2_GWQ, wtl + WT2_GWQ, 256, 0, 0,
        nullptr, qh, ql, CC, 0, 0, nullptr, NROWS, CC, CC, 1.0f, 1, 1);
    L<128, 0, 1, false, false>(geoh, geol, 256, 0, 0,
        wth + WT2_GWK, wtl + WT2_GWK, 256, 0, 0,
        nullptr, kh, kl, CC, 0, 0, nullptr, BATCH * GEO_S, CC, GEO_D, 1.0f, 1, 1);
    L<128, 0, 0, false, false>(geoh, geol, 256, 0, 0,
        wth + WT2_GWV, wtl + WT2_GWV, 256, 0, 0,
        v_d, nullptr, nullptr, CC, 0, 0, nullptr, BATCH * GEO_S, CC, GEO_D, 1.0f, 1, 1);
    vt_build<GEO_S, GEO_S><<<32, 256>>>(v_d, vth, vtl);
    L<128, 0, 0, false, false>(qh, ql, 256, (long long)NTOK * 256, 32,
        kh, kl, 256, (long long)GEO_S * 256, 32,
        big_d, nullptr, nullptr, GEO_S,
        (long long)HHEADS * NTOK * GEO_S, (long long)NTOK * GEO_S,
        nullptr, NTOK, GEO_S, HD, 0.125f, BATCH * HHEADS, HHEADS);
    softmax_hl<GEO_S, GEO_S><<<(unsigned)(rows32 / 4), 128>>>(big_d, ph, pl, rows32);
    L<64, 0, 1, false, false>(ph, pl, GEO_S / 2,
        (long long)HHEADS * NTOK * (GEO_S / 2), (long long)NTOK * (GEO_S / 2),
        vth, vtl, GEO_S / 2,
        (long long)HHEADS * HD * (GEO_S / 2), (long long)HD * (GEO_S / 2),
        nullptr, ah, al, CC, (long long)NTOK * CC, HD,
        nullptr, NTOK, HD, GEO_S, 1.0f, BATCH * HHEADS, HHEADS);
    L<128, 3, 0, false, false>(ah, al, 256, 0, 0,
        wth + WT2_GWO, wtl + WT2_GWO, 256, 0, 0,
        t_d, nullptr, nullptr, CC, 0, 0, gbo, NROWS, CC, CC, 1.0f, 1, 1);

    // ================= FFN =================
    ln_kernel<true><<<NROWS, 128>>>(t_d, g4, b4, nullptr, xnh, xnl);
    L<128, 2, 1, false, false>(xnh, xnl, 256, 0, 0,
        wth + WT2_W1, wtl + WT2_W1, 256, 0, 0,
        nullptr, ph, pl, FFN_D, 0, 0, bf1, NROWS, FFN_D, CC, 1.0f, 1, 1);
    L<128, 3, 0, false, false>(ph, pl, 1024, 0, 0,
        wth + WT2_W2, wtl + WT2_W2, 1024, 0, 0,
        t_d, nullptr, nullptr, CC, 0, 0, bf2, NROWS, CC, FFN_D, 1.0f, 1, 1);

    // ---- transpose back
    {
        dim3 grid(CC / 32, NTOK / 32, BATCH);
        transpose_kernel<<<grid, dim3(32, 8)>>>(t_d, out, NTOK, CC);
    }
}

// round 7
// speedup vs baseline: 2.0718x; 1.1004x over previous
#include <cuda_runtime.h>
#include <cuda_bf16.h>
#include <cstdint>
#include <cstddef>

// ---------------------------------------------------------------------------
// Problem constants
// ---------------------------------------------------------------------------
#define BATCH   4
#define CC      512
#define NTOK    4096
#define NROWS   (BATCH*NTOK)
#define HHEADS  8
#define HD      64
#define CTX_S   77
#define CTX_SP  96        // padded S for ctx scores / P
#define CTX_D   768
#define GEO_S   256
#define GEO_D   512
#define FFN_D   2048
#define LN_EPS  1e-5f

static inline int ceil_div(int a, int b) { return (a + b - 1) / b; }

// ---------------------------------------------------------------------------
// Scratch (static device globals) — hi/lo packed bf16 pairs as uint32
// ---------------------------------------------------------------------------
__device__ __align__(16) uint32_t g_xnh[4194304], g_xnl[4194304];   // LN output
__device__ __align__(16) uint32_t g_qh [4194304], g_ql [4194304];   // Q
__device__ __align__(16) uint32_t g_kh [262144],  g_kl [262144];    // K proj
__device__ __align__(16) uint32_t g_vth[262144],  g_vtl[262144];    // V^T per head
__device__ __align__(16) uint32_t g_ah [4194304], g_al [4194304];   // attn ctxout
__device__ __align__(16) uint32_t g_ph [16777216],g_pl [16777216];  // P / FFN hidden
__device__ __align__(16) uint32_t g_cth[118272],  g_ctl[118272];    // ctx input
__device__ __align__(16) uint32_t g_geoh[262144], g_geol[262144];   // geo input
__device__ __align__(16) uint32_t g_wth[2228224], g_wtl[2228224];   // weights^T
__device__ float g_t  [(size_t)NROWS * CC];       // residual stream (fp32)
__device__ float g_v  [(size_t)BATCH * GEO_S * CC];
__device__ float g_big[(size_t)33554432];         // scores fp32 / t0 temp

// word offsets into g_wth/g_wtl
#define WT2_CWQ 0
#define WT2_CWO 131072
#define WT2_GWQ 262144
#define WT2_GWO 393216
#define WT2_W1  524288
#define WT2_W2  1048576
#define WT2_CWK 1572864
#define WT2_CWV 1769472
#define WT2_GWK 1966080
#define WT2_GWV 2097152

__device__ __forceinline__ float gelu_exact(float x) {
    return 0.5f * x * (1.0f + erff(x * 0.70710678118654752440f));
}

// ---------------------------------------------------------------------------
// helpers
// ---------------------------------------------------------------------------
__device__ __forceinline__ uint32_t smem_u32(const void* p) {
    uint32_t a;
    asm("{ .reg .u64 t; cvta.to.shared.u64 t, %1; cvt.u32.u64 %0, t; }" : "=r"(a) : "l"(p));
    return a;
}
__device__ __forceinline__ void cvt_pair(float x, float y, uint32_t& hi, uint32_t& lo) {
    __nv_bfloat16 hx = __float2bfloat16(x);
    __nv_bfloat16 hy = __float2bfloat16(y);
    __nv_bfloat16 lx = __float2bfloat16(x - __bfloat162float(hx));
    __nv_bfloat16 ly = __float2bfloat16(y - __bfloat162float(hy));
    hi = (uint32_t)__bfloat16_as_ushort(hx) | ((uint32_t)__bfloat16_as_ushort(hy) << 16);
    lo = (uint32_t)__bfloat16_as_ushort(lx) | ((uint32_t)__bfloat16_as_ushort(ly) << 16);
}
__device__ __forceinline__ void mma16816(float c[4], uint32_t a0, uint32_t a1, uint32_t a2,
                                         uint32_t a3, uint32_t b0, uint32_t b1) {
    asm volatile(
        "mma.sync.aligned.m16n8k16.row.col.f32.bf16.bf16.f32 "
        "{%0,%1,%2,%3}, {%4,%5,%6,%7}, {%8,%9}, {%0,%1,%2,%3};"
        : "+f"(c[0]), "+f"(c[1]), "+f"(c[2]), "+f"(c[3])
        : "r"(a0), "r"(a1), "r"(a2), "r"(a3), "r"(b0), "r"(b1));
}
__device__ __forceinline__ void ldsm4(uint32_t& r0, uint32_t& r1, uint32_t& r2, uint32_t& r3,
                                      uint32_t addr) {
    asm volatile("ldmatrix.sync.aligned.m8n8.x4.shared.b16 {%0,%1,%2,%3}, [%4];"
                 : "=r"(r0), "=r"(r1), "=r"(r2), "=r"(r3) : "r"(addr));
}
// 16B-group XOR swizzle: word index within a 128x16-word tile
__device__ __forceinline__ int swz(int row, int kw) {
    return row * 16 + ((((kw >> 2) ^ ((row >> 1) & 3))) << 2) + (kw & 3);
}
// swizzled word offset of the 16B group kg (0..3) in row
__device__ __forceinline__ int swzg(int row, int kg) {
    return row * 16 + (((kg ^ ((row >> 1) & 3))) << 2);
}
__device__ __forceinline__ void cpa16(uint32_t dst, const uint32_t* src, bool ok) {
    int sz = ok ? 16 : 0;
    asm volatile("cp.async.cg.shared.global [%0], [%1], 16, %2;"
                 :: "r"(dst), "l"(src), "r"(sz) : "memory");
}

// ---------------------------------------------------------------------------
// Unified HMMA bf16x3 GEMM on pre-split hi/lo operands.
// 3-stage cp.async pipeline, ldmatrix fragment loads, register pass-reuse.
//   C[M,N] = alpha * A[M,K] @ B[N,K]^T
// NT: 128 (warps 2x4) or 64 (warps 4x2). K multiple of 32.
// GN: B rows limited to N (+f32 epilogue col guard). GM: A rows limited to M.
// EPI: 0 none, 2 gelu(v+bias), 3 C += v + bias.  OUT: 0 fp32 C, 1 hi/lo C.
// Batched via grid.z (bb = z/H, hh = z%H); strides in words (A/B) / elems (C).
// ---------------------------------------------------------------------------
template <int NT, int EPI, int OUT, bool GN, bool GM>
__global__ void __launch_bounds__(256) hgemm_kernel(
    const uint32_t* __restrict__ Ah, const uint32_t* __restrict__ Al, int lda2,
    long long sAb2, long long sAh2,
    const uint32_t* __restrict__ Bh, const uint32_t* __restrict__ Bl, int ldb2,
    long long sBb2, long long sBh2,
    float* __restrict__ Cf, uint32_t* __restrict__ Ch, uint32_t* __restrict__ Cl,
    int ldc, long long sCb, long long sChh,
    const float* __restrict__ bias,
    int M, int N, int K, float alpha, int H)
{
    constexpr int MI = (NT == 128) ? 4 : 2;
    constexpr int AW = 2048;            // words per A array (128 rows x 16)
    constexpr int BW = NT * 16;
    constexpr int STG = 2 * AW + 2 * BW;
    constexpr int O_AH = 0, O_AL = AW, O_BH = 2 * AW, O_BL = 2 * AW + BW;
    extern __shared__ uint32_t sm[];

    {
        int z = blockIdx.z;
        int bb = z / H, hh = z - bb * H;
        long long ao = bb * sAb2 + hh * sAh2;
        long long bo = bb * sBb2 + hh * sBh2;
        Ah += ao; Al += ao; Bh += bo; Bl += bo;
        long long co = bb * sCb + hh * sChh;
        if (OUT == 0) Cf += co;
        else { Ch += (co >> 1); Cl += (co >> 1); }
    }

    const int tid  = threadIdx.x;
    const int wid  = tid >> 5, lane = tid & 31;
    const int g    = lane >> 2, t4 = lane & 3;
    const int wm   = (NT == 128) ? (wid >> 2) : (wid >> 1);
    const int wn   = (NT == 128) ? (wid & 3)  : (wid & 1);
    const int m0   = blockIdx.y * 128;
    const int n0   = blockIdx.x * NT;
    const uint32_t smb = smem_u32(sm);

    auto issue = [&](int ch, int stg) {
        const int k0w = ch * 16;
        const uint32_t base = smb + (uint32_t)stg * STG * 4;
        {
            int r  = tid >> 1;
            int gr = m0 + r;
            bool ok = !GM || (gr < M);
            if (GM) gr = min(gr, M - 1);
            const uint32_t* sa = Ah + (size_t)gr * lda2 + k0w;
            const uint32_t* sl = Al + (size_t)gr * lda2 + k0w;
            #pragma unroll
            for (int e = 0; e < 2; ++e) {
                int grp = (tid & 1) * 2 + e;
                int d = swzg(r, grp);
                cpa16(base + (O_AH + d) * 4, sa + grp * 4, ok);
                cpa16(base + (O_AL + d) * 4, sl + grp * 4, ok);
            }
        }
        if (NT == 128) {
            int r  = tid >> 1;
            int gr = n0 + r;
            bool ok = !GN || (gr < N);
            if (GN) gr = min(gr, N - 1);
            const uint32_t* sb = Bh + (size_t)gr * ldb2 + k0w;
            const uint32_t* sl = Bl + (size_t)gr * ldb2 + k0w;
            #pragma unroll
            for (int e = 0; e < 2; ++e) {
                int grp = (tid & 1) * 2 + e;
                int d = swzg(r, grp);
                cpa16(base + (O_BH + d) * 4, sb + grp * 4, ok);
                cpa16(base + (O_BL + d) * 4, sl + grp * 4, ok);
            }
        } else {
            int r = tid >> 2, grp = tid & 3;
            const uint32_t* sb = Bh + (size_t)(n0 + r) * ldb2 + k0w;
            const uint32_t* sl = Bl + (size_t)(n0 + r) * ldb2 + k0w;
            int d = swzg(r, grp);
            cpa16(base + (O_BH + d) * 4, sb + grp * 4, true);
            cpa16(base + (O_BL + d) * 4, sl + grp * 4, true);
        }
        asm volatile("cp.async.commit_group;" ::: "memory");
    };

    float acc[MI][4][4] = {};
    const int nch = K >> 5;

    issue(0, 0);
    if (nch > 1) issue(1, 1);

    // per-lane ldmatrix constants
    const int a_rin = ((lane >> 3) & 1) * 8 + (lane & 7);   // row-in-16 offset
    const int a_kg  = lane >> 4;                            // +0/+1 k-group
    const int b_blk = lane >> 4;                            // n-block offset (0/1)
    const int b_kg  = (lane >> 3) & 1;                      // +0/+1 k-group
    const int b_rin = lane & 7;

    for (int ch = 0; ch < nch; ++ch) {
        if (ch + 2 < nch) {
            issue(ch + 2, (ch + 2) % 3);
            asm volatile("cp.async.wait_group 2;" ::: "memory");
        } else if (ch + 1 < nch) {
            asm volatile("cp.async.wait_group 1;" ::: "memory");
        } else {
            asm volatile("cp.async.wait_group 0;" ::: "memory");
        }
        __syncthreads();

        const uint32_t stb = smb + (uint32_t)(ch % 3) * STG * 4;
        #pragma unroll
        for (int ks = 0; ks < 2; ++ks) {
            uint32_t ahf[MI][4], alf[MI][4], bhf[4][2], blf[4][2];
            #pragma unroll
            for (int mi = 0; mi < MI; ++mi) {
                int rr = wm * (MI * 16) + mi * 16 + a_rin;
                int kg = ks * 2 + a_kg;
                uint32_t off = (uint32_t)swzg(rr, kg) * 4;
                ldsm4(ahf[mi][0], ahf[mi][1], ahf[mi][2], ahf[mi][3],
                      stb + O_AH * 4 + off);
                ldsm4(alf[mi][0], alf[mi][1], alf[mi][2], alf[mi][3],
                      stb + O_AL * 4 + off);
            }
            #pragma unroll
            for (int nb = 0; nb < 2; ++nb) {
                int nr = wn * 32 + (nb * 2 + b_blk) * 8 + b_rin;
                int kg = ks * 2 + b_kg;
                uint32_t off = (uint32_t)swzg(nr, kg) * 4;
                ldsm4(bhf[nb * 2][0], bhf[nb * 2][1], bhf[nb * 2 + 1][0],
                      bhf[nb * 2 + 1][1], stb + O_BH * 4 + off);
                ldsm4(blf[nb * 2][0], blf[nb * 2][1], blf[nb * 2 + 1][0],
                      blf[nb * 2 + 1][1], stb + O_BL * 4 + off);
            }
            #pragma unroll
            for (int mi = 0; mi < MI; ++mi)
                #pragma unroll
                for (int ni = 0; ni < 4; ++ni)
                    mma16816(acc[mi][ni], ahf[mi][0], ahf[mi][1], ahf[mi][2],
                             ahf[mi][3], bhf[ni][0], bhf[ni][1]);
            #pragma unroll
            for (int mi = 0; mi < MI; ++mi)
                #pragma unroll
                for (int ni = 0; ni < 4; ++ni)
                    mma16816(acc[mi][ni], ahf[mi][0], ahf[mi][1], ahf[mi][2],
                             ahf[mi][3], blf[ni][0], blf[ni][1]);
            #pragma unroll
            for (int mi = 0; mi < MI; ++mi)
                #pragma unroll
                for (int ni = 0; ni < 4; ++ni)
                    mma16816(acc[mi][ni], alf[mi][0], alf[mi][1], alf[mi][2],
                             alf[mi][3], bhf[ni][0], bhf[ni][1]);
        }
        __syncthreads();
    }

    // ---------------- epilogue ----------------
    const int ldc2 = ldc >> 1;
    #pragma unroll
    for (int mi = 0; mi < MI; ++mi) {
        #pragma unroll
        for (int ni = 0; ni < 4; ++ni) {
            int row0 = m0 + wm * (MI * 16) + mi * 16 + g;
            int col  = n0 + wn * 32 + ni * 8 + 2 * t4;
            float* c = acc[mi][ni];
            #pragma unroll
            for (int h = 0; h < 2; ++h) {
                int row = row0 + h * 8;
                if (GM && row >= M) continue;
                float v0 = c[2 * h] * alpha, v1 = c[2 * h + 1] * alpha;
                if (EPI == 2) {
                    v0 = gelu_exact(v0 + bias[col]);
                    v1 = gelu_exact(v1 + bias[col + 1]);
                }
                if (OUT == 0) {
                    size_t off = (size_t)row * ldc + col;
                    if (EPI == 3) {
                        v0 += bias[col]     + Cf[off];
                        v1 += bias[col + 1] + Cf[off + 1];
                    }
                    if (GN) {
                        if (col < N)     Cf[off]     = v0;
                        if (col + 1 < N) Cf[off + 1] = v1;
                    } else {
                        float2 o; o.x = v0; o.y = v1;
                        *reinterpret_cast<float2*>(&Cf[off]) = o;
                    }
                } else {
                    uint32_t wh, wl;
                    cvt_pair(v0, v1, wh, wl);
                    size_t o = (size_t)row * ldc2 + (col >> 1);
                    Ch[o] = wh; Cl[o] = wl;
                }
            }
        }
    }
}

template <int NT, int EPI, int OUT, bool GN, bool GM>
static void L(const uint32_t* Ah, const uint32_t* Al, int lda2,
              long long sAb2, long long sAh2,
              const uint32_t* Bh, const uint32_t* Bl, int ldb2,
              long long sBb2, long long sBh2,
              float* Cf, uint32_t* Ch, uint32_t* Cl, int ldc,
              long long sCb, long long sChh, const float* bias,
              int M, int N, int K, float alpha, int batches, int H) {
    constexpr int STG = 2 * 2048 + 2 * NT * 16;
    const int smem = 3 * STG * 4;
    cudaFuncSetAttribute(hgemm_kernel<NT, EPI, OUT, GN, GM>,
                         cudaFuncAttributeMaxDynamicSharedMemorySize, smem);
    dim3 grid(ceil_div(N, NT), ceil_div(M, 128), batches);
    hgemm_kernel<NT, EPI, OUT, GN, GM><<<grid, 256, smem>>>(
        Ah, Al, lda2, sAb2, sAh2, Bh, Bl, ldb2, sBb2, sBh2,
        Cf, Ch, Cl, ldc, sCb, sChh, bias, M, N, K, alpha, H);
}

// ---------------------------------------------------------------------------
// fp32 transpose (x in/out)
// ---------------------------------------------------------------------------
__global__ void transpose_kernel(const float* __restrict__ in, float* __restrict__ out,
                                 int R, int Ccol) {
    __shared__ float tile[32][33];
    int b = blockIdx.z;
    const float* ip = in  + (size_t)b * R * Ccol;
    float*       op = out + (size_t)b * R * Ccol;
    int j0 = blockIdx.x * 32, i0 = blockIdx.y * 32;
    int tx = threadIdx.x, ty = threadIdx.y;
    #pragma unroll
    for (int k = 0; k < 32; k += 8) tile[ty + k][tx] = ip[(size_t)(i0 + ty + k) * Ccol + j0 + tx];
    __syncthreads();
    #pragma unroll
    for (int k = 0; k < 32; k += 8) op[(size_t)(j0 + ty + k) * R + i0 + tx] = tile[tx][ty + k];
}

// transpose weights fp32 (R x Ccol) -> hi/lo (Ccol x R) packed pairs
__global__ void transpose_hl(const float* __restrict__ in,
                             uint32_t* __restrict__ oh, uint32_t* __restrict__ ol,
                             int R, int Ccol) {
    __shared__ float tile[32][33];
    int j0 = blockIdx.x * 32, i0 = blockIdx.y * 32;
    int tx = threadIdx.x, ty = threadIdx.y;
    #pragma unroll
    for (int k = 0; k < 32; k += 8) tile[ty + k][tx] = in[(size_t)(i0 + ty + k) * Ccol + j0 + tx];
    __syncthreads();
    int flat = ty * 32 + tx;
    int R2 = R >> 1;
    #pragma unroll
    for (int rep = 0; rep < 2; ++rep) {
        int idx = flat + rep * 256;
        int i2 = idx & 15, j = idx >> 4;
        uint32_t h, l;
        cvt_pair(tile[2 * i2][j], tile[2 * i2 + 1][j], h, l);
        size_t o = (size_t)(j0 + j) * R2 + (i0 >> 1) + i2;
        oh[o] = h; ol[o] = l;
    }
}

// elementwise fp32 -> hi/lo pairs
__global__ void cvt_split(const float* __restrict__ in, uint32_t* __restrict__ oh,
                          uint32_t* __restrict__ ol, int nw) {
    int w = blockIdx.x * 256 + threadIdx.x;
    if (w >= nw) return;
    float2 f = reinterpret_cast<const float2*>(in)[w];
    uint32_t h, l; cvt_pair(f.x, f.y, h, l);
    oh[w] = h; ol[w] = l;
}

// ---------------------------------------------------------------------------
// LayerNorm: ADD variant (fp32 out = in + LN(in)); HL variant (hi/lo out)
// ---------------------------------------------------------------------------
template <bool HL>
__global__ void ln_kernel(const float* __restrict__ in,
                          const float* __restrict__ gamma,
                          const float* __restrict__ beta,
                          float* __restrict__ outf,
                          uint32_t* __restrict__ oh, uint32_t* __restrict__ ol) {
    int row = blockIdx.x;
    const float4* rin = reinterpret_cast<const float4*>(in + (size_t)row * CC);
    int t = threadIdx.x;
    float4 v = rin[t];
    float s  = v.x + v.y + v.z + v.w;
    float ss = v.x*v.x + v.y*v.y + v.z*v.z + v.w*v.w;
    #pragma unroll
    for (int o = 16; o > 0; o >>= 1) {
        s  += __shfl_xor_sync(0xffffffffu, s,  o);
        ss += __shfl_xor_sync(0xffffffffu, ss, o);
    }
    __shared__ float shs[4], shss[4];
    int warp = t >> 5, lane = t & 31;
    if (lane == 0) { shs[warp] = s; shss[warp] = ss; }
    __syncthreads();
    s  = shs[0] + shs[1] + shs[2] + shs[3];
    ss = shss[0] + shss[1] + shss[2] + shss[3];
    float mu  = s * (1.0f / CC);
    float var = ss * (1.0f / CC) - mu * mu;
    float rs  = rsqrtf(var + LN_EPS);
    float4 g4 = reinterpret_cast<const float4*>(gamma)[t];
    float4 b4 = reinterpret_cast<const float4*>(beta)[t];
    float4 o4;
    o4.x = (v.x - mu) * rs * g4.x + b4.x;
    o4.y = (v.y - mu) * rs * g4.y + b4.y;
    o4.z = (v.z - mu) * rs * g4.z + b4.z;
    o4.w = (v.w - mu) * rs * g4.w + b4.w;
    if (!HL) {
        o4.x += v.x; o4.y += v.y; o4.z += v.z; o4.w += v.w;
        reinterpret_cast<float4*>(outf + (size_t)row * CC)[t] = o4;
    } else {
        uint32_t h0, l0, h1, l1;
        cvt_pair(o4.x, o4.y, h0, l0);
        cvt_pair(o4.z, o4.w, h1, l1);
        size_t w = (size_t)row * (CC / 2) + t * 2;
        oh[w] = h0; oh[w + 1] = h1;
        ol[w] = l0; ol[w + 1] = l1;
    }
}

// ---------------------------------------------------------------------------
// Softmax: fp32 scores (ld=SP) -> P hi/lo (padded zeros to SP)
// ---------------------------------------------------------------------------
template <int S, int SP>
__global__ void softmax_hl(const float* __restrict__ sc,
                           uint32_t* __restrict__ ph, uint32_t* __restrict__ pl,
                           long long rows) {
    long long row = (long long)blockIdx.x * 4 + (threadIdx.x >> 5);
    if (row >= rows) return;
    const float* p = sc + row * SP;
    int lane = threadIdx.x & 31;
    float mx = -1e30f;
    for (int j = lane; j < S; j += 32) mx = fmaxf(mx, p[j]);
    #pragma unroll
    for (int o = 16; o > 0; o >>= 1) mx = fmaxf(mx, __shfl_xor_sync(0xffffffffu, mx, o));
    float sum = 0.0f;
    for (int j = lane; j < S; j += 32) sum += __expf(p[j] - mx);
    #pragma unroll
    for (int o = 16; o > 0; o >>= 1) sum += __shfl_xor_sync(0xffffffffu, sum, o);
    float inv = 1.0f / sum;
    uint32_t* oh = ph + row * (SP / 2);
    uint32_t* ol = pl + row * (SP / 2);
    for (int j2 = lane; j2 < SP / 2; j2 += 32) {
        int j = 2 * j2;
        float a = (j     < S) ? __expf(p[j]     - mx) * inv : 0.0f;
        float b = (j + 1 < S) ? __expf(p[j + 1] - mx) * inv : 0.0f;
        uint32_t h, l; cvt_pair(a, b, h, l);
        oh[j2] = h; ol[j2] = l;
    }
}

// ---------------------------------------------------------------------------
// V (B*S x CC fp32) -> per-head V^T hi/lo (32 x HD x SP/2 words), zero-padded
// ---------------------------------------------------------------------------
template <int S, int SP>
__global__ void vt_build(const float* __restrict__ v,
                         uint32_t* __restrict__ vth, uint32_t* __restrict__ vtl) {
    int bh = blockIdx.x;
    int b = bh >> 3, h = bh & 7;
    const float* vb = v + (size_t)b * S * CC + h * 64;
    uint32_t* oh = vth + (size_t)bh * HD * (SP / 2);
    uint32_t* ol = vtl + (size_t)bh * HD * (SP / 2);
    for (int idx = threadIdx.x; idx < HD * (SP / 2); idx += blockDim.x) {
        int d = idx / (SP / 2), sw = idx % (SP / 2);
        int s = 2 * sw;
        float x = (s     < S) ? vb[(size_t)s       * CC + d] : 0.0f;
        float y = (s + 1 < S) ? vb[(size_t)(s + 1) * CC + d] : 0.0f;
        uint32_t hh, ll; cvt_pair(x, y, hh, ll);
        oh[idx] = hh; ol[idx] = ll;
    }
}

// ---------------------------------------------------------------------------
// Entry
// ---------------------------------------------------------------------------
extern "C" void kernel_launch(void* const* d_in, const int* in_sizes, int n_in,
                              void* d_out, int out_size) {
    const float* x    = (const float*)d_in[0];
    const float* ctx  = (const float*)d_in[1];
    const float* geo  = (const float*)d_in[2];
    const float* g1 = (const float*)d_in[3],  *b1 = (const float*)d_in[4];
    const float* g2 = (const float*)d_in[5],  *b2 = (const float*)d_in[6];
    const float* g3 = (const float*)d_in[7],  *b3 = (const float*)d_in[8];
    const float* g4 = (const float*)d_in[9],  *b4 = (const float*)d_in[10];
    const float* cWq = (const float*)d_in[11], *cWk = (const float*)d_in[12];
    const float* cWv = (const float*)d_in[13], *cWo = (const float*)d_in[14];
    const float* cbo = (const float*)d_in[15];
    const float* gWq = (const float*)d_in[16], *gWk = (const float*)d_in[17];
    const float* gWv = (const float*)d_in[18], *gWo = (const float*)d_in[19];
    const float* gbo = (const float*)d_in[20];
    const float* W1  = (const float*)d_in[21], *bf1 = (const float*)d_in[22];
    const float* W2  = (const float*)d_in[23], *bf2 = (const float*)d_in[24];
    float* out = (float*)d_out;

    float *t_d, *v_d, *big_d;
    uint32_t *xnh, *xnl, *qh, *ql, *kh, *kl, *vth, *vtl, *ah, *al, *ph, *pl;
    uint32_t *cth, *ctl, *geoh, *geol, *wth, *wtl;
    cudaGetSymbolAddress((void**)&t_d,  g_t);
    cudaGetSymbolAddress((void**)&v_d,  g_v);
    cudaGetSymbolAddress((void**)&big_d, g_big);
    cudaGetSymbolAddress((void**)&xnh, g_xnh);  cudaGetSymbolAddress((void**)&xnl, g_xnl);
    cudaGetSymbolAddress((void**)&qh,  g_qh);   cudaGetSymbolAddress((void**)&ql,  g_ql);
    cudaGetSymbolAddress((void**)&kh,  g_kh);   cudaGetSymbolAddress((void**)&kl,  g_kl);
    cudaGetSymbolAddress((void**)&vth, g_vth);  cudaGetSymbolAddress((void**)&vtl, g_vtl);
    cudaGetSymbolAddress((void**)&ah,  g_ah);   cudaGetSymbolAddress((void**)&al,  g_al);
    cudaGetSymbolAddress((void**)&ph,  g_ph);   cudaGetSymbolAddress((void**)&pl,  g_pl);
    cudaGetSymbolAddress((void**)&cth, g_cth);  cudaGetSymbolAddress((void**)&ctl, g_ctl);
    cudaGetSymbolAddress((void**)&geoh, g_geoh); cudaGetSymbolAddress((void**)&geol, g_geol);
    cudaGetSymbolAddress((void**)&wth, g_wth);  cudaGetSymbolAddress((void**)&wtl, g_wtl);

    // ---- weight transpose+split, input split
    {
        dim3 blk(32, 8);
        dim3 gr1(CC / 32, CC / 32);
        transpose_hl<<<gr1, blk>>>(cWq, wth + WT2_CWQ, wtl + WT2_CWQ, CC, CC);
        transpose_hl<<<gr1, blk>>>(cWo, wth + WT2_CWO, wtl + WT2_CWO, CC, CC);
        transpose_hl<<<gr1, blk>>>(gWq, wth + WT2_GWQ, wtl + WT2_GWQ, CC, CC);
        transpose_hl<<<gr1, blk>>>(gWo, wth + WT2_GWO, wtl + WT2_GWO, CC, CC);
        transpose_hl<<<gr1, blk>>>(gWk, wth + WT2_GWK, wtl + WT2_GWK, GEO_D, CC);
        transpose_hl<<<gr1, blk>>>(gWv, wth + WT2_GWV, wtl + WT2_GWV, GEO_D, CC);
        dim3 grc(CC / 32, CTX_D / 32);
        transpose_hl<<<grc, blk>>>(cWk, wth + WT2_CWK, wtl + WT2_CWK, CTX_D, CC);
        transpose_hl<<<grc, blk>>>(cWv, wth + WT2_CWV, wtl + WT2_CWV, CTX_D, CC);
        dim3 gr2(FFN_D / 32, CC / 32);
        transpose_hl<<<gr2, blk>>>(W1, wth + WT2_W1, wtl + WT2_W1, CC, FFN_D);
        dim3 gr3(CC / 32, FFN_D / 32);
        transpose_hl<<<gr3, blk>>>(W2, wth + WT2_W2, wtl + WT2_W2, FFN_D, CC);
        int nwc = BATCH * CTX_S * CTX_D / 2;
        cvt_split<<<ceil_div(nwc, 256), 256>>>(ctx, cth, ctl, nwc);
        int nwg = BATCH * GEO_S * GEO_D / 2;
        cvt_split<<<ceil_div(nwg, 256), 256>>>(geo, geoh, geol, nwg);
    }

    // 1) transpose x (B,C,N) -> t0 (B,N,C) in big; t = t0 + LN1(t0)
    {
        dim3 grid(NTOK / 32, CC / 32, BATCH);
        transpose_kernel<<<grid, dim3(32, 8)>>>(x, big_d, CC, NTOK);
    }
    ln_kernel<false><<<NROWS, 128>>>(big_d, g1, b1, t_d, nullptr, nullptr);

    long long rows32 = (long long)BATCH * HHEADS * NTOK;

    // ================= context cross-attention (S=77) =================
    ln_kernel<true><<<NROWS, 128>>>(t_d, g2, b2, nullptr, xnh, xnl);
    L<128, 0, 1, false, false>(xnh, xnl, 256, 0, 0,
        wth + WT2_CWQ, wtl + WT2_CWQ, 256, 0, 0,
        nullptr, qh, ql, CC, 0, 0, nullptr, NROWS, CC, CC, 1.0f, 1, 1);
    L<128, 0, 1, false, true>(cth, ctl, 384, 0, 0,
        wth + WT2_CWK, wtl + WT2_CWK, 384, 0, 0,
        nullptr, kh, kl, CC, 0, 0, nullptr, BATCH * CTX_S, CC, CTX_D, 1.0f, 1, 1);
    L<128, 0, 0, false, true>(cth, ctl, 384, 0, 0,
        wth + WT2_CWV, wtl + WT2_CWV, 384, 0, 0,
        v_d, nullptr, nullptr, CC, 0, 0, nullptr, BATCH * CTX_S, CC, CTX_D, 1.0f, 1, 1);
    vt_build<CTX_S, CTX_SP><<<32, 256>>>(v_d, vth, vtl);
    L<128, 0, 0, true, false>(qh, ql, 256, (long long)NTOK * 256, 32,
        kh, kl, 256, (long long)CTX_S * 256, 32,
        big_d, nullptr, nullptr, CTX_SP,
        (long long)HHEADS * NTOK * CTX_SP, (long long)NTOK * CTX_SP,
        nullptr, NTOK, CTX_S, HD, 0.125f, BATCH * HHEADS, HHEADS);
    softmax_hl<CTX_S, CTX_SP><<<(unsigned)(rows32 / 4), 128>>>(big_d, ph, pl, rows32);
    L<64, 0, 1, false, false>(ph, pl, CTX_SP / 2,
        (long long)HHEADS * NTOK * (CTX_SP / 2), (long long)NTOK * (CTX_SP / 2),
        vth, vtl, CTX_SP / 2,
        (long long)HHEADS * HD * (CTX_SP / 2), (long long)HD * (CTX_SP / 2),
        nullptr, ah, al, CC, (long long)NTOK * CC, HD,
        nullptr, NTOK, HD, CTX_SP, 1.0f, BATCH * HHEADS, HHEADS);
    L<128, 3, 0, false, false>(ah, al, 256, 0, 0,
        wth + WT2_CWO, wtl + WT2_CWO, 256, 0, 0,
        t_d, nullptr, nullptr, CC, 0, 0, cbo, NROWS, CC, CC, 1.0f, 1, 1);

    // ================= geometry cross-attention (S=256) =================
    ln_kernel<true><<<NROWS, 128>>>(t_d, g3, b3, nullptr, xnh, xnl);
    L<128, 0, 1, false, false>(xnh, xnl, 256, 0, 0,
        wth + WT2_GWQ, wtl + WT2_GWQ, 256, 0, 0,
        nullptr, qh, ql, CC, 0, 0, nullptr, NROWS, CC, CC, 1.0f, 1, 1);
    L<128, 0, 1, false, false>(geoh, geol, 256, 0, 0,
        wth + WT2_GWK, wtl + WT2_GWK, 256, 0, 0,
        nullptr, kh, kl, CC, 0, 0, nullptr, BATCH * GEO_S, CC, GEO_D, 1.0f, 1, 1);
    L<128, 0, 0, false, false>(geoh, geol, 256, 0, 0,
        wth + WT2_GWV, wtl + WT2_GWV, 256, 0, 0,
        v_d, nullptr, nullptr, CC, 0, 0, nullptr, BATCH * GEO_S, CC, GEO_D, 1.0f, 1, 1);
    vt_build<GEO_S, GEO_S><<<32, 256>>>(v_d, vth, vtl);
    L<128, 0, 0, false, false>(qh, ql, 256, (long long)NTOK * 256, 32,
        kh, kl, 256, (long long)GEO_S * 256, 32,
        big_d, nullptr, nullptr, GEO_S,
        (long long)HHEADS * NTOK * GEO_S, (long long)NTOK * GEO_S,
        nullptr, NTOK, GEO_S, HD, 0.125f, BATCH * HHEADS, HHEADS);
    softmax_hl<GEO_S, GEO_S><<<(unsigned)(rows32 / 4), 128>>>(big_d, ph, pl, rows32);
    L<64, 0, 1, false, false>(ph, pl, GEO_S / 2,
        (long long)HHEADS * NTOK * (GEO_S / 2), (long long)NTOK * (GEO_S / 2),
        vth, vtl, GEO_S / 2,
        (long long)HHEADS * HD * (GEO_S / 2), (long long)HD * (GEO_S / 2),
        nullptr, ah, al, CC, (long long)NTOK * CC, HD,
        nullptr, NTOK, HD, GEO_S, 1.0f, BATCH * HHEADS, HHEADS);
    L<128, 3, 0, false, false>(ah, al, 256, 0, 0,
        wth + WT2_GWO, wtl + WT2_GWO, 256, 0, 0,
        t_d, nullptr, nullptr, CC, 0, 0, gbo, NROWS, CC, CC, 1.0f, 1, 1);

    // ================= FFN =================
    ln_kernel<true><<<NROWS, 128>>>(t_d, g4, b4, nullptr, xnh, xnl);
    L<128, 2, 1, false, false>(xnh, xnl, 256, 0, 0,
        wth + WT2_W1, wtl + WT2_W1, 256, 0, 0,
        nullptr, ph, pl, FFN_D, 0, 0, bf1, NROWS, FFN_D, CC, 1.0f, 1, 1);
    L<128, 3, 0, false, false>(ph, pl, 1024, 0, 0,
        wth + WT2_W2, wtl + WT2_W2, 1024, 0, 0,
        t_d, nullptr, nullptr, CC, 0, 0, bf2, NROWS, CC, FFN_D, 1.0f, 1, 1);

    // ---- transpose back
    {
        dim3 grid(CC / 32, NTOK / 32, BATCH);
        transpose_kernel<<<grid, dim3(32, 8)>>>(t_d, out, NTOK, CC);
    }
}

// round 9
// speedup vs baseline: 2.4551x; 1.1850x over previous
#include <cuda_runtime.h>
#include <cuda_bf16.h>
#include <cuda_fp16.h>
#include <cstdint>
#include <cstddef>

// ---------------------------------------------------------------------------
// Problem constants
// ---------------------------------------------------------------------------
#define BATCH   4
#define CC      512
#define NTOK    4096
#define NROWS   (BATCH*NTOK)
#define HHEADS  8
#define HD      64
#define CTX_S   77
#define CTX_SP  96        // padded S for ctx scores / P
#define CTX_D   768
#define GEO_S   256
#define GEO_D   512
#define FFN_D   2048
#define LN_EPS  1e-5f

static inline int ceil_div(int a, int b) { return (a + b - 1) / b; }

// ---------------------------------------------------------------------------
// Scratch (static device globals) — packed 16-bit pairs as uint32
// ---------------------------------------------------------------------------
__device__ __align__(16) uint32_t g_xnh[4194304], g_xnl[4194304];   // LN output (bf16 hi/lo)
__device__ __align__(16) uint32_t g_qh [4194304];                   // Q (fp16)
__device__ __align__(16) uint32_t g_kh [262144];                    // K proj (fp16)
__device__ __align__(16) uint32_t g_vth[262144];                    // V^T per head (fp16)
__device__ __align__(16) uint32_t g_ah [4194304], g_al [4194304];   // attn out (bf16 hi/lo)
__device__ __align__(16) uint32_t g_ph [16777216],g_pl [16777216];  // P (fp16) / FFN hidden (bf16 hi/lo)
__device__ __align__(16) uint32_t g_cth[118272],  g_ctl[118272];    // ctx input (bf16 hi/lo)
__device__ __align__(16) uint32_t g_geoh[262144], g_geol[262144];   // geo input (bf16 hi/lo)
__device__ __align__(16) uint32_t g_wth[2228224], g_wtl[2228224];   // weights^T (bf16 hi/lo)
__device__ float g_t  [(size_t)NROWS * CC];       // residual stream (fp32)
__device__ float g_v  [(size_t)BATCH * GEO_S * CC];
__device__ float g_big[(size_t)33554432];         // scores fp32 / t0 temp

// word offsets into g_wth/g_wtl
#define WT2_CWQ 0
#define WT2_CWO 131072
#define WT2_GWQ 262144
#define WT2_GWO 393216
#define WT2_W1  524288
#define WT2_W2  1048576
#define WT2_CWK 1572864
#define WT2_CWV 1769472
#define WT2_GWK 1966080
#define WT2_GWV 2097152

__device__ __forceinline__ float gelu_exact(float x) {
    return 0.5f * x * (1.0f + erff(x * 0.70710678118654752440f));
}

// ---------------------------------------------------------------------------
// helpers
// ---------------------------------------------------------------------------
__device__ __forceinline__ uint32_t smem_u32(const void* p) {
    uint32_t a;
    asm("{ .reg .u64 t; cvta.to.shared.u64 t, %1; cvt.u32.u64 %0, t; }" : "=r"(a) : "l"(p));
    return a;
}
__device__ __forceinline__ void cvt_pair(float x, float y, uint32_t& hi, uint32_t& lo) {
    __nv_bfloat16 hx = __float2bfloat16(x);
    __nv_bfloat16 hy = __float2bfloat16(y);
    __nv_bfloat16 lx = __float2bfloat16(x - __bfloat162float(hx));
    __nv_bfloat16 ly = __float2bfloat16(y - __bfloat162float(hy));
    hi = (uint32_t)__bfloat16_as_ushort(hx) | ((uint32_t)__bfloat16_as_ushort(hy) << 16);
    lo = (uint32_t)__bfloat16_as_ushort(lx) | ((uint32_t)__bfloat16_as_ushort(ly) << 16);
}
__device__ __forceinline__ uint32_t pack_h2(float x, float y) {
    __half2 h = __floats2half2_rn(x, y);
    return *reinterpret_cast<uint32_t*>(&h);
}
template <bool F16>
__device__ __forceinline__ void mma16816(float c[4], uint32_t a0, uint32_t a1, uint32_t a2,
                                         uint32_t a3, uint32_t b0, uint32_t b1) {
    if (F16) {
        asm volatile(
            "mma.sync.aligned.m16n8k16.row.col.f32.f16.f16.f32 "
            "{%0,%1,%2,%3}, {%4,%5,%6,%7}, {%8,%9}, {%0,%1,%2,%3};"
            : "+f"(c[0]), "+f"(c[1]), "+f"(c[2]), "+f"(c[3])
            : "r"(a0), "r"(a1), "r"(a2), "r"(a3), "r"(b0), "r"(b1));
    } else {
        asm volatile(
            "mma.sync.aligned.m16n8k16.row.col.f32.bf16.bf16.f32 "
            "{%0,%1,%2,%3}, {%4,%5,%6,%7}, {%8,%9}, {%0,%1,%2,%3};"
            : "+f"(c[0]), "+f"(c[1]), "+f"(c[2]), "+f"(c[3])
            : "r"(a0), "r"(a1), "r"(a2), "r"(a3), "r"(b0), "r"(b1));
    }
}
__device__ __forceinline__ void ldsm4(uint32_t& r0, uint32_t& r1, uint32_t& r2, uint32_t& r3,
                                      uint32_t addr) {
    asm volatile("ldmatrix.sync.aligned.m8n8.x4.shared.b16 {%0,%1,%2,%3}, [%4];"
                 : "=r"(r0), "=r"(r1), "=r"(r2), "=r"(r3) : "r"(addr));
}
// swizzled word offset of 16B group kg (0..3) in a 16-word row
__device__ __forceinline__ int swzg(int row, int kg) {
    return row * 16 + (((kg ^ ((row >> 1) & 3))) << 2);
}
__device__ __forceinline__ void cpa16(uint32_t dst, const uint32_t* src, bool ok) {
    int sz = ok ? 16 : 0;
    asm volatile("cp.async.cg.shared.global [%0], [%1], 16, %2;"
                 :: "r"(dst), "l"(src), "r"(sz) : "memory");
}

// ---------------------------------------------------------------------------
// Unified HMMA GEMM.
// PASS=3: bf16x3 split (hi/lo arrays).  PASS=1: single fp16 pass (h arrays).
//   C[M,N] = alpha * A[M,K] @ B[N,K]^T
// NT: 128 (warps 2x4) or 64 (warps 4x2). K multiple of 32.
// GN: B row guard (+fp32 epilogue col guard). GM: A row guard.
// EPI: 0 none, 2 gelu(v+bias), 3 C += v + bias.
// OUT: 0 fp32, 1 bf16 hi/lo pair, 2 fp16 packed.
// Batched via grid.z (bb = z/H, hh = z%H); strides in words (A/B) / elems (C).
// ---------------------------------------------------------------------------
template <int NT, int EPI, int OUT, bool GN, bool GM, int PASS>
__global__ void __launch_bounds__(256) hgemm_kernel(
    const uint32_t* __restrict__ Ah, const uint32_t* __restrict__ Al, int lda2,
    long long sAb2, long long sAh2,
    const uint32_t* __restrict__ Bh, const uint32_t* __restrict__ Bl, int ldb2,
    long long sBb2, long long sBh2,
    float* __restrict__ Cf, uint32_t* __restrict__ Ch, uint32_t* __restrict__ Cl,
    int ldc, long long sCb, long long sChh,
    const float* __restrict__ bias,
    int M, int N, int K, float alpha, int H)
{
    constexpr int MI = (NT == 128) ? 4 : 2;
    constexpr int AW = 2048;
    constexpr int BW = NT * 16;
    constexpr int O_AH = 0;
    constexpr int O_AL = (PASS == 3) ? AW : 0;
    constexpr int O_BH = (PASS == 3) ? 2 * AW : AW;
    constexpr int O_BL = (PASS == 3) ? 2 * AW + BW : AW;
    constexpr int STG  = (PASS == 3) ? (2 * AW + 2 * BW) : (AW + BW);
    extern __shared__ uint32_t sm[];

    {
        int z = blockIdx.z;
        int bb = z / H, hh = z - bb * H;
        long long ao = bb * sAb2 + hh * sAh2;
        long long bo = bb * sBb2 + hh * sBh2;
        Ah += ao; Al += ao; Bh += bo; Bl += bo;
        long long co = bb * sCb + hh * sChh;
        if (OUT == 0) Cf += co;
        else { Ch += (co >> 1); Cl += (co >> 1); }
    }

    const int tid  = threadIdx.x;
    const int wid  = tid >> 5, lane = tid & 31;
    const int g    = lane >> 2, t4 = lane & 3;
    const int wm   = (NT == 128) ? (wid >> 2) : (wid >> 1);
    const int wn   = (NT == 128) ? (wid & 3)  : (wid & 1);
    const int m0   = blockIdx.y * 128;
    const int n0   = blockIdx.x * NT;
    const uint32_t smb = smem_u32(sm);

    auto issue = [&](int ch, int stg) {
        const int k0w = ch * 16;
        const uint32_t base = smb + (uint32_t)stg * STG * 4;
        {
            int r  = tid >> 1;
            int gr = m0 + r;
            bool ok = !GM || (gr < M);
            if (GM) gr = min(gr, M - 1);
            const uint32_t* sa = Ah + (size_t)gr * lda2 + k0w;
            const uint32_t* sl = Al + (size_t)gr * lda2 + k0w;
            #pragma unroll
            for (int e = 0; e < 2; ++e) {
                int grp = (tid & 1) * 2 + e;
                int d = swzg(r, grp);
                cpa16(base + (O_AH + d) * 4, sa + grp * 4, ok);
                if (PASS == 3) cpa16(base + (O_AL + d) * 4, sl + grp * 4, ok);
            }
        }
        if (NT == 128) {
            int r  = tid >> 1;
            int gr = n0 + r;
            bool ok = !GN || (gr < N);
            if (GN) gr = min(gr, N - 1);
            const uint32_t* sb = Bh + (size_t)gr * ldb2 + k0w;
            const uint32_t* sl = Bl + (size_t)gr * ldb2 + k0w;
            #pragma unroll
            for (int e = 0; e < 2; ++e) {
                int grp = (tid & 1) * 2 + e;
                int d = swzg(r, grp);
                cpa16(base + (O_BH + d) * 4, sb + grp * 4, ok);
                if (PASS == 3) cpa16(base + (O_BL + d) * 4, sl + grp * 4, ok);
            }
        } else {
            int r = tid >> 2, grp = tid & 3;
            const uint32_t* sb = Bh + (size_t)(n0 + r) * ldb2 + k0w;
            const uint32_t* sl = Bl + (size_t)(n0 + r) * ldb2 + k0w;
            int d = swzg(r, grp);
            cpa16(base + (O_BH + d) * 4, sb + grp * 4, true);
            if (PASS == 3) cpa16(base + (O_BL + d) * 4, sl + grp * 4, true);
        }
        asm volatile("cp.async.commit_group;" ::: "memory");
    };

    float acc[MI][4][4] = {};
    const int nch = K >> 5;

    issue(0, 0);
    if (nch > 1) issue(1, 1);

    const int a_rin = ((lane >> 3) & 1) * 8 + (lane & 7);
    const int a_kg  = lane >> 4;
    const int b_blk = lane >> 4;
    const int b_kg  = (lane >> 3) & 1;
    const int b_rin = lane & 7;

    for (int ch = 0; ch < nch; ++ch) {
        if (ch + 1 < nch) {
            asm volatile("cp.async.wait_group 1;" ::: "memory");
        } else {
            asm volatile("cp.async.wait_group 0;" ::: "memory");
        }
        __syncthreads();
        if (ch + 2 < nch) issue(ch + 2, (ch + 2) % 3);

        const uint32_t stb = smb + (uint32_t)(ch % 3) * STG * 4;
        #pragma unroll
        for (int ks = 0; ks < 2; ++ks) {
            uint32_t ahf[MI][4], alf[MI][4], bhf[4][2], blf[4][2];
            #pragma unroll
            for (int mi = 0; mi < MI; ++mi) {
                int rr = wm * (MI * 16) + mi * 16 + a_rin;
                int kg = ks * 2 + a_kg;
                uint32_t off = (uint32_t)swzg(rr, kg) * 4;
                ldsm4(ahf[mi][0], ahf[mi][1], ahf[mi][2], ahf[mi][3],
                      stb + O_AH * 4 + off);
                if (PASS == 3)
                    ldsm4(alf[mi][0], alf[mi][1], alf[mi][2], alf[mi][3],
                          stb + O_AL * 4 + off);
            }
            #pragma unroll
            for (int nb = 0; nb < 2; ++nb) {
                int nr = wn * 32 + (nb * 2 + b_blk) * 8 + b_rin;
                int kg = ks * 2 + b_kg;
                uint32_t off = (uint32_t)swzg(nr, kg) * 4;
                ldsm4(bhf[nb * 2][0], bhf[nb * 2][1], bhf[nb * 2 + 1][0],
                      bhf[nb * 2 + 1][1], stb + O_BH * 4 + off);
                if (PASS == 3)
                    ldsm4(blf[nb * 2][0], blf[nb * 2][1], blf[nb * 2 + 1][0],
                          blf[nb * 2 + 1][1], stb + O_BL * 4 + off);
            }
            #pragma unroll
            for (int mi = 0; mi < MI; ++mi)
                #pragma unroll
                for (int ni = 0; ni < 4; ++ni)
                    mma16816<PASS == 1>(acc[mi][ni], ahf[mi][0], ahf[mi][1],
                                        ahf[mi][2], ahf[mi][3], bhf[ni][0], bhf[ni][1]);
            if (PASS == 3) {
                #pragma unroll
                for (int mi = 0; mi < MI; ++mi)
                    #pragma unroll
                    for (int ni = 0; ni < 4; ++ni)
                        mma16816<false>(acc[mi][ni], ahf[mi][0], ahf[mi][1],
                                        ahf[mi][2], ahf[mi][3], blf[ni][0], blf[ni][1]);
                #pragma unroll
                for (int mi = 0; mi < MI; ++mi)
                    #pragma unroll
                    for (int ni = 0; ni < 4; ++ni)
                        mma16816<false>(acc[mi][ni], alf[mi][0], alf[mi][1],
                                        alf[mi][2], alf[mi][3], bhf[ni][0], bhf[ni][1]);
            }
        }
    }

    // ---------------- epilogue ----------------
    const int ldc2 = ldc >> 1;
    #pragma unroll
    for (int mi = 0; mi < MI; ++mi) {
        #pragma unroll
        for (int ni = 0; ni < 4; ++ni) {
            int row0 = m0 + wm * (MI * 16) + mi * 16 + g;
            int col  = n0 + wn * 32 + ni * 8 + 2 * t4;
            float* c = acc[mi][ni];
            #pragma unroll
            for (int h = 0; h < 2; ++h) {
                int row = row0 + h * 8;
                if (GM && row >= M) continue;
                float v0 = c[2 * h] * alpha, v1 = c[2 * h + 1] * alpha;
                if (EPI == 2) {
                    v0 = gelu_exact(v0 + bias[col]);
                    v1 = gelu_exact(v1 + bias[col + 1]);
                }
                if (OUT == 0) {
                    size_t off = (size_t)row * ldc + col;
                    if (EPI == 3) {
                        v0 += bias[col]     + Cf[off];
                        v1 += bias[col + 1] + Cf[off + 1];
                    }
                    if (GN) {
                        if (col < N)     Cf[off]     = v0;
                        if (col + 1 < N) Cf[off + 1] = v1;
                    } else {
                        float2 o; o.x = v0; o.y = v1;
                        *reinterpret_cast<float2*>(&Cf[off]) = o;
                    }
                } else if (OUT == 1) {
                    uint32_t wh, wl;
                    cvt_pair(v0, v1, wh, wl);
                    size_t o = (size_t)row * ldc2 + (col >> 1);
                    Ch[o] = wh; Cl[o] = wl;
                } else {
                    size_t o = (size_t)row * ldc2 + (col >> 1);
                    Ch[o] = pack_h2(v0, v1);
                }
            }
        }
    }
}

template <int NT, int EPI, int OUT, bool GN, bool GM, int PASS>
static void L(const uint32_t* Ah, const uint32_t* Al, int lda2,
              long long sAb2, long long sAh2,
              const uint32_t* Bh, const uint32_t* Bl, int ldb2,
              long long sBb2, long long sBh2,
              float* Cf, uint32_t* Ch, uint32_t* Cl, int ldc,
              long long sCb, long long sChh, const float* bias,
              int M, int N, int K, float alpha, int batches, int H) {
    constexpr int STG = (PASS == 3) ? (2 * 2048 + 2 * NT * 16) : (2048 + NT * 16);
    const int smem = 3 * STG * 4;
    cudaFuncSetAttribute(hgemm_kernel<NT, EPI, OUT, GN, GM, PASS>,
                         cudaFuncAttributeMaxDynamicSharedMemorySize, smem);
    dim3 grid(ceil_div(N, NT), ceil_div(M, 128), batches);
    hgemm_kernel<NT, EPI, OUT, GN, GM, PASS><<<grid, 256, smem>>>(
        Ah, Al, lda2, sAb2, sAh2, Bh, Bl, ldb2, sBb2, sBh2,
        Cf, Ch, Cl, ldc, sCb, sChh, bias, M, N, K, alpha, H);
}

// ---------------------------------------------------------------------------
// fp32 transpose (x in/out)
// ---------------------------------------------------------------------------
__global__ void transpose_kernel(const float* __restrict__ in, float* __restrict__ out,
                                 int R, int Ccol) {
    __shared__ float tile[32][33];
    int b = blockIdx.z;
    const float* ip = in  + (size_t)b * R * Ccol;
    float*       op = out + (size_t)b * R * Ccol;
    int j0 = blockIdx.x * 32, i0 = blockIdx.y * 32;
    int tx = threadIdx.x, ty = threadIdx.y;
    #pragma unroll
    for (int k = 0; k < 32; k += 8) tile[ty + k][tx] = ip[(size_t)(i0 + ty + k) * Ccol + j0 + tx];
    __syncthreads();
    #pragma unroll
    for (int k = 0; k < 32; k += 8) op[(size_t)(j0 + ty + k) * R + i0 + tx] = tile[tx][ty + k];
}

// ---------------------------------------------------------------------------
// One-shot weight prep: all 10 transpose+split tasks in a single launch.
// ---------------------------------------------------------------------------
struct PrepArgs { const float* src[10]; };

__global__ void prep_weights(PrepArgs a, uint32_t* __restrict__ wth,
                             uint32_t* __restrict__ wtl) {
    const int starts[11] = {0, 256, 512, 768, 1024, 1280, 1536, 1920, 2304, 3328, 4352};
    const int Rt[10] = {512, 512, 512, 512, 512, 512, 768, 768, 512, 2048};
    const int Ct[10] = {512, 512, 512, 512, 512, 512, 512, 512, 2048, 512};
    const int Ot[10] = {WT2_CWQ, WT2_CWO, WT2_GWQ, WT2_GWO, WT2_GWK, WT2_GWV,
                        WT2_CWK, WT2_CWV, WT2_W1, WT2_W2};
    int b = blockIdx.x, t = 0;
    while (b >= starts[t + 1]) ++t;
    int lb = b - starts[t];
    int R = Rt[t], C = Ct[t], bx = C / 32;
    int j0 = (lb % bx) * 32, i0 = (lb / bx) * 32;
    const float* in = a.src[t];
    uint32_t* oh = wth + Ot[t];
    uint32_t* ol = wtl + Ot[t];

    __shared__ float tile[32][33];
    int tid = threadIdx.x;
    int tx = tid & 31, ty = tid >> 5;
    #pragma unroll
    for (int k = 0; k < 32; k += 8)
        tile[ty + k][tx] = in[(size_t)(i0 + ty + k) * C + j0 + tx];
    __syncthreads();
    int R2 = R >> 1;
    #pragma unroll
    for (int rep = 0; rep < 2; ++rep) {
        int idx = tid + rep * 256;
        int i2 = idx & 15, j = idx >> 4;
        uint32_t h, l;
        cvt_pair(tile[2 * i2][j], tile[2 * i2 + 1][j], h, l);
        size_t o = (size_t)(j0 + j) * R2 + (i0 >> 1) + i2;
        oh[o] = h; ol[o] = l;
    }
}

// elementwise fp32 -> bf16 hi/lo pairs
__global__ void cvt_split(const float* __restrict__ in, uint32_t* __restrict__ oh,
                          uint32_t* __restrict__ ol, int nw) {
    int w = blockIdx.x * 256 + threadIdx.x;
    if (w >= nw) return;
    float2 f = reinterpret_cast<const float2*>(in)[w];
    uint32_t h, l; cvt_pair(f.x, f.y, h, l);
    oh[w] = h; ol[w] = l;
}

// ---------------------------------------------------------------------------
// LayerNorm: ADD variant (fp32 out = in + LN(in)); HL variant (bf16 hi/lo out)
// ---------------------------------------------------------------------------
template <bool HL>
__global__ void ln_kernel(const float* __restrict__ in,
                          const float* __restrict__ gamma,
                          const float* __restrict__ beta,
                          float* __restrict__ outf,
                          uint32_t* __restrict__ oh, uint32_t* __restrict__ ol) {
    int row = blockIdx.x;
    const float4* rin = reinterpret_cast<const float4*>(in + (size_t)row * CC);
    int t = threadIdx.x;
    float4 v = rin[t];
    float s  = v.x + v.y + v.z + v.w;
    float ss = v.x*v.x + v.y*v.y + v.z*v.z + v.w*v.w;
    #pragma unroll
    for (int o = 16; o > 0; o >>= 1) {
        s  += __shfl_xor_sync(0xffffffffu, s,  o);
        ss += __shfl_xor_sync(0xffffffffu, ss, o);
    }
    __shared__ float shs[4], shss[4];
    int warp = t >> 5, lane = t & 31;
    if (lane == 0) { shs[warp] = s; shss[warp] = ss; }
    __syncthreads();
    s  = shs[0] + shs[1] + shs[2] + shs[3];
    ss = shss[0] + shss[1] + shss[2] + shss[3];
    float mu  = s * (1.0f / CC);
    float var = ss * (1.0f / CC) - mu * mu;
    float rs  = rsqrtf(var + LN_EPS);
    float4 g4 = reinterpret_cast<const float4*>(gamma)[t];
    float4 b4 = reinterpret_cast<const float4*>(beta)[t];
    float4 o4;
    o4.x = (v.x - mu) * rs * g4.x + b4.x;
    o4.y = (v.y - mu) * rs * g4.y + b4.y;
    o4.z = (v.z - mu) * rs * g4.z + b4.z;
    o4.w = (v.w - mu) * rs * g4.w + b4.w;
    if (!HL) {
        o4.x += v.x; o4.y += v.y; o4.z += v.z; o4.w += v.w;
        reinterpret_cast<float4*>(outf + (size_t)row * CC)[t] = o4;
    } else {
        uint32_t h0, l0, h1, l1;
        cvt_pair(o4.x, o4.y, h0, l0);
        cvt_pair(o4.z, o4.w, h1, l1);
        size_t w = (size_t)row * (CC / 2) + t * 2;
        oh[w] = h0; oh[w + 1] = h1;
        ol[w] = l0; ol[w + 1] = l1;
    }
}

// ---------------------------------------------------------------------------
// Softmax: fp32 scores (ld=SP) -> P fp16 packed (padded zeros to SP)
// ---------------------------------------------------------------------------
template <int S, int SP>
__global__ void softmax_h(const float* __restrict__ sc,
                          uint32_t* __restrict__ ph, long long rows) {
    long long row = (long long)blockIdx.x * 4 + (threadIdx.x >> 5);
    if (row >= rows) return;
    const float* p = sc + row * SP;
    int lane = threadIdx.x & 31;
    float mx = -1e30f;
    for (int j = lane; j < S; j += 32) mx = fmaxf(mx, p[j]);
    #pragma unroll
    for (int o = 16; o > 0; o >>= 1) mx = fmaxf(mx, __shfl_xor_sync(0xffffffffu, mx, o));
    float sum = 0.0f;
    for (int j = lane; j < S; j += 32) sum += __expf(p[j] - mx);
    #pragma unroll
    for (int o = 16; o > 0; o >>= 1) sum += __shfl_xor_sync(0xffffffffu, sum, o);
    float inv = 1.0f / sum;
    uint32_t* oh = ph + row * (SP / 2);
    for (int j2 = lane; j2 < SP / 2; j2 += 32) {
        int j = 2 * j2;
        float a = (j     < S) ? __expf(p[j]     - mx) * inv : 0.0f;
        float b = (j + 1 < S) ? __expf(p[j + 1] - mx) * inv : 0.0f;
        oh[j2] = pack_h2(a, b);
    }
}

// ---------------------------------------------------------------------------
// V (B*S x CC fp32) -> per-head V^T fp16 (32 x HD x SP/2 words), zero-padded
// ---------------------------------------------------------------------------
template <int S, int SP>
__global__ void vt_build_h(const float* __restrict__ v, uint32_t* __restrict__ vth) {
    int bh = blockIdx.x;
    int b = bh >> 3, h = bh & 7;
    const float* vb = v + (size_t)b * S * CC + h * 64;
    uint32_t* oh = vth + (size_t)bh * HD * (SP / 2);
    for (int idx = threadIdx.x; idx < HD * (SP / 2); idx += blockDim.x) {
        int d = idx / (SP / 2), sw = idx % (SP / 2);
        int s = 2 * sw;
        float x = (s     < S) ? vb[(size_t)s       * CC + d] : 0.0f;
        float y = (s + 1 < S) ? vb[(size_t)(s + 1) * CC + d] : 0.0f;
        oh[idx] = pack_h2(x, y);
    }
}

// ---------------------------------------------------------------------------
// Entry
// ---------------------------------------------------------------------------
extern "C" void kernel_launch(void* const* d_in, const int* in_sizes, int n_in,
                              void* d_out, int out_size) {
    const float* x    = (const float*)d_in[0];
    const float* ctx  = (const float*)d_in[1];
    const float* geo  = (const float*)d_in[2];
    const float* g1 = (const float*)d_in[3],  *b1 = (const float*)d_in[4];
    const float* g2 = (const float*)d_in[5],  *b2 = (const float*)d_in[6];
    const float* g3 = (const float*)d_in[7],  *b3 = (const float*)d_in[8];
    const float* g4 = (const float*)d_in[9],  *b4 = (const float*)d_in[10];
    const float* cWq = (const float*)d_in[11], *cWk = (const float*)d_in[12];
    const float* cWv = (const float*)d_in[13], *cWo = (const float*)d_in[14];
    const float* cbo = (const float*)d_in[15];
    const float* gWq = (const float*)d_in[16], *gWk = (const float*)d_in[17];
    const float* gWv = (const float*)d_in[18], *gWo = (const float*)d_in[19];
    const float* gbo = (const float*)d_in[20];
    const float* W1  = (const float*)d_in[21], *bf1 = (const float*)d_in[22];
    const float* W2  = (const float*)d_in[23], *bf2 = (const float*)d_in[24];
    float* out = (float*)d_out;

    float *t_d, *v_d, *big_d;
    uint32_t *xnh, *xnl, *qh, *kh, *vth, *ah, *al, *ph, *pl;
    uint32_t *cth, *ctl, *geoh, *geol, *wth, *wtl;
    cudaGetSymbolAddress((void**)&t_d,  g_t);
    cudaGetSymbolAddress((void**)&v_d,  g_v);
    cudaGetSymbolAddress((void**)&big_d, g_big);
    cudaGetSymbolAddress((void**)&xnh, g_xnh);  cudaGetSymbolAddress((void**)&xnl, g_xnl);
    cudaGetSymbolAddress((void**)&qh,  g_qh);
    cudaGetSymbolAddress((void**)&kh,  g_kh);
    cudaGetSymbolAddress((void**)&vth, g_vth);
    cudaGetSymbolAddress((void**)&ah,  g_ah);   cudaGetSymbolAddress((void**)&al,  g_al);
    cudaGetSymbolAddress((void**)&ph,  g_ph);   cudaGetSymbolAddress((void**)&pl,  g_pl);
    cudaGetSymbolAddress((void**)&cth, g_cth);  cudaGetSymbolAddress((void**)&ctl, g_ctl);
    cudaGetSymbolAddress((void**)&geoh, g_geoh); cudaGetSymbolAddress((void**)&geol, g_geol);
    cudaGetSymbolAddress((void**)&wth, g_wth);  cudaGetSymbolAddress((void**)&wtl, g_wtl);

    // launch 0: all weight transposes in one kernel
    {
        PrepArgs pa;
        pa.src[0] = cWq; pa.src[1] = cWo; pa.src[2] = gWq; pa.src[3] = gWo;
        pa.src[4] = gWk; pa.src[5] = gWv; pa.src[6] = cWk; pa.src[7] = cWv;
        pa.src[8] = W1;  pa.src[9] = W2;
        prep_weights<<<4352, 256>>>(pa, wth, wtl);
    }
    // launch 1: ctx input split
    {
        int nwc = BATCH * CTX_S * CTX_D / 2;
        cvt_split<<<ceil_div(nwc, 256), 256>>>(ctx, cth, ctl, nwc);
    }
    // launch 2: transpose x (B,C,N) -> t0 (B,N,C)
    {
        dim3 grid(NTOK / 32, CC / 32, BATCH);
        transpose_kernel<<<grid, dim3(32, 8)>>>(x, big_d, CC, NTOK);
    }
    // launch 3: t = t0 + LN1(t0)
    ln_kernel<false><<<NROWS, 128>>>(big_d, g1, b1, t_d, nullptr, nullptr);

    long long rows32 = (long long)BATCH * HHEADS * NTOK;

    // ================= context cross-attention (S=77) =================
    ln_kernel<true><<<NROWS, 128>>>(t_d, g2, b2, nullptr, xnh, xnl);   // launch 4
    // launch 5: Q projection (ncu target)
    L<128, 0, 2, false, false, 3>(xnh, xnl, 256, 0, 0,
        wth + WT2_CWQ, wtl + WT2_CWQ, 256, 0, 0,
        nullptr, qh, nullptr, CC, 0, 0, nullptr, NROWS, CC, CC, 1.0f, 1, 1);
    L<128, 0, 2, false, true, 3>(cth, ctl, 384, 0, 0,
        wth + WT2_CWK, wtl + WT2_CWK, 384, 0, 0,
        nullptr, kh, nullptr, CC, 0, 0, nullptr, BATCH * CTX_S, CC, CTX_D, 1.0f, 1, 1);
    L<128, 0, 0, false, true, 3>(cth, ctl, 384, 0, 0,
        wth + WT2_CWV, wtl + WT2_CWV, 384, 0, 0,
        v_d, nullptr, nullptr, CC, 0, 0, nullptr, BATCH * CTX_S, CC, CTX_D, 1.0f, 1, 1);
    vt_build_h<CTX_S, CTX_SP><<<32, 256>>>(v_d, vth);
    L<128, 0, 0, true, false, 1>(qh, qh, 256, (long long)NTOK * 256, 32,
        kh, kh, 256, (long long)CTX_S * 256, 32,
        big_d, nullptr, nullptr, CTX_SP,
        (long long)HHEADS * NTOK * CTX_SP, (long long)NTOK * CTX_SP,
        nullptr, NTOK, CTX_S, HD, 0.125f, BATCH * HHEADS, HHEADS);
    softmax_h<CTX_S, CTX_SP><<<(unsigned)(rows32 / 4), 128>>>(big_d, ph, rows32);
    L<64, 0, 1, false, false, 1>(ph, ph, CTX_SP / 2,
        (long long)HHEADS * NTOK * (CTX_SP / 2), (long long)NTOK * (CTX_SP / 2),
        vth, vth, CTX_SP / 2,
        (long long)HHEADS * HD * (CTX_SP / 2), (long long)HD * (CTX_SP / 2),
        nullptr, ah, al, CC, (long long)NTOK * CC, HD,
        nullptr, NTOK, HD, CTX_SP, 1.0f, BATCH * HHEADS, HHEADS);
    L<128, 3, 0, false, false, 3>(ah, al, 256, 0, 0,
        wth + WT2_CWO, wtl + WT2_CWO, 256, 0, 0,
        t_d, nullptr, nullptr, CC, 0, 0, cbo, NROWS, CC, CC, 1.0f, 1, 1);

    // ================= geometry cross-attention (S=256) =================
    {
        int nwg = BATCH * GEO_S * GEO_D / 2;
        cvt_split<<<ceil_div(nwg, 256), 256>>>(geo, geoh, geol, nwg);
    }
    ln_kernel<true><<<NROWS, 128>>>(t_d, g3, b3, nullptr, xnh, xnl);
    L<128, 0, 2, false, false, 3>(xnh, xnl, 256, 0, 0,
        wth + WT2_GWQ, wtl + WT2_GWQ, 256, 0, 0,
        nullptr, qh, nullptr, CC, 0, 0, nullptr, NROWS, CC, CC, 1.0f, 1, 1);
    L<128, 0, 2, false, false, 3>(geoh, geol, 256, 0, 0,
        wth + WT2_GWK, wtl + WT2_GWK, 256, 0, 0,
        nullptr, kh, nullptr, CC, 0, 0, nullptr, BATCH * GEO_S, CC, GEO_D, 1.0f, 1, 1);
    L<128, 0, 0, false, false, 3>(geoh, geol, 256, 0, 0,
        wth + WT2_GWV, wtl + WT2_GWV, 256, 0, 0,
        v_d, nullptr, nullptr, CC, 0, 0, nullptr, BATCH * GEO_S, CC, GEO_D, 1.0f, 1, 1);
    vt_build_h<GEO_S, GEO_S><<<32, 256>>>(v_d, vth);
    L<128, 0, 0, false, false, 1>(qh, qh, 256, (long long)NTOK * 256, 32,
        kh, kh, 256, (long long)GEO_S * 256, 32,
        big_d, nullptr, nullptr, GEO_S,
        (long long)HHEADS * NTOK * GEO_S, (long long)NTOK * GEO_S,
        nullptr, NTOK, GEO_S, HD, 0.125f, BATCH * HHEADS, HHEADS);
    softmax_h<GEO_S, GEO_S><<<(unsigned)(rows32 / 4), 128>>>(big_d, ph, rows32);
    L<64, 0, 1, false, false, 1>(ph, ph, GEO_S / 2,
        (long long)HHEADS * NTOK * (GEO_S / 2), (long long)NTOK * (GEO_S / 2),
        vth, vth, GEO_S / 2,
        (long long)HHEADS * HD * (GEO_S / 2), (long long)HD * (GEO_S / 2),
        nullptr, ah, al, CC, (long long)NTOK * CC, HD,
        nullptr, NTOK, HD, GEO_S, 1.0f, BATCH * HHEADS, HHEADS);
    L<128, 3, 0, false, false, 3>(ah, al, 256, 0, 0,
        wth + WT2_GWO, wtl + WT2_GWO, 256, 0, 0,
        t_d, nullptr, nullptr, CC, 0, 0, gbo, NROWS, CC, CC, 1.0f, 1, 1);

    // ================= FFN =================
    ln_kernel<true><<<NROWS, 128>>>(t_d, g4, b4, nullptr, xnh, xnl);
    L<128, 2, 1, false, false, 3>(xnh, xnl, 256, 0, 0,
        wth + WT2_W1, wtl + WT2_W1, 256, 0, 0,
        nullptr, ph, pl, FFN_D, 0, 0, bf1, NROWS, FFN_D, CC, 1.0f, 1, 1);
    L<128, 3, 0, false, false, 3>(ph, pl, 1024, 0, 0,
        wth + WT2_W2, wtl + WT2_W2, 1024, 0, 0,
        t_d, nullptr, nullptr, CC, 0, 0, bf2, NROWS, CC, FFN_D, 1.0f, 1, 1);

    // ---- transpose back
    {
        dim3 grid(CC / 32, NTOK / 32, BATCH);
        transpose_kernel<<<grid, dim3(32, 8)>>>(t_d, out, NTOK, CC);
    }
}

// round 11
// speedup vs baseline: 3.9716x; 1.6177x over previous
#include <cuda_runtime.h>
#include <cuda_bf16.h>
#include <cuda_fp16.h>
#include <cstdint>
#include <cstddef>

// ---------------------------------------------------------------------------
// Problem constants
// ---------------------------------------------------------------------------
#define BATCH   4
#define CC      512
#define NTOK    4096
#define NROWS   (BATCH*NTOK)
#define HHEADS  8
#define HD      64
#define CTX_S   77
#define CTX_SP  96        // padded S for ctx scores / P
#define CTX_D   768
#define GEO_S   256
#define GEO_D   512
#define FFN_D   2048
#define LN_EPS  1e-5f

static inline int ceil_div(int a, int b) { return (a + b - 1) / b; }

// ---------------------------------------------------------------------------
// Scratch (static device globals) — fp16 pairs packed as uint32
// ---------------------------------------------------------------------------
__device__ __align__(16) uint32_t g_xn [4194304];   // LN output (fp16)
__device__ __align__(16) uint32_t g_q  [4194304];   // Q (fp16)
__device__ __align__(16) uint32_t g_k  [262144];    // K proj (fp16)
__device__ __align__(16) uint32_t g_vt [262144];    // V^T per head (fp16)
__device__ __align__(16) uint32_t g_a  [4194304];   // attn out (fp16)
__device__ __align__(16) uint32_t g_p  [16777216];  // P / FFN hidden (fp16)
__device__ __align__(16) uint32_t g_ct [118272];    // ctx input (fp16)
__device__ __align__(16) uint32_t g_geo[262144];    // geo input (fp16)
__device__ __align__(16) uint32_t g_wt [2228224];   // weights^T (fp16)
__device__ float g_t  [(size_t)NROWS * CC];         // residual stream (fp32)
__device__ float g_v  [(size_t)BATCH * GEO_S * CC];
__device__ float g_big[(size_t)33554432];           // scores fp32 / t0 temp

// word offsets into g_wt
#define WT2_CWQ 0
#define WT2_CWO 131072
#define WT2_GWQ 262144
#define WT2_GWO 393216
#define WT2_W1  524288
#define WT2_W2  1048576
#define WT2_CWK 1572864
#define WT2_CWV 1769472
#define WT2_GWK 1966080
#define WT2_GWV 2097152

__device__ __forceinline__ float gelu_exact(float x) {
    return 0.5f * x * (1.0f + erff(x * 0.70710678118654752440f));
}

// ---------------------------------------------------------------------------
// helpers
// ---------------------------------------------------------------------------
__device__ __forceinline__ uint32_t smem_u32(const void* p) {
    uint32_t a;
    asm("{ .reg .u64 t; cvta.to.shared.u64 t, %1; cvt.u32.u64 %0, t; }" : "=r"(a) : "l"(p));
    return a;
}
__device__ __forceinline__ uint32_t pack_h2(float x, float y) {
    __half2 h = __floats2half2_rn(x, y);
    return *reinterpret_cast<uint32_t*>(&h);
}
__device__ __forceinline__ void mma16816(float c[4], uint32_t a0, uint32_t a1, uint32_t a2,
                                         uint32_t a3, uint32_t b0, uint32_t b1) {
    asm volatile(
        "mma.sync.aligned.m16n8k16.row.col.f32.f16.f16.f32 "
        "{%0,%1,%2,%3}, {%4,%5,%6,%7}, {%8,%9}, {%0,%1,%2,%3};"
        : "+f"(c[0]), "+f"(c[1]), "+f"(c[2]), "+f"(c[3])
        : "r"(a0), "r"(a1), "r"(a2), "r"(a3), "r"(b0), "r"(b1));
}
__device__ __forceinline__ void ldsm4(uint32_t& r0, uint32_t& r1, uint32_t& r2, uint32_t& r3,
                                      uint32_t addr) {
    asm volatile("ldmatrix.sync.aligned.m8n8.x4.shared.b16 {%0,%1,%2,%3}, [%4];"
                 : "=r"(r0), "=r"(r1), "=r"(r2), "=r"(r3) : "r"(addr));
}
// swizzled word offset of 16B group kg (0..3) in a 16-word row
__device__ __forceinline__ int swzg(int row, int kg) {
    return row * 16 + (((kg ^ ((row >> 1) & 3))) << 2);
}
__device__ __forceinline__ void cpa16(uint32_t dst, const uint32_t* src, bool ok) {
    int sz = ok ? 16 : 0;
    asm volatile("cp.async.cg.shared.global [%0], [%1], 16, %2;"
                 :: "r"(dst), "l"(src), "r"(sz) : "memory");
}

// ---------------------------------------------------------------------------
// fp16 single-pass HMMA GEMM, 3-stage cp.async pipeline, ldmatrix loads.
//   C[M,N] = alpha * A[M,K] @ B[N,K]^T
// NT: 128 (warps 2x4) or 64 (warps 4x2). K multiple of 32.
// GN: B row guard (+fp32 epilogue col guard). GM: A row guard.
// EPI: 0 none, 2 gelu(v+bias), 3 C += v + bias.
// OUT: 0 fp32 C, 2 fp16 packed C.
// Batched via grid.z (bb = z/H, hh = z%H); strides in words (A/B) / elems (C).
// ---------------------------------------------------------------------------
template <int NT, int EPI, int OUT, bool GN, bool GM>
__global__ void __launch_bounds__(256) hgemm_kernel(
    const uint32_t* __restrict__ A, int lda2, long long sAb2, long long sAh2,
    const uint32_t* __restrict__ B, int ldb2, long long sBb2, long long sBh2,
    float* __restrict__ Cf, uint32_t* __restrict__ Ch,
    int ldc, long long sCb, long long sChh,
    const float* __restrict__ bias,
    int M, int N, int K, float alpha, int H)
{
    constexpr int MI = (NT == 128) ? 4 : 2;
    constexpr int AW = 2048;
    constexpr int BW = NT * 16;
    constexpr int O_A = 0, O_B = AW;
    constexpr int STG = AW + BW;
    extern __shared__ uint32_t sm[];

    {
        int z = blockIdx.z;
        int bb = z / H, hh = z - bb * H;
        A += bb * sAb2 + hh * sAh2;
        B += bb * sBb2 + hh * sBh2;
        long long co = bb * sCb + hh * sChh;
        if (OUT == 0) Cf += co;
        else Ch += (co >> 1);
    }

    const int tid  = threadIdx.x;
    const int wid  = tid >> 5, lane = tid & 31;
    const int g    = lane >> 2, t4 = lane & 3;
    const int wm   = (NT == 128) ? (wid >> 2) : (wid >> 1);
    const int wn   = (NT == 128) ? (wid & 3)  : (wid & 1);
    const int m0   = blockIdx.y * 128;
    const int n0   = blockIdx.x * NT;
    const uint32_t smb = smem_u32(sm);

    auto issue = [&](int ch, int stg) {
        const int k0w = ch * 16;
        const uint32_t base = smb + (uint32_t)stg * STG * 4;
        {
            int r  = tid >> 1;
            int gr = m0 + r;
            bool ok = !GM || (gr < M);
            if (GM) gr = min(gr, M - 1);
            const uint32_t* sa = A + (size_t)gr * lda2 + k0w;
            #pragma unroll
            for (int e = 0; e < 2; ++e) {
                int grp = (tid & 1) * 2 + e;
                cpa16(base + (O_A + swzg(r, grp)) * 4, sa + grp * 4, ok);
            }
        }
        if (NT == 128) {
            int r  = tid >> 1;
            int gr = n0 + r;
            bool ok = !GN || (gr < N);
            if (GN) gr = min(gr, N - 1);
            const uint32_t* sb = B + (size_t)gr * ldb2 + k0w;
            #pragma unroll
            for (int e = 0; e < 2; ++e) {
                int grp = (tid & 1) * 2 + e;
                cpa16(base + (O_B + swzg(r, grp)) * 4, sb + grp * 4, ok);
            }
        } else {
            int r = tid >> 2, grp = tid & 3;
            const uint32_t* sb = B + (size_t)(n0 + r) * ldb2 + k0w;
            cpa16(base + (O_B + swzg(r, grp)) * 4, sb + grp * 4, true);
        }
        asm volatile("cp.async.commit_group;" ::: "memory");
    };

    float acc[MI][4][4] = {};
    const int nch = K >> 5;

    issue(0, 0);
    if (nch > 1) issue(1, 1);

    const int a_rin = ((lane >> 3) & 1) * 8 + (lane & 7);
    const int a_kg  = lane >> 4;
    const int b_blk = lane >> 4;
    const int b_kg  = (lane >> 3) & 1;
    const int b_rin = lane & 7;

    for (int ch = 0; ch < nch; ++ch) {
        if (ch + 1 < nch) {
            asm volatile("cp.async.wait_group 1;" ::: "memory");
        } else {
            asm volatile("cp.async.wait_group 0;" ::: "memory");
        }
        __syncthreads();
        if (ch + 2 < nch) issue(ch + 2, (ch + 2) % 3);

        const uint32_t stb = smb + (uint32_t)(ch % 3) * STG * 4;
        #pragma unroll
        for (int ks = 0; ks < 2; ++ks) {
            uint32_t af[MI][4], bf[4][2];
            #pragma unroll
            for (int mi = 0; mi < MI; ++mi) {
                int rr = wm * (MI * 16) + mi * 16 + a_rin;
                int kg = ks * 2 + a_kg;
                ldsm4(af[mi][0], af[mi][1], af[mi][2], af[mi][3],
                      stb + (O_A + swzg(rr, kg)) * 4);
            }
            #pragma unroll
            for (int nb = 0; nb < 2; ++nb) {
                int nr = wn * 32 + (nb * 2 + b_blk) * 8 + b_rin;
                int kg = ks * 2 + b_kg;
                ldsm4(bf[nb * 2][0], bf[nb * 2][1], bf[nb * 2 + 1][0],
                      bf[nb * 2 + 1][1], stb + (O_B + swzg(nr, kg)) * 4);
            }
            #pragma unroll
            for (int mi = 0; mi < MI; ++mi)
                #pragma unroll
                for (int ni = 0; ni < 4; ++ni)
                    mma16816(acc[mi][ni], af[mi][0], af[mi][1], af[mi][2],
                             af[mi][3], bf[ni][0], bf[ni][1]);
        }
    }

    // ---------------- epilogue ----------------
    const int ldc2 = ldc >> 1;
    #pragma unroll
    for (int mi = 0; mi < MI; ++mi) {
        #pragma unroll
        for (int ni = 0; ni < 4; ++ni) {
            int row0 = m0 + wm * (MI * 16) + mi * 16 + g;
            int col  = n0 + wn * 32 + ni * 8 + 2 * t4;
            float* c = acc[mi][ni];
            #pragma unroll
            for (int h = 0; h < 2; ++h) {
                int row = row0 + h * 8;
                if (GM && row >= M) continue;
                float v0 = c[2 * h] * alpha, v1 = c[2 * h + 1] * alpha;
                if (EPI == 2) {
                    v0 = gelu_exact(v0 + bias[col]);
                    v1 = gelu_exact(v1 + bias[col + 1]);
                }
                if (OUT == 0) {
                    size_t off = (size_t)row * ldc + col;
                    if (EPI == 3) {
                        v0 += bias[col]     + Cf[off];
                        v1 += bias[col + 1] + Cf[off + 1];
                    }
                    if (GN) {
                        if (col < N)     Cf[off]     = v0;
                        if (col + 1 < N) Cf[off + 1] = v1;
                    } else {
                        float2 o; o.x = v0; o.y = v1;
                        *reinterpret_cast<float2*>(&Cf[off]) = o;
                    }
                } else {
                    size_t o = (size_t)row * ldc2 + (col >> 1);
                    Ch[o] = pack_h2(v0, v1);
                }
            }
        }
    }
}

template <int NT, int EPI, int OUT, bool GN, bool GM>
static void L(const uint32_t* A, int lda2, long long sAb2, long long sAh2,
              const uint32_t* B, int ldb2, long long sBb2, long long sBh2,
              float* Cf, uint32_t* Ch, int ldc,
              long long sCb, long long sChh, const float* bias,
              int M, int N, int K, float alpha, int batches, int H) {
    constexpr int STG = 2048 + NT * 16;
    const int smem = 3 * STG * 4;
    cudaFuncSetAttribute(hgemm_kernel<NT, EPI, OUT, GN, GM>,
                         cudaFuncAttributeMaxDynamicSharedMemorySize, smem);
    dim3 grid(ceil_div(N, NT), ceil_div(M, 128), batches);
    hgemm_kernel<NT, EPI, OUT, GN, GM><<<grid, 256, smem>>>(
        A, lda2, sAb2, sAh2, B, ldb2, sBb2, sBh2,
        Cf, Ch, ldc, sCb, sChh, bias, M, N, K, alpha, H);
}

// ---------------------------------------------------------------------------
// fp32 transpose (x in/out)
// ---------------------------------------------------------------------------
__global__ void transpose_kernel(const float* __restrict__ in, float* __restrict__ out,
                                 int R, int Ccol) {
    __shared__ float tile[32][33];
    int b = blockIdx.z;
    const float* ip = in  + (size_t)b * R * Ccol;
    float*       op = out + (size_t)b * R * Ccol;
    int j0 = blockIdx.x * 32, i0 = blockIdx.y * 32;
    int tx = threadIdx.x, ty = threadIdx.y;
    #pragma unroll
    for (int k = 0; k < 32; k += 8) tile[ty + k][tx] = ip[(size_t)(i0 + ty + k) * Ccol + j0 + tx];
    __syncthreads();
    #pragma unroll
    for (int k = 0; k < 32; k += 8) op[(size_t)(j0 + ty + k) * R + i0 + tx] = tile[tx][ty + k];
}

// ---------------------------------------------------------------------------
// One-shot weight prep: all 10 transpose tasks -> fp16 packed, single launch.
// ---------------------------------------------------------------------------
struct PrepArgs { const float* src[10]; };

__global__ void prep_weights(PrepArgs a, uint32_t* __restrict__ wt) {
    const int starts[11] = {0, 256, 512, 768, 1024, 1280, 1536, 1920, 2304, 3328, 4352};
    const int Rt[10] = {512, 512, 512, 512, 512, 512, 768, 768, 512, 2048};
    const int Ct[10] = {512, 512, 512, 512, 512, 512, 512, 512, 2048, 512};
    const int Ot[10] = {WT2_CWQ, WT2_CWO, WT2_GWQ, WT2_GWO, WT2_GWK, WT2_GWV,
                        WT2_CWK, WT2_CWV, WT2_W1, WT2_W2};
    int b = blockIdx.x, t = 0;
    while (b >= starts[t + 1]) ++t;
    int lb = b - starts[t];
    int R = Rt[t], C = Ct[t], bx = C / 32;
    int j0 = (lb % bx) * 32, i0 = (lb / bx) * 32;
    const float* in = a.src[t];
    uint32_t* oh = wt + Ot[t];

    __shared__ float tile[32][33];
    int tid = threadIdx.x;
    int tx = tid & 31, ty = tid >> 5;
    #pragma unroll
    for (int k = 0; k < 32; k += 8)
        tile[ty + k][tx] = in[(size_t)(i0 + ty + k) * C + j0 + tx];
    __syncthreads();
    int R2 = R >> 1;
    #pragma unroll
    for (int rep = 0; rep < 2; ++rep) {
        int idx = tid + rep * 256;
        int i2 = idx & 15, j = idx >> 4;
        size_t o = (size_t)(j0 + j) * R2 + (i0 >> 1) + i2;
        oh[o] = pack_h2(tile[2 * i2][j], tile[2 * i2 + 1][j]);
    }
}

// elementwise fp32 -> fp16 pairs
__global__ void cvt_pack(const float* __restrict__ in, uint32_t* __restrict__ oh, int nw) {
    int w = blockIdx.x * 256 + threadIdx.x;
    if (w >= nw) return;
    float2 f = reinterpret_cast<const float2*>(in)[w];
    oh[w] = pack_h2(f.x, f.y);
}

// ---------------------------------------------------------------------------
// LayerNorm: ADD variant (fp32 out = in + LN(in)); HL variant (fp16 out)
// ---------------------------------------------------------------------------
template <bool HL>
__global__ void ln_kernel(const float* __restrict__ in,
                          const float* __restrict__ gamma,
                          const float* __restrict__ beta,
                          float* __restrict__ outf,
                          uint32_t* __restrict__ oh) {
    int row = blockIdx.x;
    const float4* rin = reinterpret_cast<const float4*>(in + (size_t)row * CC);
    int t = threadIdx.x;
    float4 v = rin[t];
    float s  = v.x + v.y + v.z + v.w;
    float ss = v.x*v.x + v.y*v.y + v.z*v.z + v.w*v.w;
    #pragma unroll
    for (int o = 16; o > 0; o >>= 1) {
        s  += __shfl_xor_sync(0xffffffffu, s,  o);
        ss += __shfl_xor_sync(0xffffffffu, ss, o);
    }
    __shared__ float shs[4], shss[4];
    int warp = t >> 5, lane = t & 31;
    if (lane == 0) { shs[warp] = s; shss[warp] = ss; }
    __syncthreads();
    s  = shs[0] + shs[1] + shs[2] + shs[3];
    ss = shss[0] + shss[1] + shss[2] + shss[3];
    float mu  = s * (1.0f / CC);
    float var = ss * (1.0f / CC) - mu * mu;
    float rs  = rsqrtf(var + LN_EPS);
    float4 g4 = reinterpret_cast<const float4*>(gamma)[t];
    float4 b4 = reinterpret_cast<const float4*>(beta)[t];
    float4 o4;
    o4.x = (v.x - mu) * rs * g4.x + b4.x;
    o4.y = (v.y - mu) * rs * g4.y + b4.y;
    o4.z = (v.z - mu) * rs * g4.z + b4.z;
    o4.w = (v.w - mu) * rs * g4.w + b4.w;
    if (!HL) {
        o4.x += v.x; o4.y += v.y; o4.z += v.z; o4.w += v.w;
        reinterpret_cast<float4*>(outf + (size_t)row * CC)[t] = o4;
    } else {
        size_t w = (size_t)row * (CC / 2) + t * 2;
        oh[w]     = pack_h2(o4.x, o4.y);
        oh[w + 1] = pack_h2(o4.z, o4.w);
    }
}

// ---------------------------------------------------------------------------
// Softmax: fp32 scores (ld=SP) -> P fp16 packed (padded zeros to SP)
// ---------------------------------------------------------------------------
template <int S, int SP>
__global__ void softmax_h(const float* __restrict__ sc,
                          uint32_t* __restrict__ ph, long long rows) {
    long long row = (long long)blockIdx.x * 4 + (threadIdx.x >> 5);
    if (row >= rows) return;
    const float* p = sc + row * SP;
    int lane = threadIdx.x & 31;
    float mx = -1e30f;
    for (int j = lane; j < S; j += 32) mx = fmaxf(mx, p[j]);
    #pragma unroll
    for (int o = 16; o > 0; o >>= 1) mx = fmaxf(mx, __shfl_xor_sync(0xffffffffu, mx, o));
    float sum = 0.0f;
    for (int j = lane; j < S; j += 32) sum += __expf(p[j] - mx);
    #pragma unroll
    for (int o = 16; o > 0; o >>= 1) sum += __shfl_xor_sync(0xffffffffu, sum, o);
    float inv = 1.0f / sum;
    uint32_t* oh = ph + row * (SP / 2);
    for (int j2 = lane; j2 < SP / 2; j2 += 32) {
        int j = 2 * j2;
        float a = (j     < S) ? __expf(p[j]     - mx) * inv : 0.0f;
        float b = (j + 1 < S) ? __expf(p[j + 1] - mx) * inv : 0.0f;
        oh[j2] = pack_h2(a, b);
    }
}

// ---------------------------------------------------------------------------
// V (B*S x CC fp32) -> per-head V^T fp16 (32 x HD x SP/2 words), zero-padded
// ---------------------------------------------------------------------------
template <int S, int SP>
__global__ void vt_build_h(const float* __restrict__ v, uint32_t* __restrict__ vth) {
    int bh = blockIdx.x;
    int b = bh >> 3, h = bh & 7;
    const float* vb = v + (size_t)b * S * CC + h * 64;
    uint32_t* oh = vth + (size_t)bh * HD * (SP / 2);
    for (int idx = threadIdx.x; idx < HD * (SP / 2); idx += blockDim.x) {
        int d = idx / (SP / 2), sw = idx % (SP / 2);
        int s = 2 * sw;
        float x = (s     < S) ? vb[(size_t)s       * CC + d] : 0.0f;
        float y = (s + 1 < S) ? vb[(size_t)(s + 1) * CC + d] : 0.0f;
        oh[idx] = pack_h2(x, y);
    }
}

// ---------------------------------------------------------------------------
// Entry
// ---------------------------------------------------------------------------
extern "C" void kernel_launch(void* const* d_in, const int* in_sizes, int n_in,
                              void* d_out, int out_size) {
    const float* x    = (const float*)d_in[0];
    const float* ctx  = (const float*)d_in[1];
    const float* geo  = (const float*)d_in[2];
    const float* g1 = (const float*)d_in[3],  *b1 = (const float*)d_in[4];
    const float* g2 = (const float*)d_in[5],  *b2 = (const float*)d_in[6];
    const float* g3 = (const float*)d_in[7],  *b3 = (const float*)d_in[8];
    const float* g4 = (const float*)d_in[9],  *b4 = (const float*)d_in[10];
    const float* cWq = (const float*)d_in[11], *cWk = (const float*)d_in[12];
    const float* cWv = (const float*)d_in[13], *cWo = (const float*)d_in[14];
    const float* cbo = (const float*)d_in[15];
    const float* gWq = (const float*)d_in[16], *gWk = (const float*)d_in[17];
    const float* gWv = (const float*)d_in[18], *gWo = (const float*)d_in[19];
    const float* gbo = (const float*)d_in[20];
    const float* W1  = (const float*)d_in[21], *bf1 = (const float*)d_in[22];
    const float* W2  = (const float*)d_in[23], *bf2 = (const float*)d_in[24];
    float* out = (float*)d_out;

    float *t_d, *v_d, *big_d;
    uint32_t *xn, *q, *k, *vt, *a, *p, *ct, *geo16, *wt;
    cudaGetSymbolAddress((void**)&t_d,  g_t);
    cudaGetSymbolAddress((void**)&v_d,  g_v);
    cudaGetSymbolAddress((void**)&big_d, g_big);
    cudaGetSymbolAddress((void**)&xn, g_xn);
    cudaGetSymbolAddress((void**)&q,  g_q);
    cudaGetSymbolAddress((void**)&k,  g_k);
    cudaGetSymbolAddress((void**)&vt, g_vt);
    cudaGetSymbolAddress((void**)&a,  g_a);
    cudaGetSymbolAddress((void**)&p,  g_p);
    cudaGetSymbolAddress((void**)&ct, g_ct);
    cudaGetSymbolAddress((void**)&geo16, g_geo);
    cudaGetSymbolAddress((void**)&wt, g_wt);

    // launch 0: all weight transposes in one kernel
    {
        PrepArgs pa;
        pa.src[0] = cWq; pa.src[1] = cWo; pa.src[2] = gWq; pa.src[3] = gWo;
        pa.src[4] = gWk; pa.src[5] = gWv; pa.src[6] = cWk; pa.src[7] = cWv;
        pa.src[8] = W1;  pa.src[9] = W2;
        prep_weights<<<4352, 256>>>(pa, wt);
    }
    // ctx input pack
    {
        int nwc = BATCH * CTX_S * CTX_D / 2;
        cvt_pack<<<ceil_div(nwc, 256), 256>>>(ctx, ct, nwc);
    }
    // transpose x (B,C,N) -> t0 (B,N,C)
    {
        dim3 grid(NTOK / 32, CC / 32, BATCH);
        transpose_kernel<<<grid, dim3(32, 8)>>>(x, big_d, CC, NTOK);
    }
    // t = t0 + LN1(t0)
    ln_kernel<false><<<NROWS, 128>>>(big_d, g1, b1, t_d, nullptr);

    long long rows32 = (long long)BATCH * HHEADS * NTOK;

    // ================= context cross-attention (S=77) =================
    ln_kernel<true><<<NROWS, 128>>>(t_d, g2, b2, nullptr, xn);
    L<128, 0, 2, false, false>(xn, 256, 0, 0,
        wt + WT2_CWQ, 256, 0, 0,
        nullptr, q, CC, 0, 0, nullptr, NROWS, CC, CC, 1.0f, 1, 1);
    L<128, 0, 2, false, true>(ct, 384, 0, 0,
        wt + WT2_CWK, 384, 0, 0,
        nullptr, k, CC, 0, 0, nullptr, BATCH * CTX_S, CC, CTX_D, 1.0f, 1, 1);
    L<128, 0, 0, false, true>(ct, 384, 0, 0,
        wt + WT2_CWV, 384, 0, 0,
        v_d, nullptr, CC, 0, 0, nullptr, BATCH * CTX_S, CC, CTX_D, 1.0f, 1, 1);
    vt_build_h<CTX_S, CTX_SP><<<32, 256>>>(v_d, vt);
    L<128, 0, 0, true, false>(q, 256, (long long)NTOK * 256, 32,
        k, 256, (long long)CTX_S * 256, 32,
        big_d, nullptr, CTX_SP,
        (long long)HHEADS * NTOK * CTX_SP, (long long)NTOK * CTX_SP,
        nullptr, NTOK, CTX_S, HD, 0.125f, BATCH * HHEADS, HHEADS);
    softmax_h<CTX_S, CTX_SP><<<(unsigned)(rows32 / 4), 128>>>(big_d, p, rows32);
    L<64, 0, 2, false, false>(p, CTX_SP / 2,
        (long long)HHEADS * NTOK * (CTX_SP / 2), (long long)NTOK * (CTX_SP / 2),
        vt, CTX_SP / 2,
        (long long)HHEADS * HD * (CTX_SP / 2), (long long)HD * (CTX_SP / 2),
        nullptr, a, CC, (long long)NTOK * CC, HD,
        nullptr, NTOK, HD, CTX_SP, 1.0f, BATCH * HHEADS, HHEADS);
    L<128, 3, 0, false, false>(a, 256, 0, 0,
        wt + WT2_CWO, 256, 0, 0,
        t_d, nullptr, CC, 0, 0, cbo, NROWS, CC, CC, 1.0f, 1, 1);

    // ================= geometry cross-attention (S=256) =================
    {
        int nwg = BATCH * GEO_S * GEO_D / 2;
        cvt_pack<<<ceil_div(nwg, 256), 256>>>(geo, geo16, nwg);
    }
    ln_kernel<true><<<NROWS, 128>>>(t_d, g3, b3, nullptr, xn);
    L<128, 0, 2, false, false>(xn, 256, 0, 0,
        wt + WT2_GWQ, 256, 0, 0,
        nullptr, q, CC, 0, 0, nullptr, NROWS, CC, CC, 1.0f, 1, 1);
    L<128, 0, 2, false, false>(geo16, 256, 0, 0,
        wt + WT2_GWK, 256, 0, 0,
        nullptr, k, CC, 0, 0, nullptr, BATCH * GEO_S, CC, GEO_D, 1.0f, 1, 1);
    L<128, 0, 0, false, false>(geo16, 256, 0, 0,
        wt + WT2_GWV, 256, 0, 0,
        v_d, nullptr, CC, 0, 0, nullptr, BATCH * GEO_S, CC, GEO_D, 1.0f, 1, 1);
    vt_build_h<GEO_S, GEO_S><<<32, 256>>>(v_d, vt);
    L<128, 0, 0, false, false>(q, 256, (long long)NTOK * 256, 32,
        k, 256, (long long)GEO_S * 256, 32,
        big_d, nullptr, GEO_S,
        (long long)HHEADS * NTOK * GEO_S, (long long)NTOK * GEO_S,
        nullptr, NTOK, GEO_S, HD, 0.125f, BATCH * HHEADS, HHEADS);
    softmax_h<GEO_S, GEO_S><<<(unsigned)(rows32 / 4), 128>>>(big_d, p, rows32);
    L<64, 0, 2, false, false>(p, GEO_S / 2,
        (long long)HHEADS * NTOK * (GEO_S / 2), (long long)NTOK * (GEO_S / 2),
        vt, GEO_S / 2,
        (long long)HHEADS * HD * (GEO_S / 2), (long long)HD * (GEO_S / 2),
        nullptr, a, CC, (long long)NTOK * CC, HD,
        nullptr, NTOK, HD, GEO_S, 1.0f, BATCH * HHEADS, HHEADS);
    L<128, 3, 0, false, false>(a, 256, 0, 0,
        wt + WT2_GWO, 256, 0, 0,
        t_d, nullptr, CC, 0, 0, gbo, NROWS, CC, CC, 1.0f, 1, 1);

    // ================= FFN =================
    ln_kernel<true><<<NROWS, 128>>>(t_d, g4, b4, nullptr, xn);
    L<128, 2, 2, false, false>(xn, 256, 0, 0,
        wt + WT2_W1, 256, 0, 0,
        nullptr, p, FFN_D, 0, 0, bf1, NROWS, FFN_D, CC, 1.0f, 1, 1);
    L<128, 3, 0, false, false>(p, 1024, 0, 0,
        wt + WT2_W2, 1024, 0, 0,
        t_d, nullptr, CC, 0, 0, bf2, NROWS, CC, FFN_D, 1.0f, 1, 1);

    // ---- transpose back
    {
        dim3 grid(CC / 32, NTOK / 32, BATCH);
        transpose_kernel<<<grid, dim3(32, 8)>>>(t_d, out, NTOK, CC);
    }
}

// round 12
// speedup vs baseline: 4.4600x; 1.1230x over previous
#include <cuda_runtime.h>
#include <cuda_bf16.h>
#include <cuda_fp16.h>
#include <cstdint>
#include <cstddef>

// ---------------------------------------------------------------------------
// Problem constants
// ---------------------------------------------------------------------------
#define BATCH   4
#define CC      512
#define NTOK    4096
#define NROWS   (BATCH*NTOK)
#define HHEADS  8
#define HD      64
#define CTX_S   77
#define CTX_SP  128       // padded S for ctx P (cols >= 77 are exact zeros)
#define CTX_D   768
#define GEO_S   256
#define GEO_D   512
#define FFN_D   2048
#define LN_EPS  1e-5f

static inline int ceil_div(int a, int b) { return (a + b - 1) / b; }

// ---------------------------------------------------------------------------
// Scratch (static device globals) — fp16 pairs packed as uint32
// ---------------------------------------------------------------------------
__device__ __align__(16) uint32_t g_xn [4194304];   // LN output (fp16)
__device__ __align__(16) uint32_t g_q  [4194304];   // Q (fp16)
__device__ __align__(16) uint32_t g_k  [262144];    // K proj (fp16)
__device__ __align__(16) uint32_t g_vt [262144];    // V^T per head (fp16)
__device__ __align__(16) uint32_t g_a  [4194304];   // attn out (fp16)
__device__ __align__(16) uint32_t g_p  [16777216];  // P / FFN hidden (fp16)
__device__ __align__(16) uint32_t g_ct [118272];    // ctx input (fp16)
__device__ __align__(16) uint32_t g_geo[262144];    // geo input (fp16)
__device__ __align__(16) uint32_t g_wt [2228224];   // weights^T (fp16)
__device__ float g_t  [(size_t)NROWS * CC];         // residual stream (fp32)
__device__ float g_v  [(size_t)BATCH * GEO_S * CC];
__device__ float g_big[(size_t)NROWS * CC];         // t0 transpose temp

// word offsets into g_wt
#define WT2_CWQ 0
#define WT2_CWO 131072
#define WT2_GWQ 262144
#define WT2_GWO 393216
#define WT2_W1  524288
#define WT2_W2  1048576
#define WT2_CWK 1572864
#define WT2_CWV 1769472
#define WT2_GWK 1966080
#define WT2_GWV 2097152

__device__ __forceinline__ float gelu_exact(float x) {
    return 0.5f * x * (1.0f + erff(x * 0.70710678118654752440f));
}

// ---------------------------------------------------------------------------
// helpers
// ---------------------------------------------------------------------------
__device__ __forceinline__ uint32_t smem_u32(const void* p) {
    uint32_t a;
    asm("{ .reg .u64 t; cvta.to.shared.u64 t, %1; cvt.u32.u64 %0, t; }" : "=r"(a) : "l"(p));
    return a;
}
__device__ __forceinline__ uint32_t pack_h2(float x, float y) {
    __half2 h = __floats2half2_rn(x, y);
    return *reinterpret_cast<uint32_t*>(&h);
}
__device__ __forceinline__ void mma16816(float c[4], uint32_t a0, uint32_t a1, uint32_t a2,
                                         uint32_t a3, uint32_t b0, uint32_t b1) {
    asm volatile(
        "mma.sync.aligned.m16n8k16.row.col.f32.f16.f16.f32 "
        "{%0,%1,%2,%3}, {%4,%5,%6,%7}, {%8,%9}, {%0,%1,%2,%3};"
        : "+f"(c[0]), "+f"(c[1]), "+f"(c[2]), "+f"(c[3])
        : "r"(a0), "r"(a1), "r"(a2), "r"(a3), "r"(b0), "r"(b1));
}
__device__ __forceinline__ void ldsm4(uint32_t& r0, uint32_t& r1, uint32_t& r2, uint32_t& r3,
                                      uint32_t addr) {
    asm volatile("ldmatrix.sync.aligned.m8n8.x4.shared.b16 {%0,%1,%2,%3}, [%4];"
                 : "=r"(r0), "=r"(r1), "=r"(r2), "=r"(r3) : "r"(addr));
}
// swizzled word offset, 16-word rows (GEMM tiles)
__device__ __forceinline__ int swzg(int row, int kg) {
    return row * 16 + (((kg ^ ((row >> 1) & 3))) << 2);
}
// swizzled word offset, 32-word rows (attn_ps tiles): 8 groups XOR row&7
__device__ __forceinline__ int swzg32(int row, int kg) {
    return row * 32 + (((kg ^ (row & 7))) << 2);
}
__device__ __forceinline__ void cpa16(uint32_t dst, const uint32_t* src, bool ok) {
    int sz = ok ? 16 : 0;
    asm volatile("cp.async.cg.shared.global [%0], [%1], 16, %2;"
                 :: "r"(dst), "l"(src), "r"(sz) : "memory");
}

// ---------------------------------------------------------------------------
// fp16 single-pass HMMA GEMM (unchanged from R10)
// ---------------------------------------------------------------------------
template <int NT, int EPI, int OUT, bool GN, bool GM>
__global__ void __launch_bounds__(256) hgemm_kernel(
    const uint32_t* __restrict__ A, int lda2, long long sAb2, long long sAh2,
    const uint32_t* __restrict__ B, int ldb2, long long sBb2, long long sBh2,
    float* __restrict__ Cf, uint32_t* __restrict__ Ch,
    int ldc, long long sCb, long long sChh,
    const float* __restrict__ bias,
    int M, int N, int K, float alpha, int H)
{
    constexpr int MI = (NT == 128) ? 4 : 2;
    constexpr int AW = 2048;
    constexpr int BW = NT * 16;
    constexpr int O_A = 0, O_B = AW;
    constexpr int STG = AW + BW;
    extern __shared__ uint32_t sm[];

    {
        int z = blockIdx.z;
        int bb = z / H, hh = z - bb * H;
        A += bb * sAb2 + hh * sAh2;
        B += bb * sBb2 + hh * sBh2;
        long long co = bb * sCb + hh * sChh;
        if (OUT == 0) Cf += co;
        else Ch += (co >> 1);
    }

    const int tid  = threadIdx.x;
    const int wid  = tid >> 5, lane = tid & 31;
    const int g    = lane >> 2, t4 = lane & 3;
    const int wm   = (NT == 128) ? (wid >> 2) : (wid >> 1);
    const int wn   = (NT == 128) ? (wid & 3)  : (wid & 1);
    const int m0   = blockIdx.y * 128;
    const int n0   = blockIdx.x * NT;
    const uint32_t smb = smem_u32(sm);

    auto issue = [&](int ch, int stg) {
        const int k0w = ch * 16;
        const uint32_t base = smb + (uint32_t)stg * STG * 4;
        {
            int r  = tid >> 1;
            int gr = m0 + r;
            bool ok = !GM || (gr < M);
            if (GM) gr = min(gr, M - 1);
            const uint32_t* sa = A + (size_t)gr * lda2 + k0w;
            #pragma unroll
            for (int e = 0; e < 2; ++e) {
                int grp = (tid & 1) * 2 + e;
                cpa16(base + (O_A + swzg(r, grp)) * 4, sa + grp * 4, ok);
            }
        }
        if (NT == 128) {
            int r  = tid >> 1;
            int gr = n0 + r;
            bool ok = !GN || (gr < N);
            if (GN) gr = min(gr, N - 1);
            const uint32_t* sb = B + (size_t)gr * ldb2 + k0w;
            #pragma unroll
            for (int e = 0; e < 2; ++e) {
                int grp = (tid & 1) * 2 + e;
                cpa16(base + (O_B + swzg(r, grp)) * 4, sb + grp * 4, ok);
            }
        } else {
            int r = tid >> 2, grp = tid & 3;
            const uint32_t* sb = B + (size_t)(n0 + r) * ldb2 + k0w;
            cpa16(base + (O_B + swzg(r, grp)) * 4, sb + grp * 4, true);
        }
        asm volatile("cp.async.commit_group;" ::: "memory");
    };

    float acc[MI][4][4] = {};
    const int nch = K >> 5;

    issue(0, 0);
    if (nch > 1) issue(1, 1);

    const int a_rin = ((lane >> 3) & 1) * 8 + (lane & 7);
    const int a_kg  = lane >> 4;
    const int b_blk = lane >> 4;
    const int b_kg  = (lane >> 3) & 1;
    const int b_rin = lane & 7;

    for (int ch = 0; ch < nch; ++ch) {
        if (ch + 1 < nch) {
            asm volatile("cp.async.wait_group 1;" ::: "memory");
        } else {
            asm volatile("cp.async.wait_group 0;" ::: "memory");
        }
        __syncthreads();
        if (ch + 2 < nch) issue(ch + 2, (ch + 2) % 3);

        const uint32_t stb = smb + (uint32_t)(ch % 3) * STG * 4;
        #pragma unroll
        for (int ks = 0; ks < 2; ++ks) {
            uint32_t af[MI][4], bf[4][2];
            #pragma unroll
            for (int mi = 0; mi < MI; ++mi) {
                int rr = wm * (MI * 16) + mi * 16 + a_rin;
                int kg = ks * 2 + a_kg;
                ldsm4(af[mi][0], af[mi][1], af[mi][2], af[mi][3],
                      stb + (O_A + swzg(rr, kg)) * 4);
            }
            #pragma unroll
            for (int nb = 0; nb < 2; ++nb) {
                int nr = wn * 32 + (nb * 2 + b_blk) * 8 + b_rin;
                int kg = ks * 2 + b_kg;
                ldsm4(bf[nb * 2][0], bf[nb * 2][1], bf[nb * 2 + 1][0],
                      bf[nb * 2 + 1][1], stb + (O_B + swzg(nr, kg)) * 4);
            }
            #pragma unroll
            for (int mi = 0; mi < MI; ++mi)
                #pragma unroll
                for (int ni = 0; ni < 4; ++ni)
                    mma16816(acc[mi][ni], af[mi][0], af[mi][1], af[mi][2],
                             af[mi][3], bf[ni][0], bf[ni][1]);
        }
    }

    const int ldc2 = ldc >> 1;
    #pragma unroll
    for (int mi = 0; mi < MI; ++mi) {
        #pragma unroll
        for (int ni = 0; ni < 4; ++ni) {
            int row0 = m0 + wm * (MI * 16) + mi * 16 + g;
            int col  = n0 + wn * 32 + ni * 8 + 2 * t4;
            float* c = acc[mi][ni];
            #pragma unroll
            for (int h = 0; h < 2; ++h) {
                int row = row0 + h * 8;
                if (GM && row >= M) continue;
                float v0 = c[2 * h] * alpha, v1 = c[2 * h + 1] * alpha;
                if (EPI == 2) {
                    v0 = gelu_exact(v0 + bias[col]);
                    v1 = gelu_exact(v1 + bias[col + 1]);
                }
                if (OUT == 0) {
                    size_t off = (size_t)row * ldc + col;
                    if (EPI == 3) {
                        v0 += bias[col]     + Cf[off];
                        v1 += bias[col + 1] + Cf[off + 1];
                    }
                    if (GN) {
                        if (col < N)     Cf[off]     = v0;
                        if (col + 1 < N) Cf[off + 1] = v1;
                    } else {
                        float2 o; o.x = v0; o.y = v1;
                        *reinterpret_cast<float2*>(&Cf[off]) = o;
                    }
                } else {
                    size_t o = (size_t)row * ldc2 + (col >> 1);
                    Ch[o] = pack_h2(v0, v1);
                }
            }
        }
    }
}

template <int NT, int EPI, int OUT, bool GN, bool GM>
static void L(const uint32_t* A, int lda2, long long sAb2, long long sAh2,
              const uint32_t* B, int ldb2, long long sBb2, long long sBh2,
              float* Cf, uint32_t* Ch, int ldc,
              long long sCb, long long sChh, const float* bias,
              int M, int N, int K, float alpha, int batches, int H) {
    constexpr int STG = 2048 + NT * 16;
    const int smem = 3 * STG * 4;
    cudaFuncSetAttribute(hgemm_kernel<NT, EPI, OUT, GN, GM>,
                         cudaFuncAttributeMaxDynamicSharedMemorySize, smem);
    dim3 grid(ceil_div(N, NT), ceil_div(M, 128), batches);
    hgemm_kernel<NT, EPI, OUT, GN, GM><<<grid, 256, smem>>>(
        A, lda2, sAb2, sAh2, B, ldb2, sBb2, sBh2,
        Cf, Ch, ldc, sCb, sChh, bias, M, N, K, alpha, H);
}

// ---------------------------------------------------------------------------
// Fused scores+softmax: P[b,h, 64 rows, SP cols] = softmax(0.125 * Q K^T)
// Q: (B*NTOK) x 256 words fp16.  K: (B*S) x 256 words fp16.
// Grid: (NTOK/64, B*H). 256 threads, warps 2x4 (wm rows x wn cols).
// Cols >= S masked to -inf (exact zeros in P).
// ---------------------------------------------------------------------------
template <int S, int SP>
__global__ void __launch_bounds__(256) attn_ps_kernel(
    const uint32_t* __restrict__ Q, const uint32_t* __restrict__ K,
    uint32_t* __restrict__ P)
{
    constexpr int NI  = SP / 32;          // n8 tiles per warp
    constexpr int O_Q = 0;                // 64 rows x 32 words
    constexpr int O_K = 2048;             // SP rows x 32 words
    constexpr int O_R = O_K + SP * 32;    // reduction table: 64*4 floats
    extern __shared__ uint32_t sm[];

    const int bh = blockIdx.y;
    const int bb = bh >> 3, hh = bh & 7;
    const int m0 = blockIdx.x * 64;
    const uint32_t* Qp = Q + (size_t)bb * NTOK * 256 + (size_t)hh * 32;
    const uint32_t* Kp = K + (size_t)bb * S * 256 + (size_t)hh * 32;
    uint32_t* Pp = P + (size_t)bh * NTOK * (SP / 2);

    const int tid  = threadIdx.x;
    const int wid  = tid >> 5, lane = tid & 31;
    const int g    = lane >> 2, t4 = lane & 3;
    const int wm   = wid >> 2, wn = wid & 3;
    const uint32_t smb = smem_u32(sm);

    // ---- fill Q (512 tasks) and K (SP*8 tasks)
    #pragma unroll
    for (int t = tid; t < 512; t += 256) {
        int r = t >> 3, kg = t & 7;
        cpa16(smb + (O_Q + swzg32(r, kg)) * 4,
              Qp + (size_t)(m0 + r) * 256 + kg * 4, true);
    }
    for (int t = tid; t < SP * 8; t += 256) {
        int s = t >> 3, kg = t & 7;
        bool ok = (s < S);
        int sc = ok ? s : (S - 1);
        cpa16(smb + (O_K + swzg32(s, kg)) * 4,
              Kp + (size_t)sc * 256 + kg * 4, ok);
    }
    asm volatile("cp.async.commit_group;" ::: "memory");
    asm volatile("cp.async.wait_group 0;" ::: "memory");
    __syncthreads();

    // ---- MMA: 64 x SP x 64
    const int a_rin = ((lane >> 3) & 1) * 8 + (lane & 7);
    const int a_kg  = lane >> 4;
    const int b_blk = lane >> 4;
    const int b_kg  = (lane >> 3) & 1;
    const int b_rin = lane & 7;

    float acc[2][NI][4] = {};
    #pragma unroll
    for (int ks = 0; ks < 4; ++ks) {
        uint32_t af[2][4], bf[NI][2];
        #pragma unroll
        for (int mi = 0; mi < 2; ++mi) {
            int rr = wm * 32 + mi * 16 + a_rin;
            ldsm4(af[mi][0], af[mi][1], af[mi][2], af[mi][3],
                  smb + (O_Q + swzg32(rr, ks * 2 + a_kg)) * 4);
        }
        #pragma unroll
        for (int nb = 0; nb < NI / 2; ++nb) {
            int nr = wn * NI * 8 + (nb * 2 + b_blk) * 8 + b_rin;
            ldsm4(bf[nb * 2][0], bf[nb * 2][1], bf[nb * 2 + 1][0],
                  bf[nb * 2 + 1][1], smb + (O_K + swzg32(nr, ks * 2 + b_kg)) * 4);
        }
        #pragma unroll
        for (int mi = 0; mi < 2; ++mi)
            #pragma unroll
            for (int ni = 0; ni < NI; ++ni)
                mma16816(acc[mi][ni], af[mi][0], af[mi][1], af[mi][2],
                         af[mi][3], bf[ni][0], bf[ni][1]);
    }

    // ---- softmax over full rows
    float* red = reinterpret_cast<float*>(sm + O_R);
    float lmax[4] = {-1e30f, -1e30f, -1e30f, -1e30f};
    #pragma unroll
    for (int mi = 0; mi < 2; ++mi)
        #pragma unroll
        for (int ni = 0; ni < NI; ++ni)
            #pragma unroll
            for (int j = 0; j < 4; ++j) {
                float v = acc[mi][ni][j] * 0.125f;
                if (S < SP) {
                    int col = wn * NI * 8 + ni * 8 + t4 * 2 + (j & 1);
                    if (col >= S) v = -1e30f;
                }
                acc[mi][ni][j] = v;
                int ri = mi * 2 + (j >> 1);
                lmax[ri] = fmaxf(lmax[ri], v);
            }
    #pragma unroll
    for (int o = 1; o <= 2; o <<= 1)
        #pragma unroll
        for (int ri = 0; ri < 4; ++ri)
            lmax[ri] = fmaxf(lmax[ri], __shfl_xor_sync(0xffffffffu, lmax[ri], o));
    if (t4 == 0) {
        #pragma unroll
        for (int ri = 0; ri < 4; ++ri) {
            int row = wm * 32 + (ri >> 1) * 16 + (ri & 1) * 8 + g;
            red[row * 4 + wn] = lmax[ri];
        }
    }
    __syncthreads();
    float gmx[4];
    #pragma unroll
    for (int ri = 0; ri < 4; ++ri) {
        int row = wm * 32 + (ri >> 1) * 16 + (ri & 1) * 8 + g;
        gmx[ri] = fmaxf(fmaxf(red[row * 4], red[row * 4 + 1]),
                        fmaxf(red[row * 4 + 2], red[row * 4 + 3]));
    }
    __syncthreads();
    float lsum[4] = {0.f, 0.f, 0.f, 0.f};
    #pragma unroll
    for (int mi = 0; mi < 2; ++mi)
        #pragma unroll
        for (int ni = 0; ni < NI; ++ni)
            #pragma unroll
            for (int j = 0; j < 4; ++j) {
                int ri = mi * 2 + (j >> 1);
                float e = __expf(acc[mi][ni][j] - gmx[ri]);
                acc[mi][ni][j] = e;
                lsum[ri] += e;
            }
    #pragma unroll
    for (int o = 1; o <= 2; o <<= 1)
        #pragma unroll
        for (int ri = 0; ri < 4; ++ri)
            lsum[ri] += __shfl_xor_sync(0xffffffffu, lsum[ri], o);
    if (t4 == 0) {
        #pragma unroll
        for (int ri = 0; ri < 4; ++ri) {
            int row = wm * 32 + (ri >> 1) * 16 + (ri & 1) * 8 + g;
            red[row * 4 + wn] = lsum[ri];
        }
    }
    __syncthreads();
    float inv[4];
    #pragma unroll
    for (int ri = 0; ri < 4; ++ri) {
        int row = wm * 32 + (ri >> 1) * 16 + (ri & 1) * 8 + g;
        inv[ri] = 1.0f / (red[row * 4] + red[row * 4 + 1] +
                          red[row * 4 + 2] + red[row * 4 + 3]);
    }

    // ---- store P fp16
    #pragma unroll
    for (int mi = 0; mi < 2; ++mi)
        #pragma unroll
        for (int ni = 0; ni < NI; ++ni)
            #pragma unroll
            for (int h = 0; h < 2; ++h) {
                int row = m0 + wm * 32 + mi * 16 + h * 8 + g;
                int col = wn * NI * 8 + ni * 8 + t4 * 2;
                int ri = mi * 2 + h;
                float a = acc[mi][ni][h * 2]     * inv[ri];
                float b = acc[mi][ni][h * 2 + 1] * inv[ri];
                Pp[(size_t)row * (SP / 2) + (col >> 1)] = pack_h2(a, b);
            }
}

template <int S, int SP>
static void launch_attn_ps(const uint32_t* Q, const uint32_t* K, uint32_t* P) {
    const int smem = (2048 + SP * 32 + 256) * 4;
    cudaFuncSetAttribute(attn_ps_kernel<S, SP>,
                         cudaFuncAttributeMaxDynamicSharedMemorySize, smem);
    dim3 grid(NTOK / 64, BATCH * HHEADS);
    attn_ps_kernel<S, SP><<<grid, 256, smem>>>(Q, K, P);
}

// ---------------------------------------------------------------------------
// fp32 transpose (x in/out)
// ---------------------------------------------------------------------------
__global__ void transpose_kernel(const float* __restrict__ in, float* __restrict__ out,
                                 int R, int Ccol) {
    __shared__ float tile[32][33];
    int b = blockIdx.z;
    const float* ip = in  + (size_t)b * R * Ccol;
    float*       op = out + (size_t)b * R * Ccol;
    int j0 = blockIdx.x * 32, i0 = blockIdx.y * 32;
    int tx = threadIdx.x, ty = threadIdx.y;
    #pragma unroll
    for (int k = 0; k < 32; k += 8) tile[ty + k][tx] = ip[(size_t)(i0 + ty + k) * Ccol + j0 + tx];
    __syncthreads();
    #pragma unroll
    for (int k = 0; k < 32; k += 8) op[(size_t)(j0 + ty + k) * R + i0 + tx] = tile[tx][ty + k];
}

// ---------------------------------------------------------------------------
// One-shot weight prep (10 transpose tasks -> fp16 packed)
// ---------------------------------------------------------------------------
struct PrepArgs { const float* src[10]; };

__global__ void prep_weights(PrepArgs a, uint32_t* __restrict__ wt) {
    const int starts[11] = {0, 256, 512, 768, 1024, 1280, 1536, 1920, 2304, 3328, 4352};
    const int Rt[10] = {512, 512, 512, 512, 512, 512, 768, 768, 512, 2048};
    const int Ct[10] = {512, 512, 512, 512, 512, 512, 512, 512, 2048, 512};
    const int Ot[10] = {WT2_CWQ, WT2_CWO, WT2_GWQ, WT2_GWO, WT2_GWK, WT2_GWV,
                        WT2_CWK, WT2_CWV, WT2_W1, WT2_W2};
    int b = blockIdx.x, t = 0;
    while (b >= starts[t + 1]) ++t;
    int lb = b - starts[t];
    int R = Rt[t], C = Ct[t], bx = C / 32;
    int j0 = (lb % bx) * 32, i0 = (lb / bx) * 32;
    const float* in = a.src[t];
    uint32_t* oh = wt + Ot[t];

    __shared__ float tile[32][33];
    int tid = threadIdx.x;
    int tx = tid & 31, ty = tid >> 5;
    #pragma unroll
    for (int k = 0; k < 32; k += 8)
        tile[ty + k][tx] = in[(size_t)(i0 + ty + k) * C + j0 + tx];
    __syncthreads();
    int R2 = R >> 1;
    #pragma unroll
    for (int rep = 0; rep < 2; ++rep) {
        int idx = tid + rep * 256;
        int i2 = idx & 15, j = idx >> 4;
        size_t o = (size_t)(j0 + j) * R2 + (i0 >> 1) + i2;
        oh[o] = pack_h2(tile[2 * i2][j], tile[2 * i2 + 1][j]);
    }
}

// elementwise fp32 -> fp16 pairs
__global__ void cvt_pack(const float* __restrict__ in, uint32_t* __restrict__ oh, int nw) {
    int w = blockIdx.x * 256 + threadIdx.x;
    if (w >= nw) return;
    float2 f = reinterpret_cast<const float2*>(in)[w];
    oh[w] = pack_h2(f.x, f.y);
}

// ---------------------------------------------------------------------------
// LayerNorm: ADD variant (fp32 out = in + LN(in)); HL variant (fp16 out)
// ---------------------------------------------------------------------------
template <bool HL>
__global__ void ln_kernel(const float* __restrict__ in,
                          const float* __restrict__ gamma,
                          const float* __restrict__ beta,
                          float* __restrict__ outf,
                          uint32_t* __restrict__ oh) {
    int row = blockIdx.x;
    const float4* rin = reinterpret_cast<const float4*>(in + (size_t)row * CC);
    int t = threadIdx.x;
    float4 v = rin[t];
    float s  = v.x + v.y + v.z + v.w;
    float ss = v.x*v.x + v.y*v.y + v.z*v.z + v.w*v.w;
    #pragma unroll
    for (int o = 16; o > 0; o >>= 1) {
        s  += __shfl_xor_sync(0xffffffffu, s,  o);
        ss += __shfl_xor_sync(0xffffffffu, ss, o);
    }
    __shared__ float shs[4], shss[4];
    int warp = t >> 5, lane = t & 31;
    if (lane == 0) { shs[warp] = s; shss[warp] = ss; }
    __syncthreads();
    s  = shs[0] + shs[1] + shs[2] + shs[3];
    ss = shss[0] + shss[1] + shss[2] + shss[3];
    float mu  = s * (1.0f / CC);
    float var = ss * (1.0f / CC) - mu * mu;
    float rs  = rsqrtf(var + LN_EPS);
    float4 g4 = reinterpret_cast<const float4*>(gamma)[t];
    float4 b4 = reinterpret_cast<const float4*>(beta)[t];
    float4 o4;
    o4.x = (v.x - mu) * rs * g4.x + b4.x;
    o4.y = (v.y - mu) * rs * g4.y + b4.y;
    o4.z = (v.z - mu) * rs * g4.z + b4.z;
    o4.w = (v.w - mu) * rs * g4.w + b4.w;
    if (!HL) {
        o4.x += v.x; o4.y += v.y; o4.z += v.z; o4.w += v.w;
        reinterpret_cast<float4*>(outf + (size_t)row * CC)[t] = o4;
    } else {
        size_t w = (size_t)row * (CC / 2) + t * 2;
        oh[w]     = pack_h2(o4.x, o4.y);
        oh[w + 1] = pack_h2(o4.z, o4.w);
    }
}

// ---------------------------------------------------------------------------
// V (B*S x CC fp32) -> per-head V^T fp16 (32 x HD x SP/2 words), zero-padded
// ---------------------------------------------------------------------------
template <int S, int SP>
__global__ void vt_build_h(const float* __restrict__ v, uint32_t* __restrict__ vth) {
    int bh = blockIdx.x;
    int b = bh >> 3, h = bh & 7;
    const float* vb = v + (size_t)b * S * CC + h * 64;
    uint32_t* oh = vth + (size_t)bh * HD * (SP / 2);
    for (int idx = threadIdx.x; idx < HD * (SP / 2); idx += blockDim.x) {
        int d = idx / (SP / 2), sw = idx % (SP / 2);
        int s = 2 * sw;
        float x = (s     < S) ? vb[(size_t)s       * CC + d] : 0.0f;
        float y = (s + 1 < S) ? vb[(size_t)(s + 1) * CC + d] : 0.0f;
        oh[idx] = pack_h2(x, y);
    }
}

// ---------------------------------------------------------------------------
// Entry
// ---------------------------------------------------------------------------
extern "C" void kernel_launch(void* const* d_in, const int* in_sizes, int n_in,
                              void* d_out, int out_size) {
    const float* x    = (const float*)d_in[0];
    const float* ctx  = (const float*)d_in[1];
    const float* geo  = (const float*)d_in[2];
    const float* g1 = (const float*)d_in[3],  *b1 = (const float*)d_in[4];
    const float* g2 = (const float*)d_in[5],  *b2 = (const float*)d_in[6];
    const float* g3 = (const float*)d_in[7],  *b3 = (const float*)d_in[8];
    const float* g4 = (const float*)d_in[9],  *b4 = (const float*)d_in[10];
    const float* cWq = (const float*)d_in[11], *cWk = (const float*)d_in[12];
    const float* cWv = (const float*)d_in[13], *cWo = (const float*)d_in[14];
    const float* cbo = (const float*)d_in[15];
    const float* gWq = (const float*)d_in[16], *gWk = (const float*)d_in[17];
    const float* gWv = (const float*)d_in[18], *gWo = (const float*)d_in[19];
    const float* gbo = (const float*)d_in[20];
    const float* W1  = (const float*)d_in[21], *bf1 = (const float*)d_in[22];
    const float* W2  = (const float*)d_in[23], *bf2 = (const float*)d_in[24];
    float* out = (float*)d_out;

    float *t_d, *v_d, *big_d;
    uint32_t *xn, *q, *k, *vt, *a, *p, *ct, *geo16, *wt;
    cudaGetSymbolAddress((void**)&t_d,  g_t);
    cudaGetSymbolAddress((void**)&v_d,  g_v);
    cudaGetSymbolAddress((void**)&big_d, g_big);
    cudaGetSymbolAddress((void**)&xn, g_xn);
    cudaGetSymbolAddress((void**)&q,  g_q);
    cudaGetSymbolAddress((void**)&k,  g_k);
    cudaGetSymbolAddress((void**)&vt, g_vt);
    cudaGetSymbolAddress((void**)&a,  g_a);
    cudaGetSymbolAddress((void**)&p,  g_p);
    cudaGetSymbolAddress((void**)&ct, g_ct);
    cudaGetSymbolAddress((void**)&geo16, g_geo);
    cudaGetSymbolAddress((void**)&wt, g_wt);

    // weight prep + input packs
    {
        PrepArgs pa;
        pa.src[0] = cWq; pa.src[1] = cWo; pa.src[2] = gWq; pa.src[3] = gWo;
        pa.src[4] = gWk; pa.src[5] = gWv; pa.src[6] = cWk; pa.src[7] = cWv;
        pa.src[8] = W1;  pa.src[9] = W2;
        prep_weights<<<4352, 256>>>(pa, wt);
    }
    {
        int nwc = BATCH * CTX_S * CTX_D / 2;
        cvt_pack<<<ceil_div(nwc, 256), 256>>>(ctx, ct, nwc);
    }
    {
        dim3 grid(NTOK / 32, CC / 32, BATCH);
        transpose_kernel<<<grid, dim3(32, 8)>>>(x, big_d, CC, NTOK);
    }
    ln_kernel<false><<<NROWS, 128>>>(big_d, g1, b1, t_d, nullptr);

    // ================= context cross-attention (S=77, SP=128) =================
    ln_kernel<true><<<NROWS, 128>>>(t_d, g2, b2, nullptr, xn);
    L<128, 0, 2, false, false>(xn, 256, 0, 0,
        wt + WT2_CWQ, 256, 0, 0,
        nullptr, q, CC, 0, 0, nullptr, NROWS, CC, CC, 1.0f, 1, 1);
    L<128, 0, 2, false, true>(ct, 384, 0, 0,
        wt + WT2_CWK, 384, 0, 0,
        nullptr, k, CC, 0, 0, nullptr, BATCH * CTX_S, CC, CTX_D, 1.0f, 1, 1);
    L<128, 0, 0, false, true>(ct, 384, 0, 0,
        wt + WT2_CWV, 384, 0, 0,
        v_d, nullptr, CC, 0, 0, nullptr, BATCH * CTX_S, CC, CTX_D, 1.0f, 1, 1);
    vt_build_h<CTX_S, CTX_SP><<<32, 256>>>(v_d, vt);
    launch_attn_ps<CTX_S, CTX_SP>(q, k, p);
    L<64, 0, 2, false, false>(p, CTX_SP / 2,
        (long long)HHEADS * NTOK * (CTX_SP / 2), (long long)NTOK * (CTX_SP / 2),
        vt, CTX_SP / 2,
        (long long)HHEADS * HD * (CTX_SP / 2), (long long)HD * (CTX_SP / 2),
        nullptr, a, CC, (long long)NTOK * CC, HD,
        nullptr, NTOK, HD, CTX_SP, 1.0f, BATCH * HHEADS, HHEADS);
    L<128, 3, 0, false, false>(a, 256, 0, 0,
        wt + WT2_CWO, 256, 0, 0,
        t_d, nullptr, CC, 0, 0, cbo, NROWS, CC, CC, 1.0f, 1, 1);

    // ================= geometry cross-attention (S=256) =================
    {
        int nwg = BATCH * GEO_S * GEO_D / 2;
        cvt_pack<<<ceil_div(nwg, 256), 256>>>(geo, geo16, nwg);
    }
    ln_kernel<true><<<NROWS, 128>>>(t_d, g3, b3, nullptr, xn);
    L<128, 0, 2, false, false>(xn, 256, 0, 0,
        wt + WT2_GWQ, 256, 0, 0,
        nullptr, q, CC, 0, 0, nullptr, NROWS, CC, CC, 1.0f, 1, 1);
    L<128, 0, 2, false, false>(geo16, 256, 0, 0,
        wt + WT2_GWK, 256, 0, 0,
        nullptr, k, CC, 0, 0, nullptr, BATCH * GEO_S, CC, GEO_D, 1.0f, 1, 1);
    L<128, 0, 0, false, false>(geo16, 256, 0, 0,
        wt + WT2_GWV, 256, 0, 0,
        v_d, nullptr, CC, 0, 0, nullptr, BATCH * GEO_S, CC, GEO_D, 1.0f, 1, 1);
    vt_build_h<GEO_S, GEO_S><<<32, 256>>>(v_d, vt);
    launch_attn_ps<GEO_S, GEO_S>(q, k, p);
    L<64, 0, 2, false, false>(p, GEO_S / 2,
        (long long)HHEADS * NTOK * (GEO_S / 2), (long long)NTOK * (GEO_S / 2),
        vt, GEO_S / 2,
        (long long)HHEADS * HD * (GEO_S / 2), (long long)HD * (GEO_S / 2),
        nullptr, a, CC, (long long)NTOK * CC, HD,
        nullptr, NTOK, HD, GEO_S, 1.0f, BATCH * HHEADS, HHEADS);
    L<128, 3, 0, false, false>(a, 256, 0, 0,
        wt + WT2_GWO, 256, 0, 0,
        t_d, nullptr, CC, 0, 0, gbo, NROWS, CC, CC, 1.0f, 1, 1);

    // ================= FFN =================
    ln_kernel<true><<<NROWS, 128>>>(t_d, g4, b4, nullptr, xn);
    L<128, 2, 2, false, false>(xn, 256, 0, 0,
        wt + WT2_W1, 256, 0, 0,
        nullptr, p, FFN_D, 0, 0, bf1, NROWS, FFN_D, CC, 1.0f, 1, 1);
    L<128, 3, 0, false, false>(p, 1024, 0, 0,
        wt + WT2_W2, 1024, 0, 0,
        t_d, nullptr, CC, 0, 0, bf2, NROWS, CC, FFN_D, 1.0f, 1, 1);

    // ---- transpose back
    {
        dim3 grid(CC / 32, NTOK / 32, BATCH);
        transpose_kernel<<<grid, dim3(32, 8)>>>(t_d, out, NTOK, CC);
    }
}